// round 1
// baseline (speedup 1.0000x reference)
#include <cuda_runtime.h>
#include <cstdint>

#define NN 200000
#define EE 200000
#define TOT (NN + EE)

// ---------------- scratch (static device globals; no runtime allocation) ----------------
__device__ float    g_h  [(size_t)NN * 256];
__device__ float    g_hw [(size_t)NN * 256];
__device__ float    g_acc[(size_t)NN * 256];
__device__ float    g_xbu[(size_t)NN * 256];
__device__ float    g_xtd[(size_t)NN * 256];
__device__ float    g_as [NN * 4];
__device__ float    g_ad [NN * 4];
__device__ unsigned g_m  [NN * 4];
__device__ float    g_den[NN * 4];
__device__ float    g_e  [(size_t)TOT * 4];
__device__ float    g_tmp[(size_t)NN * 128];

// ---------------- ordered-float mapping for atomicMax ----------------
__device__ __forceinline__ unsigned fmap(float f) {
    unsigned u = __float_as_uint(f);
    return (u & 0x80000000u) ? ~u : (u | 0x80000000u);
}
__device__ __forceinline__ float funmap(unsigned u) {
    return (u & 0x80000000u) ? __uint_as_float(u ^ 0x80000000u) : __uint_as_float(~u);
}

// ---------------- SGEMM: C = act(concat(A1,A2) @ B + bias) ----------------
// BM=BN=64, BK=16, 256 threads, 4x4 micro-tile per thread.
// A is logically [M, K]; columns [0,K1) come from A1 (row stride K1),
// columns [K1,K) from A2 (row stride K-K1). For non-concat, pass K1 == K.
template<bool RELU, bool BIAS>
__global__ void __launch_bounds__(256) sgemm_k(
    const float* __restrict__ A1, const float* __restrict__ A2, int K1,
    const float* __restrict__ B, const float* __restrict__ bias,
    float* __restrict__ C, int K, int Nc)
{
    const int BM = 64, BN = 64, BK = 16;
    __shared__ float As[BK][BM];
    __shared__ float Bs[BK][BN];

    int tid = threadIdx.x;
    int tx = tid & 15, ty = tid >> 4;
    int rowBase = blockIdx.y * BM;
    int colBase = blockIdx.x * BN;

    int lr = tid >> 2;            // 0..63 : A row within tile
    int lc = (tid & 3) << 2;      // 0,4,8,12 : A col within k-tile
    int br = tid >> 4;            // 0..15 : B row within k-tile
    int bc = (tid & 15) << 2;     // 0..60 : B col within tile

    float acc[4][4];
#pragma unroll
    for (int i = 0; i < 4; i++)
#pragma unroll
        for (int j = 0; j < 4; j++) acc[i][j] = 0.f;

    for (int kt = 0; kt < K; kt += BK) {
        int kg = kt + lc;
        const float* Ap = (kg < K1) ? A1 : A2;
        int kk2    = (kg < K1) ? kg : (kg - K1);
        int stride = (kg < K1) ? K1 : (K - K1);
        float4 av = *reinterpret_cast<const float4*>(Ap + (size_t)(rowBase + lr) * stride + kk2);
        As[lc + 0][lr] = av.x;
        As[lc + 1][lr] = av.y;
        As[lc + 2][lr] = av.z;
        As[lc + 3][lr] = av.w;

        float4 bv = *reinterpret_cast<const float4*>(B + (size_t)(kt + br) * Nc + colBase + bc);
        *reinterpret_cast<float4*>(&Bs[br][bc]) = bv;
        __syncthreads();

#pragma unroll
        for (int kk = 0; kk < BK; kk++) {
            float a0 = As[kk][ty * 4 + 0], a1 = As[kk][ty * 4 + 1];
            float a2 = As[kk][ty * 4 + 2], a3 = As[kk][ty * 4 + 3];
            float b0 = Bs[kk][tx * 4 + 0], b1 = Bs[kk][tx * 4 + 1];
            float b2 = Bs[kk][tx * 4 + 2], b3 = Bs[kk][tx * 4 + 3];
            acc[0][0] += a0 * b0; acc[0][1] += a0 * b1; acc[0][2] += a0 * b2; acc[0][3] += a0 * b3;
            acc[1][0] += a1 * b0; acc[1][1] += a1 * b1; acc[1][2] += a1 * b2; acc[1][3] += a1 * b3;
            acc[2][0] += a2 * b0; acc[2][1] += a2 * b1; acc[2][2] += a2 * b2; acc[2][3] += a2 * b3;
            acc[3][0] += a3 * b0; acc[3][1] += a3 * b1; acc[3][2] += a3 * b2; acc[3][3] += a3 * b3;
        }
        __syncthreads();
    }

    float4 bb = make_float4(0.f, 0.f, 0.f, 0.f);
    if (BIAS) bb = *reinterpret_cast<const float4*>(bias + colBase + tx * 4);
#pragma unroll
    for (int i = 0; i < 4; i++) {
        float4 v;
        v.x = acc[i][0] + bb.x;
        v.y = acc[i][1] + bb.y;
        v.z = acc[i][2] + bb.z;
        v.w = acc[i][3] + bb.w;
        if (RELU) {
            v.x = fmaxf(v.x, 0.f); v.y = fmaxf(v.y, 0.f);
            v.z = fmaxf(v.z, 0.f); v.w = fmaxf(v.w, 0.f);
        }
        *reinterpret_cast<float4*>(C + (size_t)(rowBase + ty * 4 + i) * Nc + colBase + tx * 4) = v;
    }
}

// ---------------- per-node attention coefficients ----------------
// a_src[n,h] = sum_c hw[n,h*64+c]*asrc[h,c] ; same for a_dst. One warp per node.
__global__ void attcoef_k(const float* __restrict__ hw,
                          const float* __restrict__ asrc, const float* __restrict__ adst,
                          float* __restrict__ osrc, float* __restrict__ odst)
{
    int w = (blockIdx.x * blockDim.x + threadIdx.x) >> 5;
    int lane = threadIdx.x & 31;
    if (w >= NN) return;
    const float4* row = reinterpret_cast<const float4*>(hw + (size_t)w * 256);
    const float4* A = reinterpret_cast<const float4*>(asrc);
    const float4* D = reinterpret_cast<const float4*>(adst);
    float s1 = 0.f, s2 = 0.f;
#pragma unroll
    for (int q = 0; q < 2; q++) {
        int idx = lane * 2 + q;   // 8 consecutive floats per thread -> one head per thread group
        float4 v = row[idx], a = A[idx], d = D[idx];
        s1 += v.x * a.x + v.y * a.y + v.z * a.z + v.w * a.w;
        s2 += v.x * d.x + v.y * d.y + v.z * d.z + v.w * d.w;
    }
#pragma unroll
    for (int off = 4; off; off >>= 1) {
        s1 += __shfl_xor_sync(0xffffffffu, s1, off);
        s2 += __shfl_xor_sync(0xffffffffu, s2, off);
    }
    if ((lane & 7) == 0) {
        osrc[w * 4 + (lane >> 3)] = s1;
        odst[w * 4 + (lane >> 3)] = s2;
    }
}

// ---------------- init: acc = bias (broadcast), m = -inf, den = 0 ----------------
__global__ void init_k(const float* __restrict__ bias, float* __restrict__ acc,
                       unsigned* __restrict__ m, float* __restrict__ den)
{
    int n = blockIdx.x;
    int c = threadIdx.x;
    acc[(size_t)n * 256 + c] = bias[c];
    if (c < 4) { m[n * 4 + c] = 0x007FFFFFu; den[n * 4 + c] = 0.f; }  // fmap(-inf)
}

// ---------------- edge pass 1: logits + segment max ----------------
__global__ void edge_logits_k(const int* __restrict__ ei,
                              const float* __restrict__ asrc, const float* __restrict__ adst,
                              float* __restrict__ ebuf, unsigned* __restrict__ m)
{
    int i = blockIdx.x * blockDim.x + threadIdx.x;
    if (i >= TOT) return;
    int s, d;
    if (i < EE) { s = ei[i]; d = ei[EE + i]; } else { s = i - EE; d = s; }
    float4 as = *reinterpret_cast<const float4*>(asrc + (size_t)s * 4);
    float4 ad = *reinterpret_cast<const float4*>(adst + (size_t)d * 4);
    float e[4] = {as.x + ad.x, as.y + ad.y, as.z + ad.z, as.w + ad.w};
    float4 o;
    float* op = &o.x;
#pragma unroll
    for (int h = 0; h < 4; h++) {
        float v = e[h] > 0.f ? e[h] : 0.2f * e[h];
        op[h] = v;
        atomicMax(m + d * 4 + h, fmap(v));
    }
    *reinterpret_cast<float4*>(ebuf + (size_t)i * 4) = o;
}

// ---------------- edge pass 2: exp + segment sum ----------------
__global__ void edge_exp_k(const int* __restrict__ ei,
                           const unsigned* __restrict__ m, float* __restrict__ ebuf,
                           float* __restrict__ den)
{
    int i = blockIdx.x * blockDim.x + threadIdx.x;
    if (i >= TOT) return;
    int d = (i < EE) ? ei[EE + i] : (i - EE);
    float4 e = *reinterpret_cast<const float4*>(ebuf + (size_t)i * 4);
    float4 o;
    o.x = expf(e.x - funmap(m[d * 4 + 0]));
    o.y = expf(e.y - funmap(m[d * 4 + 1]));
    o.z = expf(e.z - funmap(m[d * 4 + 2]));
    o.w = expf(e.w - funmap(m[d * 4 + 3]));
    *reinterpret_cast<float4*>(ebuf + (size_t)i * 4) = o;
    atomicAdd(den + d * 4 + 0, o.x);
    atomicAdd(den + d * 4 + 1, o.y);
    atomicAdd(den + d * 4 + 2, o.z);
    atomicAdd(den + d * 4 + 3, o.w);
}

// ---------------- edge pass 3: weighted scatter (64 threads per edge) ----------------
__global__ void __launch_bounds__(256) edge_scatter_k(const int* __restrict__ ei,
        const float* __restrict__ ebuf, const float* __restrict__ den,
        const float* __restrict__ hw, float* __restrict__ acc)
{
    int idx = blockIdx.x * 4 + (threadIdx.x >> 6);
    int lane = threadIdx.x & 63;
    if (idx >= TOT) return;
    int s, d;
    if (idx < EE) { s = ei[idx]; d = ei[EE + idx]; } else { s = idx - EE; d = s; }
    float4 ex = *reinterpret_cast<const float4*>(ebuf + (size_t)idx * 4);
    float4 dn = *reinterpret_cast<const float4*>(den + (size_t)d * 4);
    float al[4] = {ex.x / dn.x, ex.y / dn.y, ex.z / dn.z, ex.w / dn.w};
    const float* hs = hw + (size_t)s * 256;
    float* ap = acc + (size_t)d * 256;
#pragma unroll
    for (int q = 0; q < 4; q++) {
        int c = lane + q * 64;          // head q, channel lane -> coalesced per 64-lane group
        atomicAdd(ap + c, hs[c] * al[q]);
    }
}

// ---------------- LayerNorm(256) + ReLU, one warp per row ----------------
__global__ void ln_relu_k(const float* __restrict__ in, const float* __restrict__ g,
                          const float* __restrict__ b, float* __restrict__ out)
{
    int row = (blockIdx.x * blockDim.x + threadIdx.x) >> 5;
    int lane = threadIdx.x & 31;
    if (row >= NN) return;
    const float4* ip = reinterpret_cast<const float4*>(in + (size_t)row * 256);
    float4 v0 = ip[lane * 2], v1 = ip[lane * 2 + 1];
    float sum = v0.x + v0.y + v0.z + v0.w + v1.x + v1.y + v1.z + v1.w;
#pragma unroll
    for (int off = 16; off; off >>= 1) sum += __shfl_xor_sync(0xffffffffu, sum, off);
    float mean = sum * (1.f / 256.f);
    float c0x = v0.x - mean, c0y = v0.y - mean, c0z = v0.z - mean, c0w = v0.w - mean;
    float c1x = v1.x - mean, c1y = v1.y - mean, c1z = v1.z - mean, c1w = v1.w - mean;
    float sq = c0x * c0x + c0y * c0y + c0z * c0z + c0w * c0w
             + c1x * c1x + c1y * c1y + c1z * c1z + c1w * c1w;
#pragma unroll
    for (int off = 16; off; off >>= 1) sq += __shfl_xor_sync(0xffffffffu, sq, off);
    float r = rsqrtf(sq * (1.f / 256.f) + 1e-5f);
    const float4* gp = reinterpret_cast<const float4*>(g);
    const float4* bp = reinterpret_cast<const float4*>(b);
    float4 g0 = gp[lane * 2], g1 = gp[lane * 2 + 1];
    float4 b0 = bp[lane * 2], b1 = bp[lane * 2 + 1];
    float4 o0, o1;
    o0.x = fmaxf(c0x * r * g0.x + b0.x, 0.f);
    o0.y = fmaxf(c0y * r * g0.y + b0.y, 0.f);
    o0.z = fmaxf(c0z * r * g0.z + b0.z, 0.f);
    o0.w = fmaxf(c0w * r * g0.w + b0.w, 0.f);
    o1.x = fmaxf(c1x * r * g1.x + b1.x, 0.f);
    o1.y = fmaxf(c1y * r * g1.y + b1.y, 0.f);
    o1.z = fmaxf(c1z * r * g1.z + b1.z, 0.f);
    o1.w = fmaxf(c1w * r * g1.w + b1.w, 0.f);
    float4* op = reinterpret_cast<float4*>(out + (size_t)row * 256);
    op[lane * 2] = o0;
    op[lane * 2 + 1] = o1;
}

// ---------------- final LayerNorm(128) + L2 normalize, one warp per row ----------------
__global__ void ln_norm_k(const float* __restrict__ in, const float* __restrict__ g,
                          const float* __restrict__ b, float* __restrict__ out)
{
    int row = (blockIdx.x * blockDim.x + threadIdx.x) >> 5;
    int lane = threadIdx.x & 31;
    if (row >= NN) return;
    float4 v = reinterpret_cast<const float4*>(in + (size_t)row * 128)[lane];
    float sum = v.x + v.y + v.z + v.w;
#pragma unroll
    for (int off = 16; off; off >>= 1) sum += __shfl_xor_sync(0xffffffffu, sum, off);
    float mean = sum * (1.f / 128.f);
    float cx = v.x - mean, cy = v.y - mean, cz = v.z - mean, cw = v.w - mean;
    float sq = cx * cx + cy * cy + cz * cz + cw * cw;
#pragma unroll
    for (int off = 16; off; off >>= 1) sq += __shfl_xor_sync(0xffffffffu, sq, off);
    float r = rsqrtf(sq * (1.f / 128.f) + 1e-5f);
    float4 gv = reinterpret_cast<const float4*>(g)[lane];
    float4 bv = reinterpret_cast<const float4*>(b)[lane];
    float4 y;
    y.x = cx * r * gv.x + bv.x;
    y.y = cy * r * gv.y + bv.y;
    y.z = cz * r * gv.z + bv.z;
    y.w = cw * r * gv.w + bv.w;
    float n2 = y.x * y.x + y.y * y.y + y.z * y.z + y.w * y.w;
#pragma unroll
    for (int off = 16; off; off >>= 1) n2 += __shfl_xor_sync(0xffffffffu, n2, off);
    float inv = 1.f / fmaxf(sqrtf(n2), 1e-12f);
    y.x *= inv; y.y *= inv; y.z *= inv; y.w *= inv;
    reinterpret_cast<float4*>(out + (size_t)row * 128)[lane] = y;
}

// ---------------- launcher ----------------
extern "C" void kernel_launch(void* const* d_in, const int* in_sizes, int n_in,
                              void* d_out, int out_size)
{
    const float* x       = (const float*)d_in[0];
    const int*   ei_bu   = (const int*)d_in[1];
    const int*   ei_td   = (const int*)d_in[2];
    const float* Wp      = (const float*)d_in[3];
    const float* bp      = (const float*)d_in[4];
    const float* W_bu    = (const float*)d_in[5];
    const float* asrc_bu = (const float*)d_in[6];
    const float* adst_bu = (const float*)d_in[7];
    const float* bias_bu = (const float*)d_in[8];
    const float* W_td    = (const float*)d_in[9];
    const float* asrc_td = (const float*)d_in[10];
    const float* adst_td = (const float*)d_in[11];
    const float* bias_td = (const float*)d_in[12];
    const float* Wf      = (const float*)d_in[13];
    const float* bf      = (const float*)d_in[14];
    const float* g_bu    = (const float*)d_in[15];
    const float* b_bu    = (const float*)d_in[16];
    const float* g_td    = (const float*)d_in[17];
    const float* b_td    = (const float*)d_in[18];
    const float* g_out   = (const float*)d_in[19];
    const float* b_out   = (const float*)d_in[20];
    float* out = (float*)d_out;

    float *ph, *phw, *pacc, *pxbu, *pxtd, *pas, *pad, *pden, *pe, *ptmp;
    unsigned* pm;
    cudaGetSymbolAddress((void**)&ph,   g_h);
    cudaGetSymbolAddress((void**)&phw,  g_hw);
    cudaGetSymbolAddress((void**)&pacc, g_acc);
    cudaGetSymbolAddress((void**)&pxbu, g_xbu);
    cudaGetSymbolAddress((void**)&pxtd, g_xtd);
    cudaGetSymbolAddress((void**)&pas,  g_as);
    cudaGetSymbolAddress((void**)&pad,  g_ad);
    cudaGetSymbolAddress((void**)&pm,   g_m);
    cudaGetSymbolAddress((void**)&pden, g_den);
    cudaGetSymbolAddress((void**)&pe,   g_e);
    cudaGetSymbolAddress((void**)&ptmp, g_tmp);

    const dim3 gemmGrid256(4, NN / 64);      // 256 output cols
    const dim3 gemmGrid128(2, NN / 64);      // 128 output cols
    const int warpRowBlocks = (NN * 32) / 256;          // 25000
    const int edgeBlocks    = (TOT + 255) / 256;        // 1563
    const int scatBlocks    = (TOT + 3) / 4;            // 100000

    // h = relu(x @ Wp + bp)
    sgemm_k<true, true><<<gemmGrid256, 256>>>(x, x, 256, Wp, bp, ph, 256, 256);

    const int*   eis[2]   = {ei_bu, ei_td};
    const float* Ws[2]    = {W_bu, W_td};
    const float* asr[2]   = {asrc_bu, asrc_td};
    const float* ads[2]   = {adst_bu, adst_td};
    const float* bis[2]   = {bias_bu, bias_td};
    const float* gln[2]   = {g_bu, g_td};
    const float* bln[2]   = {b_bu, b_td};
    float*       xdir[2]  = {pxbu, pxtd};

    for (int dir = 0; dir < 2; dir++) {
        sgemm_k<false, false><<<gemmGrid256, 256>>>(ph, ph, 256, Ws[dir], nullptr, phw, 256, 256);
        attcoef_k<<<warpRowBlocks, 256>>>(phw, asr[dir], ads[dir], pas, pad);
        init_k<<<NN, 256>>>(bis[dir], pacc, pm, pden);
        edge_logits_k<<<edgeBlocks, 256>>>(eis[dir], pas, pad, pe, pm);
        edge_exp_k<<<edgeBlocks, 256>>>(eis[dir], pm, pe, pden);
        edge_scatter_k<<<scatBlocks, 256>>>(eis[dir], pe, pden, phw, pacc);
        ln_relu_k<<<warpRowBlocks, 256>>>(pacc, gln[dir], bln[dir], xdir[dir]);
    }

    // out_pre = concat(x_bu, x_td) @ Wf + bf ; then LN + L2 normalize
    sgemm_k<false, true><<<gemmGrid128, 256>>>(pxbu, pxtd, 256, Wf, bf, ptmp, 512, 128);
    ln_norm_k<<<warpRowBlocks, 256>>>(ptmp, g_out, b_out, out);
}

// round 2
// speedup vs baseline: 2.2692x; 2.2692x over previous
#include <cuda_runtime.h>
#include <cstdint>

#define NN 200000
#define EE 200000
#define TOT (NN + EE)

// ---------------- scratch (static device globals; no runtime allocation) ----------------
__device__ float    g_h  [(size_t)NN * 256];
__device__ float    g_hw [(size_t)NN * 256];
__device__ float    g_acc[(size_t)NN * 256];
__device__ float    g_xbu[(size_t)NN * 256];
__device__ float    g_xtd[(size_t)NN * 256];
__device__ float    g_as [NN * 4];
__device__ float    g_ad [NN * 4];
__device__ unsigned g_m  [NN * 4];
__device__ float    g_den[NN * 4];
__device__ float    g_e  [(size_t)TOT * 4];
__device__ float    g_tmp[(size_t)NN * 128];

// ---------------- ordered-float mapping for atomicMax ----------------
// fmap(finite v) >= 0x00800000 > 0, so memset-0 init is a valid -inf because
// every dst node receives at least its self-loop edge.
__device__ __forceinline__ unsigned fmap(float f) {
    unsigned u = __float_as_uint(f);
    return (u & 0x80000000u) ? ~u : (u | 0x80000000u);
}
__device__ __forceinline__ float funmap(unsigned u) {
    return (u & 0x80000000u) ? __uint_as_float(u ^ 0x80000000u) : __uint_as_float(~u);
}

__device__ __forceinline__ unsigned f2tf32(float f) {
    unsigned r;
    asm("cvt.rna.tf32.f32 %0, %1;" : "=r"(r) : "f"(f));
    return r;
}

__device__ __forceinline__ void mma_tf32(float c[4], const unsigned a[4], const unsigned b[2]) {
    asm volatile(
        "mma.sync.aligned.m16n8k8.row.col.f32.tf32.tf32.f32 "
        "{%0,%1,%2,%3}, {%4,%5,%6,%7}, {%8,%9}, {%0,%1,%2,%3};\n"
        : "+f"(c[0]), "+f"(c[1]), "+f"(c[2]), "+f"(c[3])
        : "r"(a[0]), "r"(a[1]), "r"(a[2]), "r"(a[3]), "r"(b[0]), "r"(b[1]));
}

// ---------------- tf32 tensor-core GEMM ----------------
// C[M,Nc] = act(concat(A1,A2)[M,K] @ B[K,Nc] + bias)
// Columns [0,K1) of A come from A1 (row stride K1), [K1,K) from A2 (stride K-K1).
// BM=128, BN=128, BK=16, 256 threads = 8 warps (2 m x 4 n), warp tile 64x32.
template<bool RELU, bool BIAS>
__global__ void __launch_bounds__(256) tgemm_k(
    const float* __restrict__ A1, const float* __restrict__ A2, int K1,
    const float* __restrict__ B, const float* __restrict__ bias,
    float* __restrict__ C, int M, int K, int Nc)
{
    const int BM = 128, BK = 16;
    __shared__ float As[2][BM][20];    // [m][k], stride 20 -> conflict-free frag loads
    __shared__ float Bs[2][BK][136];   // [k][n], stride 136 -> conflict-free frag loads

    int tid = threadIdx.x;
    int lane = tid & 31, wid = tid >> 5;
    int g = lane >> 2, t = lane & 3;
    int wm = wid >> 2;       // 0..1 -> m offset wm*64
    int wn = wid & 3;        // 0..3 -> n offset wn*32
    int rowBase = blockIdx.y * BM;
    int colBase = blockIdx.x * 128;

    float acc[4][4][4];
#pragma unroll
    for (int i = 0; i < 4; i++)
#pragma unroll
        for (int j = 0; j < 4; j++)
#pragma unroll
            for (int r = 0; r < 4; r++) acc[i][j][r] = 0.f;

    // global-load coordinates (2 float4 of A, 2 float4 of B per thread per tile)
    int ar0 = tid >> 2,          ac0 = (tid & 3) * 4;
    int ar1 = (tid + 256) >> 2,  ac1 = (tid & 3) * 4;
    int br0 = tid >> 5,          bc0 = (tid & 31) * 4;
    int br1 = (tid + 256) >> 5,  bc1 = (tid & 31) * 4;

    float4 pa0, pa1, pb0, pb1;
    const float4 z4 = make_float4(0.f, 0.f, 0.f, 0.f);

    auto gload = [&](int kt) {
        const float* Ap; int kk, stride;
        if (kt < K1) { Ap = A1; kk = kt;      stride = K1;     }
        else         { Ap = A2; kk = kt - K1; stride = K - K1; }
        int r0 = rowBase + ar0, r1 = rowBase + ar1;
        pa0 = (r0 < M) ? *reinterpret_cast<const float4*>(Ap + (size_t)r0 * stride + kk + ac0) : z4;
        pa1 = (r1 < M) ? *reinterpret_cast<const float4*>(Ap + (size_t)r1 * stride + kk + ac1) : z4;
        pb0 = *reinterpret_cast<const float4*>(B + (size_t)(kt + br0) * Nc + colBase + bc0);
        pb1 = *reinterpret_cast<const float4*>(B + (size_t)(kt + br1) * Nc + colBase + bc1);
    };

    auto sts = [&](int s) {
        As[s][ar0][ac0 + 0] = __uint_as_float(f2tf32(pa0.x));
        As[s][ar0][ac0 + 1] = __uint_as_float(f2tf32(pa0.y));
        As[s][ar0][ac0 + 2] = __uint_as_float(f2tf32(pa0.z));
        As[s][ar0][ac0 + 3] = __uint_as_float(f2tf32(pa0.w));
        As[s][ar1][ac1 + 0] = __uint_as_float(f2tf32(pa1.x));
        As[s][ar1][ac1 + 1] = __uint_as_float(f2tf32(pa1.y));
        As[s][ar1][ac1 + 2] = __uint_as_float(f2tf32(pa1.z));
        As[s][ar1][ac1 + 3] = __uint_as_float(f2tf32(pa1.w));
        Bs[s][br0][bc0 + 0] = __uint_as_float(f2tf32(pb0.x));
        Bs[s][br0][bc0 + 1] = __uint_as_float(f2tf32(pb0.y));
        Bs[s][br0][bc0 + 2] = __uint_as_float(f2tf32(pb0.z));
        Bs[s][br0][bc0 + 3] = __uint_as_float(f2tf32(pb0.w));
        Bs[s][br1][bc1 + 0] = __uint_as_float(f2tf32(pb1.x));
        Bs[s][br1][bc1 + 1] = __uint_as_float(f2tf32(pb1.y));
        Bs[s][br1][bc1 + 2] = __uint_as_float(f2tf32(pb1.z));
        Bs[s][br1][bc1 + 3] = __uint_as_float(f2tf32(pb1.w));
    };

    auto compute = [&](int s) {
#pragma unroll
        for (int ks = 0; ks < 2; ks++) {
            int k0 = ks * 8;
            unsigned a[4][4], b[4][2];
#pragma unroll
            for (int mt = 0; mt < 4; mt++) {
                int m0 = wm * 64 + mt * 16;
                a[mt][0] = __float_as_uint(As[s][m0 + g][k0 + t]);
                a[mt][1] = __float_as_uint(As[s][m0 + g + 8][k0 + t]);
                a[mt][2] = __float_as_uint(As[s][m0 + g][k0 + t + 4]);
                a[mt][3] = __float_as_uint(As[s][m0 + g + 8][k0 + t + 4]);
            }
#pragma unroll
            for (int nt = 0; nt < 4; nt++) {
                int n0 = wn * 32 + nt * 8;
                b[nt][0] = __float_as_uint(Bs[s][k0 + t][n0 + g]);
                b[nt][1] = __float_as_uint(Bs[s][k0 + t + 4][n0 + g]);
            }
#pragma unroll
            for (int mt = 0; mt < 4; mt++)
#pragma unroll
                for (int nt = 0; nt < 4; nt++)
                    mma_tf32(acc[mt][nt], a[mt], b[nt]);
        }
    };

    int ntiles = K / BK;
    gload(0);
    sts(0);
    __syncthreads();
    int s = 0;
    for (int kt = 0; kt < ntiles; kt++) {
        bool more = (kt + 1 < ntiles);
        if (more) gload((kt + 1) * BK);
        compute(s);
        if (more) {
            sts(s ^ 1);
            __syncthreads();
        }
        s ^= 1;
    }

    // epilogue
#pragma unroll
    for (int nt = 0; nt < 4; nt++) {
        int col = colBase + wn * 32 + nt * 8 + 2 * t;
        float2 bb = make_float2(0.f, 0.f);
        if (BIAS) bb = *reinterpret_cast<const float2*>(bias + col);
#pragma unroll
        for (int mt = 0; mt < 4; mt++) {
            int row0 = rowBase + wm * 64 + mt * 16 + g;
            int row1 = row0 + 8;
            float2 v0 = make_float2(acc[mt][nt][0] + bb.x, acc[mt][nt][1] + bb.y);
            float2 v1 = make_float2(acc[mt][nt][2] + bb.x, acc[mt][nt][3] + bb.y);
            if (RELU) {
                v0.x = fmaxf(v0.x, 0.f); v0.y = fmaxf(v0.y, 0.f);
                v1.x = fmaxf(v1.x, 0.f); v1.y = fmaxf(v1.y, 0.f);
            }
            if (row0 < M) *reinterpret_cast<float2*>(C + (size_t)row0 * Nc + col) = v0;
            if (row1 < M) *reinterpret_cast<float2*>(C + (size_t)row1 * Nc + col) = v1;
        }
    }
}

// ---------------- per-node attention coefficients ----------------
__global__ void attcoef_k(const float* __restrict__ hw,
                          const float* __restrict__ asrc, const float* __restrict__ adst,
                          float* __restrict__ osrc, float* __restrict__ odst)
{
    int w = (blockIdx.x * blockDim.x + threadIdx.x) >> 5;
    int lane = threadIdx.x & 31;
    if (w >= NN) return;
    const float4* row = reinterpret_cast<const float4*>(hw + (size_t)w * 256);
    const float4* A = reinterpret_cast<const float4*>(asrc);
    const float4* D = reinterpret_cast<const float4*>(adst);
    float s1 = 0.f, s2 = 0.f;
#pragma unroll
    for (int q = 0; q < 2; q++) {
        int idx = lane * 2 + q;
        float4 v = row[idx], a = A[idx], d = D[idx];
        s1 += v.x * a.x + v.y * a.y + v.z * a.z + v.w * a.w;
        s2 += v.x * d.x + v.y * d.y + v.z * d.z + v.w * d.w;
    }
#pragma unroll
    for (int off = 4; off; off >>= 1) {
        s1 += __shfl_xor_sync(0xffffffffu, s1, off);
        s2 += __shfl_xor_sync(0xffffffffu, s2, off);
    }
    if ((lane & 7) == 0) {
        osrc[w * 4 + (lane >> 3)] = s1;
        odst[w * 4 + (lane >> 3)] = s2;
    }
}

// ---------------- edge pass 1: logits + segment max ----------------
__global__ void edge_logits_k(const int* __restrict__ ei,
                              const float* __restrict__ asrc, const float* __restrict__ adst,
                              float* __restrict__ ebuf, unsigned* __restrict__ m)
{
    int i = blockIdx.x * blockDim.x + threadIdx.x;
    if (i >= TOT) return;
    int s, d;
    if (i < EE) { s = ei[i]; d = ei[EE + i]; } else { s = i - EE; d = s; }
    float4 as = *reinterpret_cast<const float4*>(asrc + (size_t)s * 4);
    float4 ad = *reinterpret_cast<const float4*>(adst + (size_t)d * 4);
    float e[4] = {as.x + ad.x, as.y + ad.y, as.z + ad.z, as.w + ad.w};
    float4 o;
    float* op = &o.x;
#pragma unroll
    for (int h = 0; h < 4; h++) {
        float v = e[h] > 0.f ? e[h] : 0.2f * e[h];
        op[h] = v;
        atomicMax(m + d * 4 + h, fmap(v));
    }
    *reinterpret_cast<float4*>(ebuf + (size_t)i * 4) = o;
}

// ---------------- edge pass 2: exp + segment sum ----------------
__global__ void edge_exp_k(const int* __restrict__ ei,
                           const unsigned* __restrict__ m, float* __restrict__ ebuf,
                           float* __restrict__ den)
{
    int i = blockIdx.x * blockDim.x + threadIdx.x;
    if (i >= TOT) return;
    int d = (i < EE) ? ei[EE + i] : (i - EE);
    float4 e = *reinterpret_cast<const float4*>(ebuf + (size_t)i * 4);
    float4 o;
    o.x = expf(e.x - funmap(m[d * 4 + 0]));
    o.y = expf(e.y - funmap(m[d * 4 + 1]));
    o.z = expf(e.z - funmap(m[d * 4 + 2]));
    o.w = expf(e.w - funmap(m[d * 4 + 3]));
    *reinterpret_cast<float4*>(ebuf + (size_t)i * 4) = o;
    atomicAdd(den + d * 4 + 0, o.x);
    atomicAdd(den + d * 4 + 1, o.y);
    atomicAdd(den + d * 4 + 2, o.z);
    atomicAdd(den + d * 4 + 3, o.w);
}

// ---------------- edge pass 3: weighted scatter (64 threads per edge) ----------------
__global__ void __launch_bounds__(256) edge_scatter_k(const int* __restrict__ ei,
        const float* __restrict__ ebuf, const float* __restrict__ den,
        const float* __restrict__ hw, float* __restrict__ acc)
{
    int idx = blockIdx.x * 4 + (threadIdx.x >> 6);
    int lane = threadIdx.x & 63;
    if (idx >= TOT) return;
    int s, d;
    if (idx < EE) { s = ei[idx]; d = ei[EE + idx]; } else { s = idx - EE; d = s; }
    float4 ex = *reinterpret_cast<const float4*>(ebuf + (size_t)idx * 4);
    float4 dn = *reinterpret_cast<const float4*>(den + (size_t)d * 4);
    float al[4] = {ex.x / dn.x, ex.y / dn.y, ex.z / dn.z, ex.w / dn.w};
    const float* hs = hw + (size_t)s * 256;
    float* ap = acc + (size_t)d * 256;
#pragma unroll
    for (int q = 0; q < 4; q++) {
        int c = lane + q * 64;
        atomicAdd(ap + c, hs[c] * al[q]);
    }
}

// ---------------- LayerNorm(256) of (in+bias), then ReLU; one warp per row ----------------
__global__ void ln_relu_k(const float* __restrict__ in, const float* __restrict__ bias,
                          const float* __restrict__ g, const float* __restrict__ b,
                          float* __restrict__ out)
{
    int row = (blockIdx.x * blockDim.x + threadIdx.x) >> 5;
    int lane = threadIdx.x & 31;
    if (row >= NN) return;
    const float4* ip = reinterpret_cast<const float4*>(in + (size_t)row * 256);
    const float4* bsp = reinterpret_cast<const float4*>(bias);
    float4 v0 = ip[lane * 2], v1 = ip[lane * 2 + 1];
    float4 a0 = bsp[lane * 2], a1 = bsp[lane * 2 + 1];
    v0.x += a0.x; v0.y += a0.y; v0.z += a0.z; v0.w += a0.w;
    v1.x += a1.x; v1.y += a1.y; v1.z += a1.z; v1.w += a1.w;
    float sum = v0.x + v0.y + v0.z + v0.w + v1.x + v1.y + v1.z + v1.w;
#pragma unroll
    for (int off = 16; off; off >>= 1) sum += __shfl_xor_sync(0xffffffffu, sum, off);
    float mean = sum * (1.f / 256.f);
    float c0x = v0.x - mean, c0y = v0.y - mean, c0z = v0.z - mean, c0w = v0.w - mean;
    float c1x = v1.x - mean, c1y = v1.y - mean, c1z = v1.z - mean, c1w = v1.w - mean;
    float sq = c0x * c0x + c0y * c0y + c0z * c0z + c0w * c0w
             + c1x * c1x + c1y * c1y + c1z * c1z + c1w * c1w;
#pragma unroll
    for (int off = 16; off; off >>= 1) sq += __shfl_xor_sync(0xffffffffu, sq, off);
    float r = rsqrtf(sq * (1.f / 256.f) + 1e-5f);
    const float4* gp = reinterpret_cast<const float4*>(g);
    const float4* bp = reinterpret_cast<const float4*>(b);
    float4 g0 = gp[lane * 2], g1 = gp[lane * 2 + 1];
    float4 b0 = bp[lane * 2], b1 = bp[lane * 2 + 1];
    float4 o0, o1;
    o0.x = fmaxf(c0x * r * g0.x + b0.x, 0.f);
    o0.y = fmaxf(c0y * r * g0.y + b0.y, 0.f);
    o0.z = fmaxf(c0z * r * g0.z + b0.z, 0.f);
    o0.w = fmaxf(c0w * r * g0.w + b0.w, 0.f);
    o1.x = fmaxf(c1x * r * g1.x + b1.x, 0.f);
    o1.y = fmaxf(c1y * r * g1.y + b1.y, 0.f);
    o1.z = fmaxf(c1z * r * g1.z + b1.z, 0.f);
    o1.w = fmaxf(c1w * r * g1.w + b1.w, 0.f);
    float4* op = reinterpret_cast<float4*>(out + (size_t)row * 256);
    op[lane * 2] = o0;
    op[lane * 2 + 1] = o1;
}

// ---------------- final LayerNorm(128) + L2 normalize, one warp per row ----------------
__global__ void ln_norm_k(const float* __restrict__ in, const float* __restrict__ g,
                          const float* __restrict__ b, float* __restrict__ out)
{
    int row = (blockIdx.x * blockDim.x + threadIdx.x) >> 5;
    int lane = threadIdx.x & 31;
    if (row >= NN) return;
    float4 v = reinterpret_cast<const float4*>(in + (size_t)row * 128)[lane];
    float sum = v.x + v.y + v.z + v.w;
#pragma unroll
    for (int off = 16; off; off >>= 1) sum += __shfl_xor_sync(0xffffffffu, sum, off);
    float mean = sum * (1.f / 128.f);
    float cx = v.x - mean, cy = v.y - mean, cz = v.z - mean, cw = v.w - mean;
    float sq = cx * cx + cy * cy + cz * cz + cw * cw;
#pragma unroll
    for (int off = 16; off; off >>= 1) sq += __shfl_xor_sync(0xffffffffu, sq, off);
    float r = rsqrtf(sq * (1.f / 128.f) + 1e-5f);
    float4 gv = reinterpret_cast<const float4*>(g)[lane];
    float4 bv = reinterpret_cast<const float4*>(b)[lane];
    float4 y;
    y.x = cx * r * gv.x + bv.x;
    y.y = cy * r * gv.y + bv.y;
    y.z = cz * r * gv.z + bv.z;
    y.w = cw * r * gv.w + bv.w;
    float n2 = y.x * y.x + y.y * y.y + y.z * y.z + y.w * y.w;
#pragma unroll
    for (int off = 16; off; off >>= 1) n2 += __shfl_xor_sync(0xffffffffu, n2, off);
    float inv = 1.f / fmaxf(sqrtf(n2), 1e-12f);
    y.x *= inv; y.y *= inv; y.z *= inv; y.w *= inv;
    reinterpret_cast<float4*>(out + (size_t)row * 128)[lane] = y;
}

// ---------------- launcher ----------------
extern "C" void kernel_launch(void* const* d_in, const int* in_sizes, int n_in,
                              void* d_out, int out_size)
{
    const float* x       = (const float*)d_in[0];
    const int*   ei_bu   = (const int*)d_in[1];
    const int*   ei_td   = (const int*)d_in[2];
    const float* Wp      = (const float*)d_in[3];
    const float* bp      = (const float*)d_in[4];
    const float* W_bu    = (const float*)d_in[5];
    const float* asrc_bu = (const float*)d_in[6];
    const float* adst_bu = (const float*)d_in[7];
    const float* bias_bu = (const float*)d_in[8];
    const float* W_td    = (const float*)d_in[9];
    const float* asrc_td = (const float*)d_in[10];
    const float* adst_td = (const float*)d_in[11];
    const float* bias_td = (const float*)d_in[12];
    const float* Wf      = (const float*)d_in[13];
    const float* bf      = (const float*)d_in[14];
    const float* g_bu    = (const float*)d_in[15];
    const float* b_bu    = (const float*)d_in[16];
    const float* g_td    = (const float*)d_in[17];
    const float* b_td    = (const float*)d_in[18];
    const float* g_out   = (const float*)d_in[19];
    const float* b_out   = (const float*)d_in[20];
    float* out = (float*)d_out;

    float *ph, *phw, *pacc, *pxbu, *pxtd, *pas, *pad, *pden, *pe, *ptmp;
    unsigned* pm;
    cudaGetSymbolAddress((void**)&ph,   g_h);
    cudaGetSymbolAddress((void**)&phw,  g_hw);
    cudaGetSymbolAddress((void**)&pacc, g_acc);
    cudaGetSymbolAddress((void**)&pxbu, g_xbu);
    cudaGetSymbolAddress((void**)&pxtd, g_xtd);
    cudaGetSymbolAddress((void**)&pas,  g_as);
    cudaGetSymbolAddress((void**)&pad,  g_ad);
    cudaGetSymbolAddress((void**)&pm,   g_m);
    cudaGetSymbolAddress((void**)&pden, g_den);
    cudaGetSymbolAddress((void**)&pe,   g_e);
    cudaGetSymbolAddress((void**)&ptmp, g_tmp);

    const int mblocks = (NN + 127) / 128;               // 1563
    const dim3 gemmGrid256(2, mblocks);                 // 256 output cols
    const dim3 gemmGrid128(1, mblocks);                 // 128 output cols
    const int warpRowBlocks = (NN * 32) / 256;          // 25000
    const int edgeBlocks    = (TOT + 255) / 256;        // 1563
    const int scatBlocks    = (TOT + 3) / 4;            // 100000

    // h = relu(x @ Wp + bp)
    tgemm_k<true, true><<<gemmGrid256, 256>>>(x, x, 256, Wp, bp, ph, NN, 256, 256);

    const int*   eis[2]   = {ei_bu, ei_td};
    const float* Ws[2]    = {W_bu, W_td};
    const float* asr[2]   = {asrc_bu, asrc_td};
    const float* ads[2]   = {adst_bu, adst_td};
    const float* bis[2]   = {bias_bu, bias_td};
    const float* gln[2]   = {g_bu, g_td};
    const float* bln[2]   = {b_bu, b_td};
    float*       xdir[2]  = {pxbu, pxtd};

    for (int dir = 0; dir < 2; dir++) {
        tgemm_k<false, false><<<gemmGrid256, 256>>>(ph, ph, 256, Ws[dir], nullptr, phw, NN, 256, 256);
        attcoef_k<<<warpRowBlocks, 256>>>(phw, asr[dir], ads[dir], pas, pad);
        cudaMemsetAsync(pacc, 0, (size_t)NN * 256 * sizeof(float));
        cudaMemsetAsync(pm,   0, (size_t)NN * 4 * sizeof(unsigned));
        cudaMemsetAsync(pden, 0, (size_t)NN * 4 * sizeof(float));
        edge_logits_k<<<edgeBlocks, 256>>>(eis[dir], pas, pad, pe, pm);
        edge_exp_k<<<edgeBlocks, 256>>>(eis[dir], pm, pe, pden);
        edge_scatter_k<<<scatBlocks, 256>>>(eis[dir], pe, pden, phw, pacc);
        ln_relu_k<<<warpRowBlocks, 256>>>(pacc, bis[dir], gln[dir], bln[dir], xdir[dir]);
    }

    // out_pre = concat(x_bu, x_td) @ Wf + bf ; then LN + L2 normalize
    tgemm_k<false, true><<<gemmGrid128, 256>>>(pxbu, pxtd, 256, Wf, bf, ptmp, NN, 512, 128);
    ln_norm_k<<<warpRowBlocks, 256>>>(ptmp, g_out, b_out, out);
}

// round 6
// speedup vs baseline: 2.3999x; 1.0576x over previous
#include <cuda_runtime.h>
#include <cstdint>

#define NN 200000
#define EE 200000
#define TOT (NN + EE)

// ---------------- scratch (static device globals; no runtime allocation) ----------------
__device__ float    g_h  [(size_t)NN * 256];
__device__ float    g_hw [(size_t)NN * 256];
__device__ float    g_acc[(size_t)NN * 256];
__device__ float    g_xbu[(size_t)NN * 256];
__device__ float    g_xtd[(size_t)NN * 256];
__device__ float    g_as [NN * 4];
__device__ float    g_ad [NN * 4];
__device__ unsigned g_m  [NN * 4];
__device__ float    g_den[NN * 4];
__device__ float    g_e  [(size_t)TOT * 4];
__device__ float    g_tmp[(size_t)NN * 128];
__device__ float    g_wt [3 * 65536];     // pre-rounded W_bu | W_td | Wf

// ---------------- helpers ----------------
__device__ __forceinline__ unsigned fmap(float f) {
    unsigned u = __float_as_uint(f);
    return (u & 0x80000000u) ? ~u : (u | 0x80000000u);
}
__device__ __forceinline__ float funmap(unsigned u) {
    return (u & 0x80000000u) ? __uint_as_float(u ^ 0x80000000u) : __uint_as_float(~u);
}
__device__ __forceinline__ unsigned f2tf32(float f) {
    unsigned r;
    asm("cvt.rna.tf32.f32 %0, %1;" : "=r"(r) : "f"(f));
    return r;
}
__device__ __forceinline__ float rnd_tf32(float f) { return __uint_as_float(f2tf32(f)); }

__device__ __forceinline__ void mma_tf32(float c[4], const unsigned a[4], const unsigned b[2]) {
    asm volatile(
        "mma.sync.aligned.m16n8k8.row.col.f32.tf32.tf32.f32 "
        "{%0,%1,%2,%3}, {%4,%5,%6,%7}, {%8,%9}, {%0,%1,%2,%3};\n"
        : "+f"(c[0]), "+f"(c[1]), "+f"(c[2]), "+f"(c[3])
        : "r"(a[0]), "r"(a[1]), "r"(a[2]), "r"(a[3]), "r"(b[0]), "r"(b[1]));
}

__device__ __forceinline__ void cp16(void* smem_dst, const void* gsrc, bool pred) {
    uint32_t s = (uint32_t)__cvta_generic_to_shared(smem_dst);
    int sz = pred ? 16 : 0;
    asm volatile("cp.async.cg.shared.global [%0], [%1], 16, %2;\n"
                 :: "r"(s), "l"(gsrc), "r"(sz));
}
__device__ __forceinline__ void cp_commit() { asm volatile("cp.async.commit_group;\n"); }
template<int N>
__device__ __forceinline__ void cp_wait() { asm volatile("cp.async.wait_group %0;\n" :: "n"(N)); }

__device__ __forceinline__ void red4(float* p, float4 v) {
    asm volatile("red.global.add.v4.f32 [%0], {%1,%2,%3,%4};\n"
                 :: "l"(p), "f"(v.x), "f"(v.y), "f"(v.z), "f"(v.w) : "memory");
}

// ---------------- GEMM path 1: register-staged with tf32 cvt (for raw fp32 inputs) --------
// C = act(A @ B + bias), A[M,K] row-major, B[K,Nc]. Output optionally rounded to tf32 grid.
template<bool RELU, bool BIAS, bool ROUND>
__global__ void __launch_bounds__(256) tgemm_k(
    const float* __restrict__ A1,
    const float* __restrict__ B, const float* __restrict__ bias,
    float* __restrict__ C, int M, int K, int Nc)
{
    const int BM = 128, BK = 16;
    __shared__ float As[2][BM][20];
    __shared__ float Bs[2][BK][136];

    int tid = threadIdx.x;
    int lane = tid & 31, wid = tid >> 5;
    int g = lane >> 2, t = lane & 3;
    int wm = wid >> 2, wn = wid & 3;
    int rowBase = blockIdx.y * BM;
    int colBase = blockIdx.x * 128;

    float acc[4][4][4];
#pragma unroll
    for (int i = 0; i < 4; i++)
#pragma unroll
        for (int j = 0; j < 4; j++)
#pragma unroll
            for (int r = 0; r < 4; r++) acc[i][j][r] = 0.f;

    int ar0 = tid >> 2,          ac0 = (tid & 3) * 4;
    int ar1 = (tid + 256) >> 2;
    int br0 = tid >> 5,          bc0 = (tid & 31) * 4;
    int br1 = (tid + 256) >> 5;

    float4 pa0, pa1, pb0, pb1;
    const float4 z4 = make_float4(0.f, 0.f, 0.f, 0.f);

    int ntiles = K / BK;
    int s = 0;
    {
        int r0 = rowBase + ar0, r1 = rowBase + ar1;
        pa0 = (r0 < M) ? *reinterpret_cast<const float4*>(A1 + (size_t)r0 * K + ac0) : z4;
        pa1 = (r1 < M) ? *reinterpret_cast<const float4*>(A1 + (size_t)r1 * K + ac0) : z4;
        pb0 = *reinterpret_cast<const float4*>(B + (size_t)br0 * Nc + colBase + bc0);
        pb1 = *reinterpret_cast<const float4*>(B + (size_t)br1 * Nc + colBase + bc0);
        As[0][ar0][ac0 + 0] = rnd_tf32(pa0.x); As[0][ar0][ac0 + 1] = rnd_tf32(pa0.y);
        As[0][ar0][ac0 + 2] = rnd_tf32(pa0.z); As[0][ar0][ac0 + 3] = rnd_tf32(pa0.w);
        As[0][ar1][ac0 + 0] = rnd_tf32(pa1.x); As[0][ar1][ac0 + 1] = rnd_tf32(pa1.y);
        As[0][ar1][ac0 + 2] = rnd_tf32(pa1.z); As[0][ar1][ac0 + 3] = rnd_tf32(pa1.w);
        Bs[0][br0][bc0 + 0] = rnd_tf32(pb0.x); Bs[0][br0][bc0 + 1] = rnd_tf32(pb0.y);
        Bs[0][br0][bc0 + 2] = rnd_tf32(pb0.z); Bs[0][br0][bc0 + 3] = rnd_tf32(pb0.w);
        Bs[0][br1][bc0 + 0] = rnd_tf32(pb1.x); Bs[0][br1][bc0 + 1] = rnd_tf32(pb1.y);
        Bs[0][br1][bc0 + 2] = rnd_tf32(pb1.z); Bs[0][br1][bc0 + 3] = rnd_tf32(pb1.w);
    }
    __syncthreads();
    for (int kt = 0; kt < ntiles; kt++) {
        bool more = (kt + 1 < ntiles);
        if (more) {
            int kk = (kt + 1) * BK;
            int r0 = rowBase + ar0, r1 = rowBase + ar1;
            pa0 = (r0 < M) ? *reinterpret_cast<const float4*>(A1 + (size_t)r0 * K + kk + ac0) : z4;
            pa1 = (r1 < M) ? *reinterpret_cast<const float4*>(A1 + (size_t)r1 * K + kk + ac0) : z4;
            pb0 = *reinterpret_cast<const float4*>(B + (size_t)(kk + br0) * Nc + colBase + bc0);
            pb1 = *reinterpret_cast<const float4*>(B + (size_t)(kk + br1) * Nc + colBase + bc0);
        }
#pragma unroll
        for (int ks = 0; ks < 2; ks++) {
            int k0 = ks * 8;
            unsigned a[4][4], b[4][2];
#pragma unroll
            for (int mt = 0; mt < 4; mt++) {
                int m0 = wm * 64 + mt * 16;
                a[mt][0] = __float_as_uint(As[s][m0 + g][k0 + t]);
                a[mt][1] = __float_as_uint(As[s][m0 + g + 8][k0 + t]);
                a[mt][2] = __float_as_uint(As[s][m0 + g][k0 + t + 4]);
                a[mt][3] = __float_as_uint(As[s][m0 + g + 8][k0 + t + 4]);
            }
#pragma unroll
            for (int nt = 0; nt < 4; nt++) {
                int n0 = wn * 32 + nt * 8;
                b[nt][0] = __float_as_uint(Bs[s][k0 + t][n0 + g]);
                b[nt][1] = __float_as_uint(Bs[s][k0 + t + 4][n0 + g]);
            }
#pragma unroll
            for (int mt = 0; mt < 4; mt++)
#pragma unroll
                for (int nt = 0; nt < 4; nt++)
                    mma_tf32(acc[mt][nt], a[mt], b[nt]);
        }
        if (more) {
            int so = s ^ 1;
            As[so][ar0][ac0 + 0] = rnd_tf32(pa0.x); As[so][ar0][ac0 + 1] = rnd_tf32(pa0.y);
            As[so][ar0][ac0 + 2] = rnd_tf32(pa0.z); As[so][ar0][ac0 + 3] = rnd_tf32(pa0.w);
            As[so][ar1][ac0 + 0] = rnd_tf32(pa1.x); As[so][ar1][ac0 + 1] = rnd_tf32(pa1.y);
            As[so][ar1][ac0 + 2] = rnd_tf32(pa1.z); As[so][ar1][ac0 + 3] = rnd_tf32(pa1.w);
            Bs[so][br0][bc0 + 0] = rnd_tf32(pb0.x); Bs[so][br0][bc0 + 1] = rnd_tf32(pb0.y);
            Bs[so][br0][bc0 + 2] = rnd_tf32(pb0.z); Bs[so][br0][bc0 + 3] = rnd_tf32(pb0.w);
            Bs[so][br1][bc0 + 0] = rnd_tf32(pb1.x); Bs[so][br1][bc0 + 1] = rnd_tf32(pb1.y);
            Bs[so][br1][bc0 + 2] = rnd_tf32(pb1.z); Bs[so][br1][bc0 + 3] = rnd_tf32(pb1.w);
            __syncthreads();
        }
        s ^= 1;
    }

#pragma unroll
    for (int nt = 0; nt < 4; nt++) {
        int col = colBase + wn * 32 + nt * 8 + 2 * t;
        float2 bb = make_float2(0.f, 0.f);
        if (BIAS) bb = *reinterpret_cast<const float2*>(bias + col);
#pragma unroll
        for (int mt = 0; mt < 4; mt++) {
            int row0 = rowBase + wm * 64 + mt * 16 + g;
            int row1 = row0 + 8;
            float2 v0 = make_float2(acc[mt][nt][0] + bb.x, acc[mt][nt][1] + bb.y);
            float2 v1 = make_float2(acc[mt][nt][2] + bb.x, acc[mt][nt][3] + bb.y);
            if (RELU) {
                v0.x = fmaxf(v0.x, 0.f); v0.y = fmaxf(v0.y, 0.f);
                v1.x = fmaxf(v1.x, 0.f); v1.y = fmaxf(v1.y, 0.f);
            }
            if (ROUND) {
                v0.x = rnd_tf32(v0.x); v0.y = rnd_tf32(v0.y);
                v1.x = rnd_tf32(v1.x); v1.y = rnd_tf32(v1.y);
            }
            if (row0 < M) *reinterpret_cast<float2*>(C + (size_t)row0 * Nc + col) = v0;
            if (row1 < M) *reinterpret_cast<float2*>(C + (size_t)row1 * Nc + col) = v1;
        }
    }
}

// ---------------- GEMM path 2: cp.async, inputs already tf32-rounded ----------------
// C = act(concat(A1,A2) @ B + bias); columns [0,K1) from A1 (stride K1), rest from A2.
template<bool RELU, bool BIAS>
__global__ void __launch_bounds__(256) tgemm_async_k(
    const float* __restrict__ A1, const float* __restrict__ A2, int K1,
    const float* __restrict__ B, const float* __restrict__ bias,
    float* __restrict__ C, int M, int K, int Nc)
{
    const int BM = 128, BK = 16;
    __shared__ float As[2][BM][20];
    __shared__ float Bs[2][BK][136];

    int tid = threadIdx.x;
    int lane = tid & 31, wid = tid >> 5;
    int g = lane >> 2, t = lane & 3;
    int wm = wid >> 2, wn = wid & 3;
    int rowBase = blockIdx.y * BM;
    int colBase = blockIdx.x * 128;

    float acc[4][4][4];
#pragma unroll
    for (int i = 0; i < 4; i++)
#pragma unroll
        for (int j = 0; j < 4; j++)
#pragma unroll
            for (int r = 0; r < 4; r++) acc[i][j][r] = 0.f;

    int ar0 = tid >> 2, ac0 = (tid & 3) * 4;   // A rows 0..63 / 64..127
    int ar1 = ar0 + 64;
    int br0 = tid >> 5, bc0 = (tid & 31) * 4;  // B rows 0..7 / 8..15
    int br1 = br0 + 8;

    auto loadtile = [&](int kt, int sb) {
        const float* Ap; int kk, stride;
        if (kt < K1) { Ap = A1; kk = kt;      stride = K1;     }
        else         { Ap = A2; kk = kt - K1; stride = K - K1; }
        int r0 = rowBase + ar0, r1 = rowBase + ar1;
        cp16(&As[sb][ar0][ac0], Ap + (size_t)r0 * stride + kk + ac0, r0 < M);
        cp16(&As[sb][ar1][ac0], Ap + (size_t)r1 * stride + kk + ac0, r1 < M);
        cp16(&Bs[sb][br0][bc0], B + (size_t)(kt + br0) * Nc + colBase + bc0, true);
        cp16(&Bs[sb][br1][bc0], B + (size_t)(kt + br1) * Nc + colBase + bc0, true);
        cp_commit();
    };

    int ntiles = K / BK;
    loadtile(0, 0);
    for (int kt = 0; kt < ntiles; kt++) {
        int s = kt & 1;
        if (kt + 1 < ntiles) loadtile((kt + 1) * BK, s ^ 1);
        else cp_commit();
        cp_wait<1>();
        __syncthreads();
#pragma unroll
        for (int ks = 0; ks < 2; ks++) {
            int k0 = ks * 8;
            unsigned a[4][4], b[4][2];
#pragma unroll
            for (int mt = 0; mt < 4; mt++) {
                int m0 = wm * 64 + mt * 16;
                a[mt][0] = __float_as_uint(As[s][m0 + g][k0 + t]);
                a[mt][1] = __float_as_uint(As[s][m0 + g + 8][k0 + t]);
                a[mt][2] = __float_as_uint(As[s][m0 + g][k0 + t + 4]);
                a[mt][3] = __float_as_uint(As[s][m0 + g + 8][k0 + t + 4]);
            }
#pragma unroll
            for (int nt = 0; nt < 4; nt++) {
                int n0 = wn * 32 + nt * 8;
                b[nt][0] = __float_as_uint(Bs[s][k0 + t][n0 + g]);
                b[nt][1] = __float_as_uint(Bs[s][k0 + t + 4][n0 + g]);
            }
#pragma unroll
            for (int mt = 0; mt < 4; mt++)
#pragma unroll
                for (int nt = 0; nt < 4; nt++)
                    mma_tf32(acc[mt][nt], a[mt], b[nt]);
        }
        __syncthreads();
    }

#pragma unroll
    for (int nt = 0; nt < 4; nt++) {
        int col = colBase + wn * 32 + nt * 8 + 2 * t;
        float2 bb = make_float2(0.f, 0.f);
        if (BIAS) bb = *reinterpret_cast<const float2*>(bias + col);
#pragma unroll
        for (int mt = 0; mt < 4; mt++) {
            int row0 = rowBase + wm * 64 + mt * 16 + g;
            int row1 = row0 + 8;
            float2 v0 = make_float2(acc[mt][nt][0] + bb.x, acc[mt][nt][1] + bb.y);
            float2 v1 = make_float2(acc[mt][nt][2] + bb.x, acc[mt][nt][3] + bb.y);
            if (RELU) {
                v0.x = fmaxf(v0.x, 0.f); v0.y = fmaxf(v0.y, 0.f);
                v1.x = fmaxf(v1.x, 0.f); v1.y = fmaxf(v1.y, 0.f);
            }
            if (row0 < M) *reinterpret_cast<float2*>(C + (size_t)row0 * Nc + col) = v0;
            if (row1 < M) *reinterpret_cast<float2*>(C + (size_t)row1 * Nc + col) = v1;
        }
    }
}

// ---------------- round weights once into g_wt ----------------
__global__ void round_w_k(const float* __restrict__ w0, const float* __restrict__ w1,
                          const float* __restrict__ w2, float* __restrict__ out)
{
    int i = blockIdx.x * 256 + threadIdx.x;
    out[i]          = rnd_tf32(w0[i]);
    out[65536 + i]  = rnd_tf32(w1[i]);
    out[131072 + i] = rnd_tf32(w2[i]);
}

// ---------------- per-node attention coefficients ----------------
__global__ void attcoef_k(const float* __restrict__ hw,
                          const float* __restrict__ asrc, const float* __restrict__ adst,
                          float* __restrict__ osrc, float* __restrict__ odst)
{
    int w = (blockIdx.x * blockDim.x + threadIdx.x) >> 5;
    int lane = threadIdx.x & 31;
    if (w >= NN) return;
    const float4* row = reinterpret_cast<const float4*>(hw + (size_t)w * 256);
    const float4* A = reinterpret_cast<const float4*>(asrc);
    const float4* D = reinterpret_cast<const float4*>(adst);
    float s1 = 0.f, s2 = 0.f;
#pragma unroll
    for (int q = 0; q < 2; q++) {
        int idx = lane * 2 + q;
        float4 v = row[idx], a = A[idx], d = D[idx];
        s1 += v.x * a.x + v.y * a.y + v.z * a.z + v.w * a.w;
        s2 += v.x * d.x + v.y * d.y + v.z * d.z + v.w * d.w;
    }
#pragma unroll
    for (int off = 4; off; off >>= 1) {
        s1 += __shfl_xor_sync(0xffffffffu, s1, off);
        s2 += __shfl_xor_sync(0xffffffffu, s2, off);
    }
    if ((lane & 7) == 0) {
        osrc[w * 4 + (lane >> 3)] = s1;
        odst[w * 4 + (lane >> 3)] = s2;
    }
}

// ---------------- edge pass 1: logits + segment max ----------------
__global__ void edge_logits_k(const int* __restrict__ ei,
                              const float* __restrict__ asrc, const float* __restrict__ adst,
                              float* __restrict__ ebuf, unsigned* __restrict__ m)
{
    int i = blockIdx.x * blockDim.x + threadIdx.x;
    if (i >= TOT) return;
    int s, d;
    if (i < EE) { s = ei[i]; d = ei[EE + i]; } else { s = i - EE; d = s; }
    float4 as = *reinterpret_cast<const float4*>(asrc + (size_t)s * 4);
    float4 ad = *reinterpret_cast<const float4*>(adst + (size_t)d * 4);
    float e[4] = {as.x + ad.x, as.y + ad.y, as.z + ad.z, as.w + ad.w};
    float4 o;
    float* op = &o.x;
#pragma unroll
    for (int h = 0; h < 4; h++) {
        float v = e[h] > 0.f ? e[h] : 0.2f * e[h];
        op[h] = v;
        atomicMax(m + d * 4 + h, fmap(v));
    }
    *reinterpret_cast<float4*>(ebuf + (size_t)i * 4) = o;
}

// ---------------- edge pass 2: exp + segment sum (v4 reduction) ----------------
__global__ void edge_exp_k(const int* __restrict__ ei,
                           const unsigned* __restrict__ m, float* __restrict__ ebuf,
                           float* __restrict__ den)
{
    int i = blockIdx.x * blockDim.x + threadIdx.x;
    if (i >= TOT) return;
    int d = (i < EE) ? ei[EE + i] : (i - EE);
    float4 e = *reinterpret_cast<const float4*>(ebuf + (size_t)i * 4);
    float4 o;
    o.x = expf(e.x - funmap(m[d * 4 + 0]));
    o.y = expf(e.y - funmap(m[d * 4 + 1]));
    o.z = expf(e.z - funmap(m[d * 4 + 2]));
    o.w = expf(e.w - funmap(m[d * 4 + 3]));
    *reinterpret_cast<float4*>(ebuf + (size_t)i * 4) = o;
    red4(den + (size_t)d * 4, o);
}

// ---------------- edge pass 3: weighted scatter (64 threads/edge, v4 reductions) ----------
__global__ void __launch_bounds__(256) edge_scatter_k(const int* __restrict__ ei,
        const float* __restrict__ ebuf, const float* __restrict__ den,
        const float* __restrict__ hw, float* __restrict__ acc)
{
    int idx = blockIdx.x * 4 + (threadIdx.x >> 6);
    int lane = threadIdx.x & 63;
    if (idx >= TOT) return;
    int s, d;
    if (idx < EE) { s = ei[idx]; d = ei[EE + idx]; } else { s = idx - EE; d = s; }
    float4 ex = *reinterpret_cast<const float4*>(ebuf + (size_t)idx * 4);
    float4 dn = *reinterpret_cast<const float4*>(den + (size_t)d * 4);
    int head = lane >> 4;
    float exs = (head == 0) ? ex.x : (head == 1) ? ex.y : (head == 2) ? ex.z : ex.w;
    float dns = (head == 0) ? dn.x : (head == 1) ? dn.y : (head == 2) ? dn.z : dn.w;
    float al = exs / dns;
    float4 hv = reinterpret_cast<const float4*>(hw + (size_t)s * 256)[lane];
    float4 v = make_float4(hv.x * al, hv.y * al, hv.z * al, hv.w * al);
    red4(acc + (size_t)d * 256 + lane * 4, v);
}

// ---------------- LayerNorm(256) of (in+bias), ReLU, output rounded to tf32 grid --------
__global__ void ln_relu_k(const float* __restrict__ in, const float* __restrict__ bias,
                          const float* __restrict__ g, const float* __restrict__ b,
                          float* __restrict__ out)
{
    int row = (blockIdx.x * blockDim.x + threadIdx.x) >> 5;
    int lane = threadIdx.x & 31;
    if (row >= NN) return;
    const float4* ip = reinterpret_cast<const float4*>(in + (size_t)row * 256);
    const float4* bsp = reinterpret_cast<const float4*>(bias);
    float4 v0 = ip[lane * 2], v1 = ip[lane * 2 + 1];
    float4 a0 = bsp[lane * 2], a1 = bsp[lane * 2 + 1];
    v0.x += a0.x; v0.y += a0.y; v0.z += a0.z; v0.w += a0.w;
    v1.x += a1.x; v1.y += a1.y; v1.z += a1.z; v1.w += a1.w;
    float sum = v0.x + v0.y + v0.z + v0.w + v1.x + v1.y + v1.z + v1.w;
#pragma unroll
    for (int off = 16; off; off >>= 1) sum += __shfl_xor_sync(0xffffffffu, sum, off);
    float mean = sum * (1.f / 256.f);
    float c0x = v0.x - mean, c0y = v0.y - mean, c0z = v0.z - mean, c0w = v0.w - mean;
    float c1x = v1.x - mean, c1y = v1.y - mean, c1z = v1.z - mean, c1w = v1.w - mean;
    float sq = c0x * c0x + c0y * c0y + c0z * c0z + c0w * c0w
             + c1x * c1x + c1y * c1y + c1z * c1z + c1w * c1w;
#pragma unroll
    for (int off = 16; off; off >>= 1) sq += __shfl_xor_sync(0xffffffffu, sq, off);
    float r = rsqrtf(sq * (1.f / 256.f) + 1e-5f);
    const float4* gp = reinterpret_cast<const float4*>(g);
    const float4* bp = reinterpret_cast<const float4*>(b);
    float4 g0 = gp[lane * 2], g1 = gp[lane * 2 + 1];
    float4 b0 = bp[lane * 2], b1 = bp[lane * 2 + 1];
    float4 o0, o1;
    o0.x = rnd_tf32(fmaxf(c0x * r * g0.x + b0.x, 0.f));
    o0.y = rnd_tf32(fmaxf(c0y * r * g0.y + b0.y, 0.f));
    o0.z = rnd_tf32(fmaxf(c0z * r * g0.z + b0.z, 0.f));
    o0.w = rnd_tf32(fmaxf(c0w * r * g0.w + b0.w, 0.f));
    o1.x = rnd_tf32(fmaxf(c1x * r * g1.x + b1.x, 0.f));
    o1.y = rnd_tf32(fmaxf(c1y * r * g1.y + b1.y, 0.f));
    o1.z = rnd_tf32(fmaxf(c1z * r * g1.z + b1.z, 0.f));
    o1.w = rnd_tf32(fmaxf(c1w * r * g1.w + b1.w, 0.f));
    float4* op = reinterpret_cast<float4*>(out + (size_t)row * 256);
    op[lane * 2] = o0;
    op[lane * 2 + 1] = o1;
}

// ---------------- final LayerNorm(128) + L2 normalize ----------------
__global__ void ln_norm_k(const float* __restrict__ in, const float* __restrict__ g,
                          const float* __restrict__ b, float* __restrict__ out)
{
    int row = (blockIdx.x * blockDim.x + threadIdx.x) >> 5;
    int lane = threadIdx.x & 31;
    if (row >= NN) return;
    float4 v = reinterpret_cast<const float4*>(in + (size_t)row * 128)[lane];
    float sum = v.x + v.y + v.z + v.w;
#pragma unroll
    for (int off = 16; off; off >>= 1) sum += __shfl_xor_sync(0xffffffffu, sum, off);
    float mean = sum * (1.f / 128.f);
    float cx = v.x - mean, cy = v.y - mean, cz = v.z - mean, cw = v.w - mean;
    float sq = cx * cx + cy * cy + cz * cz + cw * cw;
#pragma unroll
    for (int off = 16; off; off >>= 1) sq += __shfl_xor_sync(0xffffffffu, sq, off);
    float r = rsqrtf(sq * (1.f / 128.f) + 1e-5f);
    float4 gv = reinterpret_cast<const float4*>(g)[lane];
    float4 bv = reinterpret_cast<const float4*>(b)[lane];
    float4 y;
    y.x = cx * r * gv.x + bv.x;
    y.y = cy * r * gv.y + bv.y;
    y.z = cz * r * gv.z + bv.z;
    y.w = cw * r * gv.w + bv.w;
    float n2 = y.x * y.x + y.y * y.y + y.z * y.z + y.w * y.w;
#pragma unroll
    for (int off = 16; off; off >>= 1) n2 += __shfl_xor_sync(0xffffffffu, n2, off);
    float inv = 1.f / fmaxf(sqrtf(n2), 1e-12f);
    y.x *= inv; y.y *= inv; y.z *= inv; y.w *= inv;
    reinterpret_cast<float4*>(out + (size_t)row * 128)[lane] = y;
}

// ---------------- launcher ----------------
extern "C" void kernel_launch(void* const* d_in, const int* in_sizes, int n_in,
                              void* d_out, int out_size)
{
    const float* x       = (const float*)d_in[0];
    const int*   ei_bu   = (const int*)d_in[1];
    const int*   ei_td   = (const int*)d_in[2];
    const float* Wp      = (const float*)d_in[3];
    const float* bp      = (const float*)d_in[4];
    const float* W_bu    = (const float*)d_in[5];
    const float* asrc_bu = (const float*)d_in[6];
    const float* adst_bu = (const float*)d_in[7];
    const float* bias_bu = (const float*)d_in[8];
    const float* W_td    = (const float*)d_in[9];
    const float* asrc_td = (const float*)d_in[10];
    const float* adst_td = (const float*)d_in[11];
    const float* bias_td = (const float*)d_in[12];
    const float* Wf      = (const float*)d_in[13];
    const float* bf      = (const float*)d_in[14];
    const float* g_bu    = (const float*)d_in[15];
    const float* b_bu    = (const float*)d_in[16];
    const float* g_td    = (const float*)d_in[17];
    const float* b_td    = (const float*)d_in[18];
    const float* g_out   = (const float*)d_in[19];
    const float* b_out   = (const float*)d_in[20];
    float* out = (float*)d_out;

    float *ph, *phw, *pacc, *pxbu, *pxtd, *pas, *pad, *pden, *pe, *ptmp, *pwt;
    unsigned* pm;
    cudaGetSymbolAddress((void**)&ph,   g_h);
    cudaGetSymbolAddress((void**)&phw,  g_hw);
    cudaGetSymbolAddress((void**)&pacc, g_acc);
    cudaGetSymbolAddress((void**)&pxbu, g_xbu);
    cudaGetSymbolAddress((void**)&pxtd, g_xtd);
    cudaGetSymbolAddress((void**)&pas,  g_as);
    cudaGetSymbolAddress((void**)&pad,  g_ad);
    cudaGetSymbolAddress((void**)&pm,   g_m);
    cudaGetSymbolAddress((void**)&pden, g_den);
    cudaGetSymbolAddress((void**)&pe,   g_e);
    cudaGetSymbolAddress((void**)&ptmp, g_tmp);
    cudaGetSymbolAddress((void**)&pwt,  g_wt);

    const int mblocks = (NN + 127) / 128;               // 1563
    const dim3 gemmGrid256(2, mblocks);
    const dim3 gemmGrid128(1, mblocks);
    const int warpRowBlocks = (NN * 32) / 256;          // 25000
    const int edgeBlocks    = (TOT + 255) / 256;        // 1563
    const int scatBlocks    = (TOT + 3) / 4;            // 100000

    // pre-round weights (W_bu | W_td | Wf) once
    round_w_k<<<256, 256>>>(W_bu, W_td, Wf, pwt);

    // h = round_tf32(relu(x @ Wp + bp))   (cvt path: x is raw fp32)
    tgemm_k<true, true, true><<<gemmGrid256, 256>>>(x, Wp, bp, ph, NN, 256, 256);

    const int*   eis[2]   = {ei_bu, ei_td};
    const float* asr[2]   = {asrc_bu, asrc_td};
    const float* ads[2]   = {adst_bu, adst_td};
    const float* bis[2]   = {bias_bu, bias_td};
    const float* gln[2]   = {g_bu, g_td};
    const float* bln[2]   = {b_bu, b_td};
    float*       xdir[2]  = {pxbu, pxtd};

    for (int dir = 0; dir < 2; dir++) {
        tgemm_async_k<false, false><<<gemmGrid256, 256>>>(
            ph, ph, 256, pwt + dir * 65536, nullptr, phw, NN, 256, 256);
        attcoef_k<<<warpRowBlocks, 256>>>(phw, asr[dir], ads[dir], pas, pad);
        cudaMemsetAsync(pacc, 0, (size_t)NN * 256 * sizeof(float));
        cudaMemsetAsync(pm,   0, (size_t)NN * 4 * sizeof(unsigned));
        cudaMemsetAsync(pden, 0, (size_t)NN * 4 * sizeof(float));
        edge_logits_k<<<edgeBlocks, 256>>>(eis[dir], pas, pad, pe, pm);
        edge_exp_k<<<edgeBlocks, 256>>>(eis[dir], pm, pe, pden);
        edge_scatter_k<<<scatBlocks, 256>>>(eis[dir], pe, pden, phw, pacc);
        ln_relu_k<<<warpRowBlocks, 256>>>(pacc, bis[dir], gln[dir], bln[dir], xdir[dir]);
    }

    // out_pre = concat(x_bu, x_td) @ Wf + bf ; then LN + L2 normalize
    tgemm_async_k<false, true><<<gemmGrid128, 256>>>(
        pxbu, pxtd, 256, pwt + 131072, bf, ptmp, NN, 512, 128);
    ln_norm_k<<<warpRowBlocks, 256>>>(ptmp, g_out, b_out, out);
}

// round 7
// speedup vs baseline: 2.5870x; 1.0780x over previous
#include <cuda_runtime.h>
#include <cstdint>

#define NN 200000
#define EE 200000
#define TOT (NN + EE)

// ---------------- scratch (static device globals; no runtime allocation) ----------------
__device__ float    g_h  [(size_t)NN * 256];
__device__ float    g_hw [(size_t)NN * 256];
__device__ float    g_acc[(size_t)NN * 256];
__device__ float    g_xbu[(size_t)NN * 256];
__device__ float    g_xtd[(size_t)NN * 256];
__device__ float    g_as [NN * 4];
__device__ float    g_ad [NN * 4];
__device__ unsigned g_m  [NN * 4];
__device__ float    g_den[NN * 4];
__device__ float    g_e  [(size_t)TOT * 4];
__device__ float    g_wt [3 * 65536];     // pre-rounded W_bu | W_td | Wf

// ---------------- helpers ----------------
__device__ __forceinline__ unsigned fmap(float f) {
    unsigned u = __float_as_uint(f);
    return (u & 0x80000000u) ? ~u : (u | 0x80000000u);
}
__device__ __forceinline__ float funmap(unsigned u) {
    return (u & 0x80000000u) ? __uint_as_float(u ^ 0x80000000u) : __uint_as_float(~u);
}
__device__ __forceinline__ unsigned f2tf32(float f) {
    unsigned r;
    asm("cvt.rna.tf32.f32 %0, %1;" : "=r"(r) : "f"(f));
    return r;
}
__device__ __forceinline__ float rnd_tf32(float f) { return __uint_as_float(f2tf32(f)); }

__device__ __forceinline__ void mma_tf32(float c[4], const unsigned a[4], const unsigned b[2]) {
    asm volatile(
        "mma.sync.aligned.m16n8k8.row.col.f32.tf32.tf32.f32 "
        "{%0,%1,%2,%3}, {%4,%5,%6,%7}, {%8,%9}, {%0,%1,%2,%3};\n"
        : "+f"(c[0]), "+f"(c[1]), "+f"(c[2]), "+f"(c[3])
        : "r"(a[0]), "r"(a[1]), "r"(a[2]), "r"(a[3]), "r"(b[0]), "r"(b[1]));
}

__device__ __forceinline__ void cp16(void* smem_dst, const void* gsrc, bool pred) {
    uint32_t s = (uint32_t)__cvta_generic_to_shared(smem_dst);
    int sz = pred ? 16 : 0;   // sz=0 -> cp.async zero-fills the 16 bytes
    asm volatile("cp.async.cg.shared.global [%0], [%1], 16, %2;\n"
                 :: "r"(s), "l"(gsrc), "r"(sz));
}
__device__ __forceinline__ void cp_commit() { asm volatile("cp.async.commit_group;\n"); }
template<int N>
__device__ __forceinline__ void cp_wait() { asm volatile("cp.async.wait_group %0;\n" :: "n"(N)); }

__device__ __forceinline__ void red4(float* p, float4 v) {
    asm volatile("red.global.add.v4.f32 [%0], {%1,%2,%3,%4};\n"
                 :: "l"(p), "f"(v.x), "f"(v.y), "f"(v.z), "f"(v.w) : "memory");
}

// ---------------- GEMM path 1: register-staged with tf32 cvt (raw fp32 input x) ----------
template<bool RELU, bool BIAS, bool ROUND>
__global__ void __launch_bounds__(256) tgemm_k(
    const float* __restrict__ A1,
    const float* __restrict__ B, const float* __restrict__ bias,
    float* __restrict__ C, int M, int K, int Nc)
{
    const int BM = 128, BK = 16;
    __shared__ float As[2][BM][20];
    __shared__ float Bs[2][BK][136];

    int tid = threadIdx.x;
    int lane = tid & 31, wid = tid >> 5;
    int g = lane >> 2, t = lane & 3;
    int wm = wid >> 2, wn = wid & 3;
    int rowBase = blockIdx.y * BM;
    int colBase = blockIdx.x * 128;

    float acc[4][4][4];
#pragma unroll
    for (int i = 0; i < 4; i++)
#pragma unroll
        for (int j = 0; j < 4; j++)
#pragma unroll
            for (int r = 0; r < 4; r++) acc[i][j][r] = 0.f;

    int ar0 = tid >> 2,          ac0 = (tid & 3) * 4;
    int ar1 = (tid + 256) >> 2;
    int br0 = tid >> 5,          bc0 = (tid & 31) * 4;
    int br1 = (tid + 256) >> 5;

    float4 pa0, pa1, pb0, pb1;
    const float4 z4 = make_float4(0.f, 0.f, 0.f, 0.f);

    int ntiles = K / BK;
    int s = 0;
    {
        int r0 = rowBase + ar0, r1 = rowBase + ar1;
        pa0 = (r0 < M) ? *reinterpret_cast<const float4*>(A1 + (size_t)r0 * K + ac0) : z4;
        pa1 = (r1 < M) ? *reinterpret_cast<const float4*>(A1 + (size_t)r1 * K + ac0) : z4;
        pb0 = *reinterpret_cast<const float4*>(B + (size_t)br0 * Nc + colBase + bc0);
        pb1 = *reinterpret_cast<const float4*>(B + (size_t)br1 * Nc + colBase + bc0);
        As[0][ar0][ac0 + 0] = rnd_tf32(pa0.x); As[0][ar0][ac0 + 1] = rnd_tf32(pa0.y);
        As[0][ar0][ac0 + 2] = rnd_tf32(pa0.z); As[0][ar0][ac0 + 3] = rnd_tf32(pa0.w);
        As[0][ar1][ac0 + 0] = rnd_tf32(pa1.x); As[0][ar1][ac0 + 1] = rnd_tf32(pa1.y);
        As[0][ar1][ac0 + 2] = rnd_tf32(pa1.z); As[0][ar1][ac0 + 3] = rnd_tf32(pa1.w);
        Bs[0][br0][bc0 + 0] = rnd_tf32(pb0.x); Bs[0][br0][bc0 + 1] = rnd_tf32(pb0.y);
        Bs[0][br0][bc0 + 2] = rnd_tf32(pb0.z); Bs[0][br0][bc0 + 3] = rnd_tf32(pb0.w);
        Bs[0][br1][bc0 + 0] = rnd_tf32(pb1.x); Bs[0][br1][bc0 + 1] = rnd_tf32(pb1.y);
        Bs[0][br1][bc0 + 2] = rnd_tf32(pb1.z); Bs[0][br1][bc0 + 3] = rnd_tf32(pb1.w);
    }
    __syncthreads();
    for (int kt = 0; kt < ntiles; kt++) {
        bool more = (kt + 1 < ntiles);
        if (more) {
            int kk = (kt + 1) * BK;
            int r0 = rowBase + ar0, r1 = rowBase + ar1;
            pa0 = (r0 < M) ? *reinterpret_cast<const float4*>(A1 + (size_t)r0 * K + kk + ac0) : z4;
            pa1 = (r1 < M) ? *reinterpret_cast<const float4*>(A1 + (size_t)r1 * K + kk + ac0) : z4;
            pb0 = *reinterpret_cast<const float4*>(B + (size_t)(kk + br0) * Nc + colBase + bc0);
            pb1 = *reinterpret_cast<const float4*>(B + (size_t)(kk + br1) * Nc + colBase + bc0);
        }
#pragma unroll
        for (int ks = 0; ks < 2; ks++) {
            int k0 = ks * 8;
            unsigned a[4][4], b[4][2];
#pragma unroll
            for (int mt = 0; mt < 4; mt++) {
                int m0 = wm * 64 + mt * 16;
                a[mt][0] = __float_as_uint(As[s][m0 + g][k0 + t]);
                a[mt][1] = __float_as_uint(As[s][m0 + g + 8][k0 + t]);
                a[mt][2] = __float_as_uint(As[s][m0 + g][k0 + t + 4]);
                a[mt][3] = __float_as_uint(As[s][m0 + g + 8][k0 + t + 4]);
            }
#pragma unroll
            for (int nt = 0; nt < 4; nt++) {
                int n0 = wn * 32 + nt * 8;
                b[nt][0] = __float_as_uint(Bs[s][k0 + t][n0 + g]);
                b[nt][1] = __float_as_uint(Bs[s][k0 + t + 4][n0 + g]);
            }
#pragma unroll
            for (int mt = 0; mt < 4; mt++)
#pragma unroll
                for (int nt = 0; nt < 4; nt++)
                    mma_tf32(acc[mt][nt], a[mt], b[nt]);
        }
        if (more) {
            int so = s ^ 1;
            As[so][ar0][ac0 + 0] = rnd_tf32(pa0.x); As[so][ar0][ac0 + 1] = rnd_tf32(pa0.y);
            As[so][ar0][ac0 + 2] = rnd_tf32(pa0.z); As[so][ar0][ac0 + 3] = rnd_tf32(pa0.w);
            As[so][ar1][ac0 + 0] = rnd_tf32(pa1.x); As[so][ar1][ac0 + 1] = rnd_tf32(pa1.y);
            As[so][ar1][ac0 + 2] = rnd_tf32(pa1.z); As[so][ar1][ac0 + 3] = rnd_tf32(pa1.w);
            Bs[so][br0][bc0 + 0] = rnd_tf32(pb0.x); Bs[so][br0][bc0 + 1] = rnd_tf32(pb0.y);
            Bs[so][br0][bc0 + 2] = rnd_tf32(pb0.z); Bs[so][br0][bc0 + 3] = rnd_tf32(pb0.w);
            Bs[so][br1][bc0 + 0] = rnd_tf32(pb1.x); Bs[so][br1][bc0 + 1] = rnd_tf32(pb1.y);
            Bs[so][br1][bc0 + 2] = rnd_tf32(pb1.z); Bs[so][br1][bc0 + 3] = rnd_tf32(pb1.w);
            __syncthreads();
        }
        s ^= 1;
    }

#pragma unroll
    for (int nt = 0; nt < 4; nt++) {
        int col = colBase + wn * 32 + nt * 8 + 2 * t;
        float2 bb = make_float2(0.f, 0.f);
        if (BIAS) bb = *reinterpret_cast<const float2*>(bias + col);
#pragma unroll
        for (int mt = 0; mt < 4; mt++) {
            int row0 = rowBase + wm * 64 + mt * 16 + g;
            int row1 = row0 + 8;
            float2 v0 = make_float2(acc[mt][nt][0] + bb.x, acc[mt][nt][1] + bb.y);
            float2 v1 = make_float2(acc[mt][nt][2] + bb.x, acc[mt][nt][3] + bb.y);
            if (RELU) {
                v0.x = fmaxf(v0.x, 0.f); v0.y = fmaxf(v0.y, 0.f);
                v1.x = fmaxf(v1.x, 0.f); v1.y = fmaxf(v1.y, 0.f);
            }
            if (ROUND) {
                v0.x = rnd_tf32(v0.x); v0.y = rnd_tf32(v0.y);
                v1.x = rnd_tf32(v1.x); v1.y = rnd_tf32(v1.y);
            }
            if (row0 < M) *reinterpret_cast<float2*>(C + (size_t)row0 * Nc + col) = v0;
            if (row1 < M) *reinterpret_cast<float2*>(C + (size_t)row1 * Nc + col) = v1;
        }
    }
}

// ---------------- GEMM path 2: cp.async + fused attention-coefficient epilogue ----------
// C = A @ B (no bias/relu), Nc=256. Each block covers 128 cols = 2 heads.
// Also computes osrc/odst[row,head] = sum_col C[row,col]*asrc/adst[col] for its heads.
__global__ void __launch_bounds__(256) tgemm_att_k(
    const float* __restrict__ A1,
    const float* __restrict__ B,
    float* __restrict__ C, int M, int K, int Nc,
    const float* __restrict__ asrc, const float* __restrict__ adst,
    float* __restrict__ osrc, float* __restrict__ odst)
{
    const int BM = 128, BK = 16;
    __shared__ float As[2][BM][20];
    __shared__ float Bs[2][BK][136];
    __shared__ float attS[128][2];
    __shared__ float attD[128][2];

    int tid = threadIdx.x;
    int lane = tid & 31, wid = tid >> 5;
    int g = lane >> 2, t = lane & 3;
    int wm = wid >> 2, wn = wid & 3;
    int rowBase = blockIdx.y * BM;
    int colBase = blockIdx.x * 128;

    if (tid < 128) {
        attS[tid][0] = 0.f; attS[tid][1] = 0.f;
        attD[tid][0] = 0.f; attD[tid][1] = 0.f;
    }

    float acc[4][4][4];
#pragma unroll
    for (int i = 0; i < 4; i++)
#pragma unroll
        for (int j = 0; j < 4; j++)
#pragma unroll
            for (int r = 0; r < 4; r++) acc[i][j][r] = 0.f;

    int ar0 = tid >> 2, ac0 = (tid & 3) * 4;
    int ar1 = ar0 + 64;
    int br0 = tid >> 5, bc0 = (tid & 31) * 4;
    int br1 = br0 + 8;

    auto loadtile = [&](int kt, int sb) {
        int r0 = rowBase + ar0, r1 = rowBase + ar1;
        cp16(&As[sb][ar0][ac0], A1 + (size_t)r0 * K + kt + ac0, r0 < M);
        cp16(&As[sb][ar1][ac0], A1 + (size_t)r1 * K + kt + ac0, r1 < M);
        cp16(&Bs[sb][br0][bc0], B + (size_t)(kt + br0) * Nc + colBase + bc0, true);
        cp16(&Bs[sb][br1][bc0], B + (size_t)(kt + br1) * Nc + colBase + bc0, true);
        cp_commit();
    };

    int ntiles = K / BK;
    loadtile(0, 0);
    for (int kt = 0; kt < ntiles; kt++) {
        int s = kt & 1;
        if (kt + 1 < ntiles) loadtile((kt + 1) * BK, s ^ 1);
        else cp_commit();
        cp_wait<1>();
        __syncthreads();
#pragma unroll
        for (int ks = 0; ks < 2; ks++) {
            int k0 = ks * 8;
            unsigned a[4][4], b[4][2];
#pragma unroll
            for (int mt = 0; mt < 4; mt++) {
                int m0 = wm * 64 + mt * 16;
                a[mt][0] = __float_as_uint(As[s][m0 + g][k0 + t]);
                a[mt][1] = __float_as_uint(As[s][m0 + g + 8][k0 + t]);
                a[mt][2] = __float_as_uint(As[s][m0 + g][k0 + t + 4]);
                a[mt][3] = __float_as_uint(As[s][m0 + g + 8][k0 + t + 4]);
            }
#pragma unroll
            for (int nt = 0; nt < 4; nt++) {
                int n0 = wn * 32 + nt * 8;
                b[nt][0] = __float_as_uint(Bs[s][k0 + t][n0 + g]);
                b[nt][1] = __float_as_uint(Bs[s][k0 + t + 4][n0 + g]);
            }
#pragma unroll
            for (int mt = 0; mt < 4; mt++)
#pragma unroll
                for (int nt = 0; nt < 4; nt++)
                    mma_tf32(acc[mt][nt], a[mt], b[nt]);
        }
        __syncthreads();
    }

    // load attention vectors for this thread's 8 columns
    float as_c[4][2], ad_c[4][2];
#pragma unroll
    for (int nt = 0; nt < 4; nt++) {
        int colG = colBase + wn * 32 + nt * 8 + 2 * t;
        float2 a2 = *reinterpret_cast<const float2*>(asrc + colG);
        float2 d2 = *reinterpret_cast<const float2*>(adst + colG);
        as_c[nt][0] = a2.x; as_c[nt][1] = a2.y;
        ad_c[nt][0] = d2.x; ad_c[nt][1] = d2.y;
    }
    int hl = wn >> 1;  // head-local within block

#pragma unroll
    for (int mt = 0; mt < 4; mt++) {
        float s0 = 0.f, d0 = 0.f, s1 = 0.f, d1 = 0.f;
#pragma unroll
        for (int nt = 0; nt < 4; nt++) {
            s0 += acc[mt][nt][0] * as_c[nt][0] + acc[mt][nt][1] * as_c[nt][1];
            d0 += acc[mt][nt][0] * ad_c[nt][0] + acc[mt][nt][1] * ad_c[nt][1];
            s1 += acc[mt][nt][2] * as_c[nt][0] + acc[mt][nt][3] * as_c[nt][1];
            d1 += acc[mt][nt][2] * ad_c[nt][0] + acc[mt][nt][3] * ad_c[nt][1];
        }
#pragma unroll
        for (int off = 1; off <= 2; off <<= 1) {
            s0 += __shfl_xor_sync(0xffffffffu, s0, off);
            d0 += __shfl_xor_sync(0xffffffffu, d0, off);
            s1 += __shfl_xor_sync(0xffffffffu, s1, off);
            d1 += __shfl_xor_sync(0xffffffffu, d1, off);
        }
        if (t == 0) {
            int lr = wm * 64 + mt * 16 + g;
            atomicAdd(&attS[lr][hl], s0);
            atomicAdd(&attD[lr][hl], d0);
            atomicAdd(&attS[lr + 8][hl], s1);
            atomicAdd(&attD[lr + 8][hl], d1);
        }
        // store C tile
#pragma unroll
        for (int nt = 0; nt < 4; nt++) {
            int col = colBase + wn * 32 + nt * 8 + 2 * t;
            int row0 = rowBase + wm * 64 + mt * 16 + g;
            int row1 = row0 + 8;
            if (row0 < M) *reinterpret_cast<float2*>(C + (size_t)row0 * Nc + col)
                = make_float2(acc[mt][nt][0], acc[mt][nt][1]);
            if (row1 < M) *reinterpret_cast<float2*>(C + (size_t)row1 * Nc + col)
                = make_float2(acc[mt][nt][2], acc[mt][nt][3]);
        }
    }
    __syncthreads();
    if (tid < 256) {
        int lr = tid >> 1, h = tid & 1;
        int grow = rowBase + lr;
        if (grow < M) {
            osrc[(size_t)grow * 4 + blockIdx.x * 2 + h] = attS[lr][h];
            odst[(size_t)grow * 4 + blockIdx.x * 2 + h] = attD[lr][h];
        }
    }
}

// ---------------- final GEMM: concat(A1,A2)@Wf + bf, fused LN(128) + L2 normalize --------
__global__ void __launch_bounds__(256) tgemm_final_k(
    const float* __restrict__ A1, const float* __restrict__ A2, int K1,
    const float* __restrict__ B, const float* __restrict__ bias,
    const float* __restrict__ gw, const float* __restrict__ bw,
    float* __restrict__ C, int M, int K)
{
    const int BM = 128, BK = 16, Nc = 128;
    __shared__ float As[2][BM][20];
    __shared__ float Bs[2][BK][136];
    __shared__ float redS[128], redQ[128], redN[128];

    int tid = threadIdx.x;
    int lane = tid & 31, wid = tid >> 5;
    int g = lane >> 2, t = lane & 3;
    int wm = wid >> 2, wn = wid & 3;
    int rowBase = blockIdx.x * BM;

    if (tid < 128) { redS[tid] = 0.f; redQ[tid] = 0.f; redN[tid] = 0.f; }

    float acc[4][4][4];
#pragma unroll
    for (int i = 0; i < 4; i++)
#pragma unroll
        for (int j = 0; j < 4; j++)
#pragma unroll
            for (int r = 0; r < 4; r++) acc[i][j][r] = 0.f;

    int ar0 = tid >> 2, ac0 = (tid & 3) * 4;
    int ar1 = ar0 + 64;
    int br0 = tid >> 5, bc0 = (tid & 31) * 4;
    int br1 = br0 + 8;

    auto loadtile = [&](int kt, int sb) {
        const float* Ap; int kk, stride;
        if (kt < K1) { Ap = A1; kk = kt;      stride = K1;     }
        else         { Ap = A2; kk = kt - K1; stride = K - K1; }
        int r0 = rowBase + ar0, r1 = rowBase + ar1;
        cp16(&As[sb][ar0][ac0], Ap + (size_t)r0 * stride + kk + ac0, r0 < M);
        cp16(&As[sb][ar1][ac0], Ap + (size_t)r1 * stride + kk + ac0, r1 < M);
        cp16(&Bs[sb][br0][bc0], B + (size_t)(kt + br0) * Nc + bc0, true);
        cp16(&Bs[sb][br1][bc0], B + (size_t)(kt + br1) * Nc + bc0, true);
        cp_commit();
    };

    int ntiles = K / BK;
    loadtile(0, 0);
    for (int kt = 0; kt < ntiles; kt++) {
        int s = kt & 1;
        if (kt + 1 < ntiles) loadtile((kt + 1) * BK, s ^ 1);
        else cp_commit();
        cp_wait<1>();
        __syncthreads();
#pragma unroll
        for (int ks = 0; ks < 2; ks++) {
            int k0 = ks * 8;
            unsigned a[4][4], b[4][2];
#pragma unroll
            for (int mt = 0; mt < 4; mt++) {
                int m0 = wm * 64 + mt * 16;
                a[mt][0] = __float_as_uint(As[s][m0 + g][k0 + t]);
                a[mt][1] = __float_as_uint(As[s][m0 + g + 8][k0 + t]);
                a[mt][2] = __float_as_uint(As[s][m0 + g][k0 + t + 4]);
                a[mt][3] = __float_as_uint(As[s][m0 + g + 8][k0 + t + 4]);
            }
#pragma unroll
            for (int nt = 0; nt < 4; nt++) {
                int n0 = wn * 32 + nt * 8;
                b[nt][0] = __float_as_uint(Bs[s][k0 + t][n0 + g]);
                b[nt][1] = __float_as_uint(Bs[s][k0 + t + 4][n0 + g]);
            }
#pragma unroll
            for (int mt = 0; mt < 4; mt++)
#pragma unroll
                for (int nt = 0; nt < 4; nt++)
                    mma_tf32(acc[mt][nt], a[mt], b[nt]);
        }
        __syncthreads();
    }

    // ---- epilogue: add bias, LN over 128 cols, L2 normalize ----
#pragma unroll
    for (int nt = 0; nt < 4; nt++) {
        int col = wn * 32 + nt * 8 + 2 * t;
        float2 bb = *reinterpret_cast<const float2*>(bias + col);
#pragma unroll
        for (int mt = 0; mt < 4; mt++) {
            acc[mt][nt][0] += bb.x; acc[mt][nt][1] += bb.y;
            acc[mt][nt][2] += bb.x; acc[mt][nt][3] += bb.y;
        }
    }
    // row sums / sumsq
#pragma unroll
    for (int mt = 0; mt < 4; mt++) {
        float s0 = 0.f, q0 = 0.f, s1 = 0.f, q1 = 0.f;
#pragma unroll
        for (int nt = 0; nt < 4; nt++) {
            s0 += acc[mt][nt][0] + acc[mt][nt][1];
            q0 += acc[mt][nt][0] * acc[mt][nt][0] + acc[mt][nt][1] * acc[mt][nt][1];
            s1 += acc[mt][nt][2] + acc[mt][nt][3];
            q1 += acc[mt][nt][2] * acc[mt][nt][2] + acc[mt][nt][3] * acc[mt][nt][3];
        }
#pragma unroll
        for (int off = 1; off <= 2; off <<= 1) {
            s0 += __shfl_xor_sync(0xffffffffu, s0, off);
            q0 += __shfl_xor_sync(0xffffffffu, q0, off);
            s1 += __shfl_xor_sync(0xffffffffu, s1, off);
            q1 += __shfl_xor_sync(0xffffffffu, q1, off);
        }
        if (t == 0) {
            int lr = wm * 64 + mt * 16 + g;
            atomicAdd(&redS[lr], s0); atomicAdd(&redQ[lr], q0);
            atomicAdd(&redS[lr + 8], s1); atomicAdd(&redQ[lr + 8], q1);
        }
    }
    __syncthreads();
    // normalize + gamma/beta; accumulate y^2
#pragma unroll
    for (int mt = 0; mt < 4; mt++) {
        int lr0 = wm * 64 + mt * 16 + g, lr1 = lr0 + 8;
        float m0 = redS[lr0] * (1.f / 128.f), m1 = redS[lr1] * (1.f / 128.f);
        float var0 = redQ[lr0] * (1.f / 128.f) - m0 * m0;
        float var1 = redQ[lr1] * (1.f / 128.f) - m1 * m1;
        float r0 = rsqrtf(var0 + 1e-5f), r1 = rsqrtf(var1 + 1e-5f);
        float n0 = 0.f, n1 = 0.f;
#pragma unroll
        for (int nt = 0; nt < 4; nt++) {
            int col = wn * 32 + nt * 8 + 2 * t;
            float2 gg = *reinterpret_cast<const float2*>(gw + col);
            float2 b2 = *reinterpret_cast<const float2*>(bw + col);
            float y00 = (acc[mt][nt][0] - m0) * r0 * gg.x + b2.x;
            float y01 = (acc[mt][nt][1] - m0) * r0 * gg.y + b2.y;
            float y10 = (acc[mt][nt][2] - m1) * r1 * gg.x + b2.x;
            float y11 = (acc[mt][nt][3] - m1) * r1 * gg.y + b2.y;
            acc[mt][nt][0] = y00; acc[mt][nt][1] = y01;
            acc[mt][nt][2] = y10; acc[mt][nt][3] = y11;
            n0 += y00 * y00 + y01 * y01;
            n1 += y10 * y10 + y11 * y11;
        }
#pragma unroll
        for (int off = 1; off <= 2; off <<= 1) {
            n0 += __shfl_xor_sync(0xffffffffu, n0, off);
            n1 += __shfl_xor_sync(0xffffffffu, n1, off);
        }
        if (t == 0) { atomicAdd(&redN[lr0], n0); atomicAdd(&redN[lr1], n1); }
    }
    __syncthreads();
#pragma unroll
    for (int mt = 0; mt < 4; mt++) {
        int lr0 = wm * 64 + mt * 16 + g, lr1 = lr0 + 8;
        float inv0 = 1.f / fmaxf(sqrtf(redN[lr0]), 1e-12f);
        float inv1 = 1.f / fmaxf(sqrtf(redN[lr1]), 1e-12f);
        int row0 = rowBase + lr0, row1 = rowBase + lr1;
#pragma unroll
        for (int nt = 0; nt < 4; nt++) {
            int col = wn * 32 + nt * 8 + 2 * t;
            if (row0 < M) *reinterpret_cast<float2*>(C + (size_t)row0 * 128 + col)
                = make_float2(acc[mt][nt][0] * inv0, acc[mt][nt][1] * inv0);
            if (row1 < M) *reinterpret_cast<float2*>(C + (size_t)row1 * 128 + col)
                = make_float2(acc[mt][nt][2] * inv1, acc[mt][nt][3] * inv1);
        }
    }
}

// ---------------- round weights once into g_wt ----------------
__global__ void round_w_k(const float* __restrict__ w0, const float* __restrict__ w1,
                          const float* __restrict__ w2, float* __restrict__ out)
{
    int i = blockIdx.x * 256 + threadIdx.x;
    out[i]          = rnd_tf32(w0[i]);
    out[65536 + i]  = rnd_tf32(w1[i]);
    out[131072 + i] = rnd_tf32(w2[i]);
}

// ---------------- edge pass 1: logits + segment max ----------------
__global__ void edge_logits_k(const int* __restrict__ ei,
                              const float* __restrict__ asrc, const float* __restrict__ adst,
                              float* __restrict__ ebuf, unsigned* __restrict__ m)
{
    int i = blockIdx.x * blockDim.x + threadIdx.x;
    if (i >= TOT) return;
    int s, d;
    if (i < EE) { s = ei[i]; d = ei[EE + i]; } else { s = i - EE; d = s; }
    float4 as = *reinterpret_cast<const float4*>(asrc + (size_t)s * 4);
    float4 ad = *reinterpret_cast<const float4*>(adst + (size_t)d * 4);
    float e[4] = {as.x + ad.x, as.y + ad.y, as.z + ad.z, as.w + ad.w};
    float4 o;
    float* op = &o.x;
#pragma unroll
    for (int h = 0; h < 4; h++) {
        float v = e[h] > 0.f ? e[h] : 0.2f * e[h];
        op[h] = v;
        atomicMax(m + d * 4 + h, fmap(v));
    }
    *reinterpret_cast<float4*>(ebuf + (size_t)i * 4) = o;
}

// ---------------- edge pass 2: exp + segment sum (v4 reduction) ----------------
__global__ void edge_exp_k(const int* __restrict__ ei,
                           const unsigned* __restrict__ m, float* __restrict__ ebuf,
                           float* __restrict__ den)
{
    int i = blockIdx.x * blockDim.x + threadIdx.x;
    if (i >= TOT) return;
    int d = (i < EE) ? ei[EE + i] : (i - EE);
    float4 e = *reinterpret_cast<const float4*>(ebuf + (size_t)i * 4);
    float4 o;
    o.x = expf(e.x - funmap(m[d * 4 + 0]));
    o.y = expf(e.y - funmap(m[d * 4 + 1]));
    o.z = expf(e.z - funmap(m[d * 4 + 2]));
    o.w = expf(e.w - funmap(m[d * 4 + 3]));
    *reinterpret_cast<float4*>(ebuf + (size_t)i * 4) = o;
    red4(den + (size_t)d * 4, o);
}

// ---------------- edge pass 3: weighted scatter (64 threads/edge, v4 reductions) ----------
__global__ void __launch_bounds__(256) edge_scatter_k(const int* __restrict__ ei,
        const float* __restrict__ ebuf, const float* __restrict__ den,
        const float* __restrict__ hw, float* __restrict__ acc)
{
    int idx = blockIdx.x * 4 + (threadIdx.x >> 6);
    int lane = threadIdx.x & 63;
    if (idx >= TOT) return;
    int s, d;
    if (idx < EE) { s = ei[idx]; d = ei[EE + idx]; } else { s = idx - EE; d = s; }
    float4 ex = *reinterpret_cast<const float4*>(ebuf + (size_t)idx * 4);
    float4 dn = *reinterpret_cast<const float4*>(den + (size_t)d * 4);
    int head = lane >> 4;
    float exs = (head == 0) ? ex.x : (head == 1) ? ex.y : (head == 2) ? ex.z : ex.w;
    float dns = (head == 0) ? dn.x : (head == 1) ? dn.y : (head == 2) ? dn.z : dn.w;
    float al = exs / dns;
    float4 hv = reinterpret_cast<const float4*>(hw + (size_t)s * 256)[lane];
    float4 v = make_float4(hv.x * al, hv.y * al, hv.z * al, hv.w * al);
    red4(acc + (size_t)d * 256 + lane * 4, v);
}

// ---------------- LayerNorm(256) of (in+bias), ReLU, output rounded to tf32 grid --------
__global__ void ln_relu_k(const float* __restrict__ in, const float* __restrict__ bias,
                          const float* __restrict__ g, const float* __restrict__ b,
                          float* __restrict__ out)
{
    int row = (blockIdx.x * blockDim.x + threadIdx.x) >> 5;
    int lane = threadIdx.x & 31;
    if (row >= NN) return;
    const float4* ip = reinterpret_cast<const float4*>(in + (size_t)row * 256);
    const float4* bsp = reinterpret_cast<const float4*>(bias);
    float4 v0 = ip[lane * 2], v1 = ip[lane * 2 + 1];
    float4 a0 = bsp[lane * 2], a1 = bsp[lane * 2 + 1];
    v0.x += a0.x; v0.y += a0.y; v0.z += a0.z; v0.w += a0.w;
    v1.x += a1.x; v1.y += a1.y; v1.z += a1.z; v1.w += a1.w;
    float sum = v0.x + v0.y + v0.z + v0.w + v1.x + v1.y + v1.z + v1.w;
#pragma unroll
    for (int off = 16; off; off >>= 1) sum += __shfl_xor_sync(0xffffffffu, sum, off);
    float mean = sum * (1.f / 256.f);
    float c0x = v0.x - mean, c0y = v0.y - mean, c0z = v0.z - mean, c0w = v0.w - mean;
    float c1x = v1.x - mean, c1y = v1.y - mean, c1z = v1.z - mean, c1w = v1.w - mean;
    float sq = c0x * c0x + c0y * c0y + c0z * c0z + c0w * c0w
             + c1x * c1x + c1y * c1y + c1z * c1z + c1w * c1w;
#pragma unroll
    for (int off = 16; off; off >>= 1) sq += __shfl_xor_sync(0xffffffffu, sq, off);
    float r = rsqrtf(sq * (1.f / 256.f) + 1e-5f);
    const float4* gp = reinterpret_cast<const float4*>(g);
    const float4* bp = reinterpret_cast<const float4*>(b);
    float4 g0 = gp[lane * 2], g1 = gp[lane * 2 + 1];
    float4 b0 = bp[lane * 2], b1 = bp[lane * 2 + 1];
    float4 o0, o1;
    o0.x = rnd_tf32(fmaxf(c0x * r * g0.x + b0.x, 0.f));
    o0.y = rnd_tf32(fmaxf(c0y * r * g0.y + b0.y, 0.f));
    o0.z = rnd_tf32(fmaxf(c0z * r * g0.z + b0.z, 0.f));
    o0.w = rnd_tf32(fmaxf(c0w * r * g0.w + b0.w, 0.f));
    o1.x = rnd_tf32(fmaxf(c1x * r * g1.x + b1.x, 0.f));
    o1.y = rnd_tf32(fmaxf(c1y * r * g1.y + b1.y, 0.f));
    o1.z = rnd_tf32(fmaxf(c1z * r * g1.z + b1.z, 0.f));
    o1.w = rnd_tf32(fmaxf(c1w * r * g1.w + b1.w, 0.f));
    float4* op = reinterpret_cast<float4*>(out + (size_t)row * 256);
    op[lane * 2] = o0;
    op[lane * 2 + 1] = o1;
}

// ---------------- launcher ----------------
extern "C" void kernel_launch(void* const* d_in, const int* in_sizes, int n_in,
                              void* d_out, int out_size)
{
    const float* x       = (const float*)d_in[0];
    const int*   ei_bu   = (const int*)d_in[1];
    const int*   ei_td   = (const int*)d_in[2];
    const float* Wp      = (const float*)d_in[3];
    const float* bp      = (const float*)d_in[4];
    const float* W_bu    = (const float*)d_in[5];
    const float* asrc_bu = (const float*)d_in[6];
    const float* adst_bu = (const float*)d_in[7];
    const float* bias_bu = (const float*)d_in[8];
    const float* W_td    = (const float*)d_in[9];
    const float* asrc_td = (const float*)d_in[10];
    const float* adst_td = (const float*)d_in[11];
    const float* bias_td = (const float*)d_in[12];
    const float* Wf      = (const float*)d_in[13];
    const float* bf      = (const float*)d_in[14];
    const float* g_bu    = (const float*)d_in[15];
    const float* b_bu    = (const float*)d_in[16];
    const float* g_td    = (const float*)d_in[17];
    const float* b_td    = (const float*)d_in[18];
    const float* g_out   = (const float*)d_in[19];
    const float* b_out   = (const float*)d_in[20];
    float* out = (float*)d_out;

    float *ph, *phw, *pacc, *pxbu, *pxtd, *pas, *pad, *pden, *pe, *pwt;
    unsigned* pm;
    cudaGetSymbolAddress((void**)&ph,   g_h);
    cudaGetSymbolAddress((void**)&phw,  g_hw);
    cudaGetSymbolAddress((void**)&pacc, g_acc);
    cudaGetSymbolAddress((void**)&pxbu, g_xbu);
    cudaGetSymbolAddress((void**)&pxtd, g_xtd);
    cudaGetSymbolAddress((void**)&pas,  g_as);
    cudaGetSymbolAddress((void**)&pad,  g_ad);
    cudaGetSymbolAddress((void**)&pm,   g_m);
    cudaGetSymbolAddress((void**)&pden, g_den);
    cudaGetSymbolAddress((void**)&pe,   g_e);
    cudaGetSymbolAddress((void**)&pwt,  g_wt);

    const int mblocks = (NN + 127) / 128;               // 1563
    const dim3 gemmGrid256(2, mblocks);
    const int warpRowBlocks = (NN * 32) / 256;          // 25000
    const int edgeBlocks    = (TOT + 255) / 256;        // 1563
    const int scatBlocks    = (TOT + 3) / 4;            // 100000

    // pre-round weights (W_bu | W_td | Wf) once
    round_w_k<<<256, 256>>>(W_bu, W_td, Wf, pwt);

    // h = round_tf32(relu(x @ Wp + bp))   (cvt path: x is raw fp32)
    tgemm_k<true, true, true><<<gemmGrid256, 256>>>(x, Wp, bp, ph, NN, 256, 256);

    const int*   eis[2]   = {ei_bu, ei_td};
    const float* asr[2]   = {asrc_bu, asrc_td};
    const float* ads[2]   = {adst_bu, adst_td};
    const float* bis[2]   = {bias_bu, bias_td};
    const float* gln[2]   = {g_bu, g_td};
    const float* bln[2]   = {b_bu, b_td};
    float*       xdir[2]  = {pxbu, pxtd};

    for (int dir = 0; dir < 2; dir++) {
        tgemm_att_k<<<gemmGrid256, 256>>>(
            ph, pwt + dir * 65536, phw, NN, 256, 256,
            asr[dir], ads[dir], pas, pad);
        cudaMemsetAsync(pacc, 0, (size_t)NN * 256 * sizeof(float));
        cudaMemsetAsync(pm,   0, (size_t)NN * 4 * sizeof(unsigned));
        cudaMemsetAsync(pden, 0, (size_t)NN * 4 * sizeof(float));
        edge_logits_k<<<edgeBlocks, 256>>>(eis[dir], pas, pad, pe, pm);
        edge_exp_k<<<edgeBlocks, 256>>>(eis[dir], pm, pe, pden);
        edge_scatter_k<<<scatBlocks, 256>>>(eis[dir], pe, pden, phw, pacc);
        ln_relu_k<<<warpRowBlocks, 256>>>(pacc, bis[dir], gln[dir], bln[dir], xdir[dir]);
    }

    // out = L2norm(LN(concat(x_bu, x_td) @ Wf + bf)) fused
    tgemm_final_k<<<mblocks, 256>>>(pxbu, pxtd, 256, pwt + 131072, bf,
                                    g_out, b_out, out, NN, 512);
}

// round 8
// speedup vs baseline: 2.8659x; 1.1078x over previous
#include <cuda_runtime.h>
#include <cstdint>

#define NN 200000
#define EE 200000

// ---------------- scratch (static device globals; no runtime allocation) ----------------
__device__ float    g_h  [(size_t)NN * 256];
__device__ float    g_hw [(size_t)NN * 256];
__device__ float    g_acc[(size_t)NN * 256];
__device__ float    g_xbu[(size_t)NN * 256];
__device__ float    g_xtd[(size_t)NN * 256];
__device__ float    g_as [NN * 4];
__device__ float    g_ad [NN * 4];
__device__ unsigned g_m  [NN * 4];
__device__ float    g_den[NN * 4];
__device__ float    g_e  [(size_t)EE * 4];
__device__ float    g_wt [3 * 65536];     // pre-rounded W_bu | W_td | Wf

// ---------------- helpers ----------------
__device__ __forceinline__ unsigned fmap(float f) {
    unsigned u = __float_as_uint(f);
    return (u & 0x80000000u) ? ~u : (u | 0x80000000u);
}
__device__ __forceinline__ float funmap(unsigned u) {
    return (u & 0x80000000u) ? __uint_as_float(u ^ 0x80000000u) : __uint_as_float(~u);
}
__device__ __forceinline__ unsigned f2tf32(float f) {
    unsigned r;
    asm("cvt.rna.tf32.f32 %0, %1;" : "=r"(r) : "f"(f));
    return r;
}
__device__ __forceinline__ float rnd_tf32(float f) { return __uint_as_float(f2tf32(f)); }

__device__ __forceinline__ void mma_tf32(float c[4], const unsigned a[4], const unsigned b[2]) {
    asm volatile(
        "mma.sync.aligned.m16n8k8.row.col.f32.tf32.tf32.f32 "
        "{%0,%1,%2,%3}, {%4,%5,%6,%7}, {%8,%9}, {%0,%1,%2,%3};\n"
        : "+f"(c[0]), "+f"(c[1]), "+f"(c[2]), "+f"(c[3])
        : "r"(a[0]), "r"(a[1]), "r"(a[2]), "r"(a[3]), "r"(b[0]), "r"(b[1]));
}

__device__ __forceinline__ void cp16(void* smem_dst, const void* gsrc, bool pred) {
    uint32_t s = (uint32_t)__cvta_generic_to_shared(smem_dst);
    int sz = pred ? 16 : 0;
    asm volatile("cp.async.cg.shared.global [%0], [%1], 16, %2;\n"
                 :: "r"(s), "l"(gsrc), "r"(sz));
}
__device__ __forceinline__ void cp_commit() { asm volatile("cp.async.commit_group;\n"); }
template<int N>
__device__ __forceinline__ void cp_wait() { asm volatile("cp.async.wait_group %0;\n" :: "n"(N)); }

__device__ __forceinline__ void red4(float* p, float4 v) {
    asm volatile("red.global.add.v4.f32 [%0], {%1,%2,%3,%4};\n"
                 :: "l"(p), "f"(v.x), "f"(v.y), "f"(v.z), "f"(v.w) : "memory");
}

__device__ __forceinline__ float leaky(float v) { return v > 0.f ? v : 0.2f * v; }

// ---------------- GEMM path 1: register-staged with tf32 cvt (raw fp32 input x) ----------
template<bool RELU, bool BIAS, bool ROUND>
__global__ void __launch_bounds__(256) tgemm_k(
    const float* __restrict__ A1,
    const float* __restrict__ B, const float* __restrict__ bias,
    float* __restrict__ C, int M, int K, int Nc)
{
    const int BM = 128, BK = 16;
    __shared__ float As[2][BM][20];
    __shared__ float Bs[2][BK][136];

    int tid = threadIdx.x;
    int lane = tid & 31, wid = tid >> 5;
    int g = lane >> 2, t = lane & 3;
    int wm = wid >> 2, wn = wid & 3;
    int rowBase = blockIdx.y * BM;
    int colBase = blockIdx.x * 128;

    float acc[4][4][4];
#pragma unroll
    for (int i = 0; i < 4; i++)
#pragma unroll
        for (int j = 0; j < 4; j++)
#pragma unroll
            for (int r = 0; r < 4; r++) acc[i][j][r] = 0.f;

    int ar0 = tid >> 2,          ac0 = (tid & 3) * 4;
    int ar1 = (tid + 256) >> 2;
    int br0 = tid >> 5,          bc0 = (tid & 31) * 4;
    int br1 = (tid + 256) >> 5;

    float4 pa0, pa1, pb0, pb1;
    const float4 z4 = make_float4(0.f, 0.f, 0.f, 0.f);

    int ntiles = K / BK;
    int s = 0;
    {
        int r0 = rowBase + ar0, r1 = rowBase + ar1;
        pa0 = (r0 < M) ? *reinterpret_cast<const float4*>(A1 + (size_t)r0 * K + ac0) : z4;
        pa1 = (r1 < M) ? *reinterpret_cast<const float4*>(A1 + (size_t)r1 * K + ac0) : z4;
        pb0 = *reinterpret_cast<const float4*>(B + (size_t)br0 * Nc + colBase + bc0);
        pb1 = *reinterpret_cast<const float4*>(B + (size_t)br1 * Nc + colBase + bc0);
        As[0][ar0][ac0 + 0] = rnd_tf32(pa0.x); As[0][ar0][ac0 + 1] = rnd_tf32(pa0.y);
        As[0][ar0][ac0 + 2] = rnd_tf32(pa0.z); As[0][ar0][ac0 + 3] = rnd_tf32(pa0.w);
        As[0][ar1][ac0 + 0] = rnd_tf32(pa1.x); As[0][ar1][ac0 + 1] = rnd_tf32(pa1.y);
        As[0][ar1][ac0 + 2] = rnd_tf32(pa1.z); As[0][ar1][ac0 + 3] = rnd_tf32(pa1.w);
        Bs[0][br0][bc0 + 0] = rnd_tf32(pb0.x); Bs[0][br0][bc0 + 1] = rnd_tf32(pb0.y);
        Bs[0][br0][bc0 + 2] = rnd_tf32(pb0.z); Bs[0][br0][bc0 + 3] = rnd_tf32(pb0.w);
        Bs[0][br1][bc0 + 0] = rnd_tf32(pb1.x); Bs[0][br1][bc0 + 1] = rnd_tf32(pb1.y);
        Bs[0][br1][bc0 + 2] = rnd_tf32(pb1.z); Bs[0][br1][bc0 + 3] = rnd_tf32(pb1.w);
    }
    __syncthreads();
    for (int kt = 0; kt < ntiles; kt++) {
        bool more = (kt + 1 < ntiles);
        if (more) {
            int kk = (kt + 1) * BK;
            int r0 = rowBase + ar0, r1 = rowBase + ar1;
            pa0 = (r0 < M) ? *reinterpret_cast<const float4*>(A1 + (size_t)r0 * K + kk + ac0) : z4;
            pa1 = (r1 < M) ? *reinterpret_cast<const float4*>(A1 + (size_t)r1 * K + kk + ac0) : z4;
            pb0 = *reinterpret_cast<const float4*>(B + (size_t)(kk + br0) * Nc + colBase + bc0);
            pb1 = *reinterpret_cast<const float4*>(B + (size_t)(kk + br1) * Nc + colBase + bc0);
        }
#pragma unroll
        for (int ks = 0; ks < 2; ks++) {
            int k0 = ks * 8;
            unsigned a[4][4], b[4][2];
#pragma unroll
            for (int mt = 0; mt < 4; mt++) {
                int m0 = wm * 64 + mt * 16;
                a[mt][0] = __float_as_uint(As[s][m0 + g][k0 + t]);
                a[mt][1] = __float_as_uint(As[s][m0 + g + 8][k0 + t]);
                a[mt][2] = __float_as_uint(As[s][m0 + g][k0 + t + 4]);
                a[mt][3] = __float_as_uint(As[s][m0 + g + 8][k0 + t + 4]);
            }
#pragma unroll
            for (int nt = 0; nt < 4; nt++) {
                int n0 = wn * 32 + nt * 8;
                b[nt][0] = __float_as_uint(Bs[s][k0 + t][n0 + g]);
                b[nt][1] = __float_as_uint(Bs[s][k0 + t + 4][n0 + g]);
            }
#pragma unroll
            for (int mt = 0; mt < 4; mt++)
#pragma unroll
                for (int nt = 0; nt < 4; nt++)
                    mma_tf32(acc[mt][nt], a[mt], b[nt]);
        }
        if (more) {
            int so = s ^ 1;
            As[so][ar0][ac0 + 0] = rnd_tf32(pa0.x); As[so][ar0][ac0 + 1] = rnd_tf32(pa0.y);
            As[so][ar0][ac0 + 2] = rnd_tf32(pa0.z); As[so][ar0][ac0 + 3] = rnd_tf32(pa0.w);
            As[so][ar1][ac0 + 0] = rnd_tf32(pa1.x); As[so][ar1][ac0 + 1] = rnd_tf32(pa1.y);
            As[so][ar1][ac0 + 2] = rnd_tf32(pa1.z); As[so][ar1][ac0 + 3] = rnd_tf32(pa1.w);
            Bs[so][br0][bc0 + 0] = rnd_tf32(pb0.x); Bs[so][br0][bc0 + 1] = rnd_tf32(pb0.y);
            Bs[so][br0][bc0 + 2] = rnd_tf32(pb0.z); Bs[so][br0][bc0 + 3] = rnd_tf32(pb0.w);
            Bs[so][br1][bc0 + 0] = rnd_tf32(pb1.x); Bs[so][br1][bc0 + 1] = rnd_tf32(pb1.y);
            Bs[so][br1][bc0 + 2] = rnd_tf32(pb1.z); Bs[so][br1][bc0 + 3] = rnd_tf32(pb1.w);
            __syncthreads();
        }
        s ^= 1;
    }

#pragma unroll
    for (int nt = 0; nt < 4; nt++) {
        int col = colBase + wn * 32 + nt * 8 + 2 * t;
        float2 bb = make_float2(0.f, 0.f);
        if (BIAS) bb = *reinterpret_cast<const float2*>(bias + col);
#pragma unroll
        for (int mt = 0; mt < 4; mt++) {
            int row0 = rowBase + wm * 64 + mt * 16 + g;
            int row1 = row0 + 8;
            float2 v0 = make_float2(acc[mt][nt][0] + bb.x, acc[mt][nt][1] + bb.y);
            float2 v1 = make_float2(acc[mt][nt][2] + bb.x, acc[mt][nt][3] + bb.y);
            if (RELU) {
                v0.x = fmaxf(v0.x, 0.f); v0.y = fmaxf(v0.y, 0.f);
                v1.x = fmaxf(v1.x, 0.f); v1.y = fmaxf(v1.y, 0.f);
            }
            if (ROUND) {
                v0.x = rnd_tf32(v0.x); v0.y = rnd_tf32(v0.y);
                v1.x = rnd_tf32(v1.x); v1.y = rnd_tf32(v1.y);
            }
            if (row0 < M) *reinterpret_cast<float2*>(C + (size_t)row0 * Nc + col) = v0;
            if (row1 < M) *reinterpret_cast<float2*>(C + (size_t)row1 * Nc + col) = v1;
        }
    }
}

// ---------------- GEMM path 2: cp.async + fused attention-coefficient epilogue ----------
__global__ void __launch_bounds__(256) tgemm_att_k(
    const float* __restrict__ A1,
    const float* __restrict__ B,
    float* __restrict__ C, int M, int K, int Nc,
    const float* __restrict__ asrc, const float* __restrict__ adst,
    float* __restrict__ osrc, float* __restrict__ odst)
{
    const int BM = 128, BK = 16;
    __shared__ float As[2][BM][20];
    __shared__ float Bs[2][BK][136];
    __shared__ float attS[128][2];
    __shared__ float attD[128][2];

    int tid = threadIdx.x;
    int lane = tid & 31, wid = tid >> 5;
    int g = lane >> 2, t = lane & 3;
    int wm = wid >> 2, wn = wid & 3;
    int rowBase = blockIdx.y * BM;
    int colBase = blockIdx.x * 128;

    if (tid < 128) {
        attS[tid][0] = 0.f; attS[tid][1] = 0.f;
        attD[tid][0] = 0.f; attD[tid][1] = 0.f;
    }

    float acc[4][4][4];
#pragma unroll
    for (int i = 0; i < 4; i++)
#pragma unroll
        for (int j = 0; j < 4; j++)
#pragma unroll
            for (int r = 0; r < 4; r++) acc[i][j][r] = 0.f;

    int ar0 = tid >> 2, ac0 = (tid & 3) * 4;
    int ar1 = ar0 + 64;
    int br0 = tid >> 5, bc0 = (tid & 31) * 4;
    int br1 = br0 + 8;

    auto loadtile = [&](int kt, int sb) {
        int r0 = rowBase + ar0, r1 = rowBase + ar1;
        cp16(&As[sb][ar0][ac0], A1 + (size_t)r0 * K + kt + ac0, r0 < M);
        cp16(&As[sb][ar1][ac0], A1 + (size_t)r1 * K + kt + ac0, r1 < M);
        cp16(&Bs[sb][br0][bc0], B + (size_t)(kt + br0) * Nc + colBase + bc0, true);
        cp16(&Bs[sb][br1][bc0], B + (size_t)(kt + br1) * Nc + colBase + bc0, true);
        cp_commit();
    };

    int ntiles = K / BK;
    loadtile(0, 0);
    for (int kt = 0; kt < ntiles; kt++) {
        int s = kt & 1;
        if (kt + 1 < ntiles) loadtile((kt + 1) * BK, s ^ 1);
        else cp_commit();
        cp_wait<1>();
        __syncthreads();
#pragma unroll
        for (int ks = 0; ks < 2; ks++) {
            int k0 = ks * 8;
            unsigned a[4][4], b[4][2];
#pragma unroll
            for (int mt = 0; mt < 4; mt++) {
                int m0 = wm * 64 + mt * 16;
                a[mt][0] = __float_as_uint(As[s][m0 + g][k0 + t]);
                a[mt][1] = __float_as_uint(As[s][m0 + g + 8][k0 + t]);
                a[mt][2] = __float_as_uint(As[s][m0 + g][k0 + t + 4]);
                a[mt][3] = __float_as_uint(As[s][m0 + g + 8][k0 + t + 4]);
            }
#pragma unroll
            for (int nt = 0; nt < 4; nt++) {
                int n0 = wn * 32 + nt * 8;
                b[nt][0] = __float_as_uint(Bs[s][k0 + t][n0 + g]);
                b[nt][1] = __float_as_uint(Bs[s][k0 + t + 4][n0 + g]);
            }
#pragma unroll
            for (int mt = 0; mt < 4; mt++)
#pragma unroll
                for (int nt = 0; nt < 4; nt++)
                    mma_tf32(acc[mt][nt], a[mt], b[nt]);
        }
        __syncthreads();
    }

    float as_c[4][2], ad_c[4][2];
#pragma unroll
    for (int nt = 0; nt < 4; nt++) {
        int colG = colBase + wn * 32 + nt * 8 + 2 * t;
        float2 a2 = *reinterpret_cast<const float2*>(asrc + colG);
        float2 d2 = *reinterpret_cast<const float2*>(adst + colG);
        as_c[nt][0] = a2.x; as_c[nt][1] = a2.y;
        ad_c[nt][0] = d2.x; ad_c[nt][1] = d2.y;
    }
    int hl = wn >> 1;

#pragma unroll
    for (int mt = 0; mt < 4; mt++) {
        float s0 = 0.f, d0 = 0.f, s1 = 0.f, d1 = 0.f;
#pragma unroll
        for (int nt = 0; nt < 4; nt++) {
            s0 += acc[mt][nt][0] * as_c[nt][0] + acc[mt][nt][1] * as_c[nt][1];
            d0 += acc[mt][nt][0] * ad_c[nt][0] + acc[mt][nt][1] * ad_c[nt][1];
            s1 += acc[mt][nt][2] * as_c[nt][0] + acc[mt][nt][3] * as_c[nt][1];
            d1 += acc[mt][nt][2] * ad_c[nt][0] + acc[mt][nt][3] * ad_c[nt][1];
        }
#pragma unroll
        for (int off = 1; off <= 2; off <<= 1) {
            s0 += __shfl_xor_sync(0xffffffffu, s0, off);
            d0 += __shfl_xor_sync(0xffffffffu, d0, off);
            s1 += __shfl_xor_sync(0xffffffffu, s1, off);
            d1 += __shfl_xor_sync(0xffffffffu, d1, off);
        }
        if (t == 0) {
            int lr = wm * 64 + mt * 16 + g;
            atomicAdd(&attS[lr][hl], s0);
            atomicAdd(&attD[lr][hl], d0);
            atomicAdd(&attS[lr + 8][hl], s1);
            atomicAdd(&attD[lr + 8][hl], d1);
        }
#pragma unroll
        for (int nt = 0; nt < 4; nt++) {
            int col = colBase + wn * 32 + nt * 8 + 2 * t;
            int row0 = rowBase + wm * 64 + mt * 16 + g;
            int row1 = row0 + 8;
            if (row0 < M) *reinterpret_cast<float2*>(C + (size_t)row0 * Nc + col)
                = make_float2(acc[mt][nt][0], acc[mt][nt][1]);
            if (row1 < M) *reinterpret_cast<float2*>(C + (size_t)row1 * Nc + col)
                = make_float2(acc[mt][nt][2], acc[mt][nt][3]);
        }
    }
    __syncthreads();
    if (tid < 256) {
        int lr = tid >> 1, h = tid & 1;
        int grow = rowBase + lr;
        if (grow < M) {
            osrc[(size_t)grow * 4 + blockIdx.x * 2 + h] = attS[lr][h];
            odst[(size_t)grow * 4 + blockIdx.x * 2 + h] = attD[lr][h];
        }
    }
}

// ---------------- final GEMM: concat(A1,A2)@Wf + bf, fused LN(128) + L2 normalize --------
__global__ void __launch_bounds__(256) tgemm_final_k(
    const float* __restrict__ A1, const float* __restrict__ A2, int K1,
    const float* __restrict__ B, const float* __restrict__ bias,
    const float* __restrict__ gw, const float* __restrict__ bw,
    float* __restrict__ C, int M, int K)
{
    const int BM = 128, BK = 16, Nc = 128;
    __shared__ float As[2][BM][20];
    __shared__ float Bs[2][BK][136];
    __shared__ float redS[128], redQ[128], redN[128];

    int tid = threadIdx.x;
    int lane = tid & 31, wid = tid >> 5;
    int g = lane >> 2, t = lane & 3;
    int wm = wid >> 2, wn = wid & 3;
    int rowBase = blockIdx.x * BM;

    if (tid < 128) { redS[tid] = 0.f; redQ[tid] = 0.f; redN[tid] = 0.f; }

    float acc[4][4][4];
#pragma unroll
    for (int i = 0; i < 4; i++)
#pragma unroll
        for (int j = 0; j < 4; j++)
#pragma unroll
            for (int r = 0; r < 4; r++) acc[i][j][r] = 0.f;

    int ar0 = tid >> 2, ac0 = (tid & 3) * 4;
    int ar1 = ar0 + 64;
    int br0 = tid >> 5, bc0 = (tid & 31) * 4;
    int br1 = br0 + 8;

    auto loadtile = [&](int kt, int sb) {
        const float* Ap; int kk, stride;
        if (kt < K1) { Ap = A1; kk = kt;      stride = K1;     }
        else         { Ap = A2; kk = kt - K1; stride = K - K1; }
        int r0 = rowBase + ar0, r1 = rowBase + ar1;
        cp16(&As[sb][ar0][ac0], Ap + (size_t)r0 * stride + kk + ac0, r0 < M);
        cp16(&As[sb][ar1][ac0], Ap + (size_t)r1 * stride + kk + ac0, r1 < M);
        cp16(&Bs[sb][br0][bc0], B + (size_t)(kt + br0) * Nc + bc0, true);
        cp16(&Bs[sb][br1][bc0], B + (size_t)(kt + br1) * Nc + bc0, true);
        cp_commit();
    };

    int ntiles = K / BK;
    loadtile(0, 0);
    for (int kt = 0; kt < ntiles; kt++) {
        int s = kt & 1;
        if (kt + 1 < ntiles) loadtile((kt + 1) * BK, s ^ 1);
        else cp_commit();
        cp_wait<1>();
        __syncthreads();
#pragma unroll
        for (int ks = 0; ks < 2; ks++) {
            int k0 = ks * 8;
            unsigned a[4][4], b[4][2];
#pragma unroll
            for (int mt = 0; mt < 4; mt++) {
                int m0 = wm * 64 + mt * 16;
                a[mt][0] = __float_as_uint(As[s][m0 + g][k0 + t]);
                a[mt][1] = __float_as_uint(As[s][m0 + g + 8][k0 + t]);
                a[mt][2] = __float_as_uint(As[s][m0 + g][k0 + t + 4]);
                a[mt][3] = __float_as_uint(As[s][m0 + g + 8][k0 + t + 4]);
            }
#pragma unroll
            for (int nt = 0; nt < 4; nt++) {
                int n0 = wn * 32 + nt * 8;
                b[nt][0] = __float_as_uint(Bs[s][k0 + t][n0 + g]);
                b[nt][1] = __float_as_uint(Bs[s][k0 + t + 4][n0 + g]);
            }
#pragma unroll
            for (int mt = 0; mt < 4; mt++)
#pragma unroll
                for (int nt = 0; nt < 4; nt++)
                    mma_tf32(acc[mt][nt], a[mt], b[nt]);
        }
        __syncthreads();
    }

#pragma unroll
    for (int nt = 0; nt < 4; nt++) {
        int col = wn * 32 + nt * 8 + 2 * t;
        float2 bb = *reinterpret_cast<const float2*>(bias + col);
#pragma unroll
        for (int mt = 0; mt < 4; mt++) {
            acc[mt][nt][0] += bb.x; acc[mt][nt][1] += bb.y;
            acc[mt][nt][2] += bb.x; acc[mt][nt][3] += bb.y;
        }
    }
#pragma unroll
    for (int mt = 0; mt < 4; mt++) {
        float s0 = 0.f, q0 = 0.f, s1 = 0.f, q1 = 0.f;
#pragma unroll
        for (int nt = 0; nt < 4; nt++) {
            s0 += acc[mt][nt][0] + acc[mt][nt][1];
            q0 += acc[mt][nt][0] * acc[mt][nt][0] + acc[mt][nt][1] * acc[mt][nt][1];
            s1 += acc[mt][nt][2] + acc[mt][nt][3];
            q1 += acc[mt][nt][2] * acc[mt][nt][2] + acc[mt][nt][3] * acc[mt][nt][3];
        }
#pragma unroll
        for (int off = 1; off <= 2; off <<= 1) {
            s0 += __shfl_xor_sync(0xffffffffu, s0, off);
            q0 += __shfl_xor_sync(0xffffffffu, q0, off);
            s1 += __shfl_xor_sync(0xffffffffu, s1, off);
            q1 += __shfl_xor_sync(0xffffffffu, q1, off);
        }
        if (t == 0) {
            int lr = wm * 64 + mt * 16 + g;
            atomicAdd(&redS[lr], s0); atomicAdd(&redQ[lr], q0);
            atomicAdd(&redS[lr + 8], s1); atomicAdd(&redQ[lr + 8], q1);
        }
    }
    __syncthreads();
#pragma unroll
    for (int mt = 0; mt < 4; mt++) {
        int lr0 = wm * 64 + mt * 16 + g, lr1 = lr0 + 8;
        float m0 = redS[lr0] * (1.f / 128.f), m1 = redS[lr1] * (1.f / 128.f);
        float var0 = redQ[lr0] * (1.f / 128.f) - m0 * m0;
        float var1 = redQ[lr1] * (1.f / 128.f) - m1 * m1;
        float r0 = rsqrtf(var0 + 1e-5f), r1 = rsqrtf(var1 + 1e-5f);
        float n0 = 0.f, n1 = 0.f;
#pragma unroll
        for (int nt = 0; nt < 4; nt++) {
            int col = wn * 32 + nt * 8 + 2 * t;
            float2 gg = *reinterpret_cast<const float2*>(gw + col);
            float2 b2 = *reinterpret_cast<const float2*>(bw + col);
            float y00 = (acc[mt][nt][0] - m0) * r0 * gg.x + b2.x;
            float y01 = (acc[mt][nt][1] - m0) * r0 * gg.y + b2.y;
            float y10 = (acc[mt][nt][2] - m1) * r1 * gg.x + b2.x;
            float y11 = (acc[mt][nt][3] - m1) * r1 * gg.y + b2.y;
            acc[mt][nt][0] = y00; acc[mt][nt][1] = y01;
            acc[mt][nt][2] = y10; acc[mt][nt][3] = y11;
            n0 += y00 * y00 + y01 * y01;
            n1 += y10 * y10 + y11 * y11;
        }
#pragma unroll
        for (int off = 1; off <= 2; off <<= 1) {
            n0 += __shfl_xor_sync(0xffffffffu, n0, off);
            n1 += __shfl_xor_sync(0xffffffffu, n1, off);
        }
        if (t == 0) { atomicAdd(&redN[lr0], n0); atomicAdd(&redN[lr1], n1); }
    }
    __syncthreads();
#pragma unroll
    for (int mt = 0; mt < 4; mt++) {
        int lr0 = wm * 64 + mt * 16 + g, lr1 = lr0 + 8;
        float inv0 = 1.f / fmaxf(sqrtf(redN[lr0]), 1e-12f);
        float inv1 = 1.f / fmaxf(sqrtf(redN[lr1]), 1e-12f);
        int row0 = rowBase + lr0, row1 = rowBase + lr1;
#pragma unroll
        for (int nt = 0; nt < 4; nt++) {
            int col = wn * 32 + nt * 8 + 2 * t;
            if (row0 < M) *reinterpret_cast<float2*>(C + (size_t)row0 * 128 + col)
                = make_float2(acc[mt][nt][0] * inv0, acc[mt][nt][1] * inv0);
            if (row1 < M) *reinterpret_cast<float2*>(C + (size_t)row1 * 128 + col)
                = make_float2(acc[mt][nt][2] * inv1, acc[mt][nt][3] * inv1);
        }
    }
}

// ---------------- round weights once into g_wt ----------------
__global__ void round_w_k(const float* __restrict__ w0, const float* __restrict__ w1,
                          const float* __restrict__ w2, float* __restrict__ out)
{
    int i = blockIdx.x * 256 + threadIdx.x;
    out[i]          = rnd_tf32(w0[i]);
    out[65536 + i]  = rnd_tf32(w1[i]);
    out[131072 + i] = rnd_tf32(w2[i]);
}

// ---------------- self-loop max init: m[n] = fmap(leaky(as[n]+ad[n])) ----------------
__global__ void self_max_k(const float* __restrict__ asrc, const float* __restrict__ adst,
                           unsigned* __restrict__ m)
{
    int n = blockIdx.x * blockDim.x + threadIdx.x;
    if (n >= NN) return;
    float4 as = *reinterpret_cast<const float4*>(asrc + (size_t)n * 4);
    float4 ad = *reinterpret_cast<const float4*>(adst + (size_t)n * 4);
    uint4 o;
    o.x = fmap(leaky(as.x + ad.x));
    o.y = fmap(leaky(as.y + ad.y));
    o.z = fmap(leaky(as.z + ad.z));
    o.w = fmap(leaky(as.w + ad.w));
    *reinterpret_cast<uint4*>(m + (size_t)n * 4) = o;
}

// ---------------- edge pass 1 (real edges only): logits + segment max --------------------
__global__ void edge_logits_k(const int* __restrict__ ei,
                              const float* __restrict__ asrc, const float* __restrict__ adst,
                              float* __restrict__ ebuf, unsigned* __restrict__ m)
{
    int i = blockIdx.x * blockDim.x + threadIdx.x;
    if (i >= EE) return;
    int s = ei[i], d = ei[EE + i];
    float4 as = *reinterpret_cast<const float4*>(asrc + (size_t)s * 4);
    float4 ad = *reinterpret_cast<const float4*>(adst + (size_t)d * 4);
    float e[4] = {as.x + ad.x, as.y + ad.y, as.z + ad.z, as.w + ad.w};
    float4 o;
    float* op = &o.x;
#pragma unroll
    for (int h = 0; h < 4; h++) {
        float v = leaky(e[h]);
        op[h] = v;
        atomicMax(m + d * 4 + h, fmap(v));
    }
    *reinterpret_cast<float4*>(ebuf + (size_t)i * 4) = o;
}

// ---------------- den init (after max pass): den[n] = exp(e_self - m[n]) ----------------
__global__ void den_init_k(const float* __restrict__ asrc, const float* __restrict__ adst,
                           const unsigned* __restrict__ m, float* __restrict__ den)
{
    int n = blockIdx.x * blockDim.x + threadIdx.x;
    if (n >= NN) return;
    float4 as = *reinterpret_cast<const float4*>(asrc + (size_t)n * 4);
    float4 ad = *reinterpret_cast<const float4*>(adst + (size_t)n * 4);
    uint4 mu = *reinterpret_cast<const uint4*>(m + (size_t)n * 4);
    float4 o;
    o.x = expf(leaky(as.x + ad.x) - funmap(mu.x));
    o.y = expf(leaky(as.y + ad.y) - funmap(mu.y));
    o.z = expf(leaky(as.z + ad.z) - funmap(mu.z));
    o.w = expf(leaky(as.w + ad.w) - funmap(mu.w));
    *reinterpret_cast<float4*>(den + (size_t)n * 4) = o;
}

// ---------------- edge pass 2 (real edges only): exp + segment sum ----------------------
__global__ void edge_exp_k(const int* __restrict__ ei,
                           const unsigned* __restrict__ m, float* __restrict__ ebuf,
                           float* __restrict__ den)
{
    int i = blockIdx.x * blockDim.x + threadIdx.x;
    if (i >= EE) return;
    int d = ei[EE + i];
    float4 e = *reinterpret_cast<const float4*>(ebuf + (size_t)i * 4);
    float4 o;
    o.x = expf(e.x - funmap(m[d * 4 + 0]));
    o.y = expf(e.y - funmap(m[d * 4 + 1]));
    o.z = expf(e.z - funmap(m[d * 4 + 2]));
    o.w = expf(e.w - funmap(m[d * 4 + 3]));
    *reinterpret_cast<float4*>(ebuf + (size_t)i * 4) = o;
    red4(den + (size_t)d * 4, o);
}

// ---------------- edge pass 3 (real edges only): weighted scatter -----------------------
__global__ void __launch_bounds__(256) edge_scatter_k(const int* __restrict__ ei,
        const float* __restrict__ ebuf, const float* __restrict__ den,
        const float* __restrict__ hw, float* __restrict__ acc)
{
    int idx = blockIdx.x * 4 + (threadIdx.x >> 6);
    int lane = threadIdx.x & 63;
    if (idx >= EE) return;
    int s = ei[idx], d = ei[EE + idx];
    float4 ex = *reinterpret_cast<const float4*>(ebuf + (size_t)idx * 4);
    float4 dn = *reinterpret_cast<const float4*>(den + (size_t)d * 4);
    int head = lane >> 4;
    float exs = (head == 0) ? ex.x : (head == 1) ? ex.y : (head == 2) ? ex.z : ex.w;
    float dns = (head == 0) ? dn.x : (head == 1) ? dn.y : (head == 2) ? dn.z : dn.w;
    float al = exs / dns;
    float4 hv = reinterpret_cast<const float4*>(hw + (size_t)s * 256)[lane];
    float4 v = make_float4(hv.x * al, hv.y * al, hv.z * al, hv.w * al);
    red4(acc + (size_t)d * 256 + lane * 4, v);
}

// ---------------- LN(256) of (acc + alpha_self*hw + bias), ReLU, tf32-rounded out -------
__global__ void ln_relu_k(const float* __restrict__ in, const float* __restrict__ hw,
                          const float* __restrict__ asrc, const float* __restrict__ adst,
                          const unsigned* __restrict__ m, const float* __restrict__ den,
                          const float* __restrict__ bias,
                          const float* __restrict__ g, const float* __restrict__ b,
                          float* __restrict__ out)
{
    int row = (blockIdx.x * blockDim.x + threadIdx.x) >> 5;
    int lane = threadIdx.x & 31;
    if (row >= NN) return;
    int h = lane >> 3;   // this thread's 8 channels live in head h
    // alpha_self for this head
    float es = leaky(asrc[row * 4 + h] + adst[row * 4 + h]);
    float al = expf(es - funmap(m[row * 4 + h])) / den[row * 4 + h];

    const float4* ip = reinterpret_cast<const float4*>(in + (size_t)row * 256);
    const float4* hp = reinterpret_cast<const float4*>(hw + (size_t)row * 256);
    const float4* bsp = reinterpret_cast<const float4*>(bias);
    float4 v0 = ip[lane * 2], v1 = ip[lane * 2 + 1];
    float4 h0 = hp[lane * 2], h1 = hp[lane * 2 + 1];
    float4 a0 = bsp[lane * 2], a1 = bsp[lane * 2 + 1];
    v0.x += al * h0.x + a0.x; v0.y += al * h0.y + a0.y;
    v0.z += al * h0.z + a0.z; v0.w += al * h0.w + a0.w;
    v1.x += al * h1.x + a1.x; v1.y += al * h1.y + a1.y;
    v1.z += al * h1.z + a1.z; v1.w += al * h1.w + a1.w;
    float sum = v0.x + v0.y + v0.z + v0.w + v1.x + v1.y + v1.z + v1.w;
#pragma unroll
    for (int off = 16; off; off >>= 1) sum += __shfl_xor_sync(0xffffffffu, sum, off);
    float mean = sum * (1.f / 256.f);
    float c0x = v0.x - mean, c0y = v0.y - mean, c0z = v0.z - mean, c0w = v0.w - mean;
    float c1x = v1.x - mean, c1y = v1.y - mean, c1z = v1.z - mean, c1w = v1.w - mean;
    float sq = c0x * c0x + c0y * c0y + c0z * c0z + c0w * c0w
             + c1x * c1x + c1y * c1y + c1z * c1z + c1w * c1w;
#pragma unroll
    for (int off = 16; off; off >>= 1) sq += __shfl_xor_sync(0xffffffffu, sq, off);
    float r = rsqrtf(sq * (1.f / 256.f) + 1e-5f);
    const float4* gp = reinterpret_cast<const float4*>(g);
    const float4* bp = reinterpret_cast<const float4*>(b);
    float4 g0 = gp[lane * 2], g1 = gp[lane * 2 + 1];
    float4 b0 = bp[lane * 2], b1 = bp[lane * 2 + 1];
    float4 o0, o1;
    o0.x = rnd_tf32(fmaxf(c0x * r * g0.x + b0.x, 0.f));
    o0.y = rnd_tf32(fmaxf(c0y * r * g0.y + b0.y, 0.f));
    o0.z = rnd_tf32(fmaxf(c0z * r * g0.z + b0.z, 0.f));
    o0.w = rnd_tf32(fmaxf(c0w * r * g0.w + b0.w, 0.f));
    o1.x = rnd_tf32(fmaxf(c1x * r * g1.x + b1.x, 0.f));
    o1.y = rnd_tf32(fmaxf(c1y * r * g1.y + b1.y, 0.f));
    o1.z = rnd_tf32(fmaxf(c1z * r * g1.z + b1.z, 0.f));
    o1.w = rnd_tf32(fmaxf(c1w * r * g1.w + b1.w, 0.f));
    float4* op = reinterpret_cast<float4*>(out + (size_t)row * 256);
    op[lane * 2] = o0;
    op[lane * 2 + 1] = o1;
}

// ---------------- launcher ----------------
extern "C" void kernel_launch(void* const* d_in, const int* in_sizes, int n_in,
                              void* d_out, int out_size)
{
    const float* x       = (const float*)d_in[0];
    const int*   ei_bu   = (const int*)d_in[1];
    const int*   ei_td   = (const int*)d_in[2];
    const float* Wp      = (const float*)d_in[3];
    const float* bp      = (const float*)d_in[4];
    const float* W_bu    = (const float*)d_in[5];
    const float* asrc_bu = (const float*)d_in[6];
    const float* adst_bu = (const float*)d_in[7];
    const float* bias_bu = (const float*)d_in[8];
    const float* W_td    = (const float*)d_in[9];
    const float* asrc_td = (const float*)d_in[10];
    const float* adst_td = (const float*)d_in[11];
    const float* bias_td = (const float*)d_in[12];
    const float* Wf      = (const float*)d_in[13];
    const float* bf      = (const float*)d_in[14];
    const float* g_bu    = (const float*)d_in[15];
    const float* b_bu    = (const float*)d_in[16];
    const float* g_td    = (const float*)d_in[17];
    const float* b_td    = (const float*)d_in[18];
    const float* g_out   = (const float*)d_in[19];
    const float* b_out   = (const float*)d_in[20];
    float* out = (float*)d_out;

    float *ph, *phw, *pacc, *pxbu, *pxtd, *pas, *pad, *pden, *pe, *pwt;
    unsigned* pm;
    cudaGetSymbolAddress((void**)&ph,   g_h);
    cudaGetSymbolAddress((void**)&phw,  g_hw);
    cudaGetSymbolAddress((void**)&pacc, g_acc);
    cudaGetSymbolAddress((void**)&pxbu, g_xbu);
    cudaGetSymbolAddress((void**)&pxtd, g_xtd);
    cudaGetSymbolAddress((void**)&pas,  g_as);
    cudaGetSymbolAddress((void**)&pad,  g_ad);
    cudaGetSymbolAddress((void**)&pm,   g_m);
    cudaGetSymbolAddress((void**)&pden, g_den);
    cudaGetSymbolAddress((void**)&pe,   g_e);
    cudaGetSymbolAddress((void**)&pwt,  g_wt);

    const int mblocks = (NN + 127) / 128;               // 1563
    const dim3 gemmGrid256(2, mblocks);
    const int warpRowBlocks = (NN * 32) / 256;          // 25000
    const int nodeBlocks    = (NN + 255) / 256;         // 782
    const int edgeBlocks    = (EE + 255) / 256;         // 782
    const int scatBlocks    = (EE + 3) / 4;             // 50000

    // pre-round weights (W_bu | W_td | Wf) once
    round_w_k<<<256, 256>>>(W_bu, W_td, Wf, pwt);

    // h = round_tf32(relu(x @ Wp + bp))
    tgemm_k<true, true, true><<<gemmGrid256, 256>>>(x, Wp, bp, ph, NN, 256, 256);

    const int*   eis[2]   = {ei_bu, ei_td};
    const float* asr[2]   = {asrc_bu, asrc_td};
    const float* ads[2]   = {adst_bu, adst_td};
    const float* bis[2]   = {bias_bu, bias_td};
    const float* gln[2]   = {g_bu, g_td};
    const float* bln[2]   = {b_bu, b_td};
    float*       xdir[2]  = {pxbu, pxtd};

    for (int dir = 0; dir < 2; dir++) {
        tgemm_att_k<<<gemmGrid256, 256>>>(
            ph, pwt + dir * 65536, phw, NN, 256, 256,
            asr[dir], ads[dir], pas, pad);
        cudaMemsetAsync(pacc, 0, (size_t)NN * 256 * sizeof(float));
        self_max_k<<<nodeBlocks, 256>>>(pas, pad, pm);
        edge_logits_k<<<edgeBlocks, 256>>>(eis[dir], pas, pad, pe, pm);
        den_init_k<<<nodeBlocks, 256>>>(pas, pad, pm, pden);
        edge_exp_k<<<edgeBlocks, 256>>>(eis[dir], pm, pe, pden);
        edge_scatter_k<<<scatBlocks, 256>>>(eis[dir], pe, pden, phw, pacc);
        ln_relu_k<<<warpRowBlocks, 256>>>(pacc, phw, pas, pad, pm, pden,
                                          bis[dir], gln[dir], bln[dir], xdir[dir]);
    }

    // out = L2norm(LN(concat(x_bu, x_td) @ Wf + bf)) fused
    tgemm_final_k<<<mblocks, 256>>>(pxbu, pxtd, 256, pwt + 131072, bf,
                                    g_out, b_out, out, NN, 512);
}

// round 9
// speedup vs baseline: 2.9577x; 1.0320x over previous
#include <cuda_runtime.h>
#include <cstdint>

#define NN 200000
#define EE 200000

// ---------------- scratch (static device globals; no runtime allocation) ----------------
__device__ float    g_h   [(size_t)NN * 256];
__device__ float    g_hw0 [(size_t)NN * 256];
__device__ float    g_hw1 [(size_t)NN * 256];
__device__ float    g_acc0[(size_t)NN * 256];
__device__ float    g_acc1[(size_t)NN * 256];
__device__ float    g_xbu [(size_t)NN * 256];
__device__ float    g_xtd [(size_t)NN * 256];
__device__ float    g_as0 [NN * 4];
__device__ float    g_as1 [NN * 4];
__device__ float    g_ad0 [NN * 4];
__device__ float    g_ad1 [NN * 4];
__device__ unsigned g_m0  [NN * 4];
__device__ unsigned g_m1  [NN * 4];
__device__ float    g_den0[NN * 4];
__device__ float    g_den1[NN * 4];
__device__ float    g_e0  [(size_t)EE * 4];
__device__ float    g_e1  [(size_t)EE * 4];
__device__ float    g_wt  [3 * 65536];     // pre-rounded W_bu | W_td | Wf

// ---------------- helpers ----------------
__device__ __forceinline__ unsigned fmap(float f) {
    unsigned u = __float_as_uint(f);
    return (u & 0x80000000u) ? ~u : (u | 0x80000000u);
}
__device__ __forceinline__ float funmap(unsigned u) {
    return (u & 0x80000000u) ? __uint_as_float(u ^ 0x80000000u) : __uint_as_float(~u);
}
__device__ __forceinline__ unsigned f2tf32(float f) {
    unsigned r;
    asm("cvt.rna.tf32.f32 %0, %1;" : "=r"(r) : "f"(f));
    return r;
}
__device__ __forceinline__ float rnd_tf32(float f) { return __uint_as_float(f2tf32(f)); }

__device__ __forceinline__ void mma_tf32(float c[4], const unsigned a[4], const unsigned b[2]) {
    asm volatile(
        "mma.sync.aligned.m16n8k8.row.col.f32.tf32.tf32.f32 "
        "{%0,%1,%2,%3}, {%4,%5,%6,%7}, {%8,%9}, {%0,%1,%2,%3};\n"
        : "+f"(c[0]), "+f"(c[1]), "+f"(c[2]), "+f"(c[3])
        : "r"(a[0]), "r"(a[1]), "r"(a[2]), "r"(a[3]), "r"(b[0]), "r"(b[1]));
}

__device__ __forceinline__ void cp16(void* smem_dst, const void* gsrc, bool pred) {
    uint32_t s = (uint32_t)__cvta_generic_to_shared(smem_dst);
    int sz = pred ? 16 : 0;
    asm volatile("cp.async.cg.shared.global [%0], [%1], 16, %2;\n"
                 :: "r"(s), "l"(gsrc), "r"(sz));
}
__device__ __forceinline__ void cp_commit() { asm volatile("cp.async.commit_group;\n"); }
template<int N>
__device__ __forceinline__ void cp_wait() { asm volatile("cp.async.wait_group %0;\n" :: "n"(N)); }

__device__ __forceinline__ void red4(float* p, float4 v) {
    asm volatile("red.global.add.v4.f32 [%0], {%1,%2,%3,%4};\n"
                 :: "l"(p), "f"(v.x), "f"(v.y), "f"(v.z), "f"(v.w) : "memory");
}

__device__ __forceinline__ float leaky(float v) { return v > 0.f ? v : 0.2f * v; }

// ---------------- GEMM path 1: register-staged with tf32 cvt (raw fp32 input x) ----------
template<bool RELU, bool BIAS, bool ROUND>
__global__ void __launch_bounds__(256) tgemm_k(
    const float* __restrict__ A1,
    const float* __restrict__ B, const float* __restrict__ bias,
    float* __restrict__ C, int M, int K, int Nc)
{
    const int BM = 128, BK = 16;
    __shared__ float As[2][BM][20];
    __shared__ float Bs[2][BK][136];

    int tid = threadIdx.x;
    int lane = tid & 31, wid = tid >> 5;
    int g = lane >> 2, t = lane & 3;
    int wm = wid >> 2, wn = wid & 3;
    int rowBase = blockIdx.y * BM;
    int colBase = blockIdx.x * 128;

    float acc[4][4][4];
#pragma unroll
    for (int i = 0; i < 4; i++)
#pragma unroll
        for (int j = 0; j < 4; j++)
#pragma unroll
            for (int r = 0; r < 4; r++) acc[i][j][r] = 0.f;

    int ar0 = tid >> 2,          ac0 = (tid & 3) * 4;
    int ar1 = (tid + 256) >> 2;
    int br0 = tid >> 5,          bc0 = (tid & 31) * 4;
    int br1 = (tid + 256) >> 5;

    float4 pa0, pa1, pb0, pb1;
    const float4 z4 = make_float4(0.f, 0.f, 0.f, 0.f);

    int ntiles = K / BK;
    int s = 0;
    {
        int r0 = rowBase + ar0, r1 = rowBase + ar1;
        pa0 = (r0 < M) ? *reinterpret_cast<const float4*>(A1 + (size_t)r0 * K + ac0) : z4;
        pa1 = (r1 < M) ? *reinterpret_cast<const float4*>(A1 + (size_t)r1 * K + ac0) : z4;
        pb0 = *reinterpret_cast<const float4*>(B + (size_t)br0 * Nc + colBase + bc0);
        pb1 = *reinterpret_cast<const float4*>(B + (size_t)br1 * Nc + colBase + bc0);
        As[0][ar0][ac0 + 0] = rnd_tf32(pa0.x); As[0][ar0][ac0 + 1] = rnd_tf32(pa0.y);
        As[0][ar0][ac0 + 2] = rnd_tf32(pa0.z); As[0][ar0][ac0 + 3] = rnd_tf32(pa0.w);
        As[0][ar1][ac0 + 0] = rnd_tf32(pa1.x); As[0][ar1][ac0 + 1] = rnd_tf32(pa1.y);
        As[0][ar1][ac0 + 2] = rnd_tf32(pa1.z); As[0][ar1][ac0 + 3] = rnd_tf32(pa1.w);
        Bs[0][br0][bc0 + 0] = rnd_tf32(pb0.x); Bs[0][br0][bc0 + 1] = rnd_tf32(pb0.y);
        Bs[0][br0][bc0 + 2] = rnd_tf32(pb0.z); Bs[0][br0][bc0 + 3] = rnd_tf32(pb0.w);
        Bs[0][br1][bc0 + 0] = rnd_tf32(pb1.x); Bs[0][br1][bc0 + 1] = rnd_tf32(pb1.y);
        Bs[0][br1][bc0 + 2] = rnd_tf32(pb1.z); Bs[0][br1][bc0 + 3] = rnd_tf32(pb1.w);
    }
    __syncthreads();
    for (int kt = 0; kt < ntiles; kt++) {
        bool more = (kt + 1 < ntiles);
        if (more) {
            int kk = (kt + 1) * BK;
            int r0 = rowBase + ar0, r1 = rowBase + ar1;
            pa0 = (r0 < M) ? *reinterpret_cast<const float4*>(A1 + (size_t)r0 * K + kk + ac0) : z4;
            pa1 = (r1 < M) ? *reinterpret_cast<const float4*>(A1 + (size_t)r1 * K + kk + ac0) : z4;
            pb0 = *reinterpret_cast<const float4*>(B + (size_t)(kk + br0) * Nc + colBase + bc0);
            pb1 = *reinterpret_cast<const float4*>(B + (size_t)(kk + br1) * Nc + colBase + bc0);
        }
#pragma unroll
        for (int ks = 0; ks < 2; ks++) {
            int k0 = ks * 8;
            unsigned a[4][4], b[4][2];
#pragma unroll
            for (int mt = 0; mt < 4; mt++) {
                int m0 = wm * 64 + mt * 16;
                a[mt][0] = __float_as_uint(As[s][m0 + g][k0 + t]);
                a[mt][1] = __float_as_uint(As[s][m0 + g + 8][k0 + t]);
                a[mt][2] = __float_as_uint(As[s][m0 + g][k0 + t + 4]);
                a[mt][3] = __float_as_uint(As[s][m0 + g + 8][k0 + t + 4]);
            }
#pragma unroll
            for (int nt = 0; nt < 4; nt++) {
                int n0 = wn * 32 + nt * 8;
                b[nt][0] = __float_as_uint(Bs[s][k0 + t][n0 + g]);
                b[nt][1] = __float_as_uint(Bs[s][k0 + t + 4][n0 + g]);
            }
#pragma unroll
            for (int mt = 0; mt < 4; mt++)
#pragma unroll
                for (int nt = 0; nt < 4; nt++)
                    mma_tf32(acc[mt][nt], a[mt], b[nt]);
        }
        if (more) {
            int so = s ^ 1;
            As[so][ar0][ac0 + 0] = rnd_tf32(pa0.x); As[so][ar0][ac0 + 1] = rnd_tf32(pa0.y);
            As[so][ar0][ac0 + 2] = rnd_tf32(pa0.z); As[so][ar0][ac0 + 3] = rnd_tf32(pa0.w);
            As[so][ar1][ac0 + 0] = rnd_tf32(pa1.x); As[so][ar1][ac0 + 1] = rnd_tf32(pa1.y);
            As[so][ar1][ac0 + 2] = rnd_tf32(pa1.z); As[so][ar1][ac0 + 3] = rnd_tf32(pa1.w);
            Bs[so][br0][bc0 + 0] = rnd_tf32(pb0.x); Bs[so][br0][bc0 + 1] = rnd_tf32(pb0.y);
            Bs[so][br0][bc0 + 2] = rnd_tf32(pb0.z); Bs[so][br0][bc0 + 3] = rnd_tf32(pb0.w);
            Bs[so][br1][bc0 + 0] = rnd_tf32(pb1.x); Bs[so][br1][bc0 + 1] = rnd_tf32(pb1.y);
            Bs[so][br1][bc0 + 2] = rnd_tf32(pb1.z); Bs[so][br1][bc0 + 3] = rnd_tf32(pb1.w);
            __syncthreads();
        }
        s ^= 1;
    }

#pragma unroll
    for (int nt = 0; nt < 4; nt++) {
        int col = colBase + wn * 32 + nt * 8 + 2 * t;
        float2 bb = make_float2(0.f, 0.f);
        if (BIAS) bb = *reinterpret_cast<const float2*>(bias + col);
#pragma unroll
        for (int mt = 0; mt < 4; mt++) {
            int row0 = rowBase + wm * 64 + mt * 16 + g;
            int row1 = row0 + 8;
            float2 v0 = make_float2(acc[mt][nt][0] + bb.x, acc[mt][nt][1] + bb.y);
            float2 v1 = make_float2(acc[mt][nt][2] + bb.x, acc[mt][nt][3] + bb.y);
            if (RELU) {
                v0.x = fmaxf(v0.x, 0.f); v0.y = fmaxf(v0.y, 0.f);
                v1.x = fmaxf(v1.x, 0.f); v1.y = fmaxf(v1.y, 0.f);
            }
            if (ROUND) {
                v0.x = rnd_tf32(v0.x); v0.y = rnd_tf32(v0.y);
                v1.x = rnd_tf32(v1.x); v1.y = rnd_tf32(v1.y);
            }
            if (row0 < M) *reinterpret_cast<float2*>(C + (size_t)row0 * Nc + col) = v0;
            if (row1 < M) *reinterpret_cast<float2*>(C + (size_t)row1 * Nc + col) = v1;
        }
    }
}

// ---------------- GEMM path 2: cp.async + fused attention-coeff + self-max epilogue -----
__global__ void __launch_bounds__(256) tgemm_att_k(
    const float* __restrict__ A1,
    const float* __restrict__ B,
    float* __restrict__ C, int M, int K, int Nc,
    const float* __restrict__ asrc, const float* __restrict__ adst,
    float* __restrict__ osrc, float* __restrict__ odst, unsigned* __restrict__ om)
{
    const int BM = 128, BK = 16;
    __shared__ float As[2][BM][20];
    __shared__ float Bs[2][BK][136];
    __shared__ float attS[128][2];
    __shared__ float attD[128][2];

    int tid = threadIdx.x;
    int lane = tid & 31, wid = tid >> 5;
    int g = lane >> 2, t = lane & 3;
    int wm = wid >> 2, wn = wid & 3;
    int rowBase = blockIdx.y * BM;
    int colBase = blockIdx.x * 128;

    if (tid < 128) {
        attS[tid][0] = 0.f; attS[tid][1] = 0.f;
        attD[tid][0] = 0.f; attD[tid][1] = 0.f;
    }

    float acc[4][4][4];
#pragma unroll
    for (int i = 0; i < 4; i++)
#pragma unroll
        for (int j = 0; j < 4; j++)
#pragma unroll
            for (int r = 0; r < 4; r++) acc[i][j][r] = 0.f;

    int ar0 = tid >> 2, ac0 = (tid & 3) * 4;
    int ar1 = ar0 + 64;
    int br0 = tid >> 5, bc0 = (tid & 31) * 4;
    int br1 = br0 + 8;

    auto loadtile = [&](int kt, int sb) {
        int r0 = rowBase + ar0, r1 = rowBase + ar1;
        cp16(&As[sb][ar0][ac0], A1 + (size_t)r0 * K + kt + ac0, r0 < M);
        cp16(&As[sb][ar1][ac0], A1 + (size_t)r1 * K + kt + ac0, r1 < M);
        cp16(&Bs[sb][br0][bc0], B + (size_t)(kt + br0) * Nc + colBase + bc0, true);
        cp16(&Bs[sb][br1][bc0], B + (size_t)(kt + br1) * Nc + colBase + bc0, true);
        cp_commit();
    };

    int ntiles = K / BK;
    loadtile(0, 0);
    for (int kt = 0; kt < ntiles; kt++) {
        int s = kt & 1;
        if (kt + 1 < ntiles) loadtile((kt + 1) * BK, s ^ 1);
        else cp_commit();
        cp_wait<1>();
        __syncthreads();
#pragma unroll
        for (int ks = 0; ks < 2; ks++) {
            int k0 = ks * 8;
            unsigned a[4][4], b[4][2];
#pragma unroll
            for (int mt = 0; mt < 4; mt++) {
                int m0 = wm * 64 + mt * 16;
                a[mt][0] = __float_as_uint(As[s][m0 + g][k0 + t]);
                a[mt][1] = __float_as_uint(As[s][m0 + g + 8][k0 + t]);
                a[mt][2] = __float_as_uint(As[s][m0 + g][k0 + t + 4]);
                a[mt][3] = __float_as_uint(As[s][m0 + g + 8][k0 + t + 4]);
            }
#pragma unroll
            for (int nt = 0; nt < 4; nt++) {
                int n0 = wn * 32 + nt * 8;
                b[nt][0] = __float_as_uint(Bs[s][k0 + t][n0 + g]);
                b[nt][1] = __float_as_uint(Bs[s][k0 + t + 4][n0 + g]);
            }
#pragma unroll
            for (int mt = 0; mt < 4; mt++)
#pragma unroll
                for (int nt = 0; nt < 4; nt++)
                    mma_tf32(acc[mt][nt], a[mt], b[nt]);
        }
        __syncthreads();
    }

    float as_c[4][2], ad_c[4][2];
#pragma unroll
    for (int nt = 0; nt < 4; nt++) {
        int colG = colBase + wn * 32 + nt * 8 + 2 * t;
        float2 a2 = *reinterpret_cast<const float2*>(asrc + colG);
        float2 d2 = *reinterpret_cast<const float2*>(adst + colG);
        as_c[nt][0] = a2.x; as_c[nt][1] = a2.y;
        ad_c[nt][0] = d2.x; ad_c[nt][1] = d2.y;
    }
    int hl = wn >> 1;

#pragma unroll
    for (int mt = 0; mt < 4; mt++) {
        float s0 = 0.f, d0 = 0.f, s1 = 0.f, d1 = 0.f;
#pragma unroll
        for (int nt = 0; nt < 4; nt++) {
            s0 += acc[mt][nt][0] * as_c[nt][0] + acc[mt][nt][1] * as_c[nt][1];
            d0 += acc[mt][nt][0] * ad_c[nt][0] + acc[mt][nt][1] * ad_c[nt][1];
            s1 += acc[mt][nt][2] * as_c[nt][0] + acc[mt][nt][3] * as_c[nt][1];
            d1 += acc[mt][nt][2] * ad_c[nt][0] + acc[mt][nt][3] * ad_c[nt][1];
        }
#pragma unroll
        for (int off = 1; off <= 2; off <<= 1) {
            s0 += __shfl_xor_sync(0xffffffffu, s0, off);
            d0 += __shfl_xor_sync(0xffffffffu, d0, off);
            s1 += __shfl_xor_sync(0xffffffffu, s1, off);
            d1 += __shfl_xor_sync(0xffffffffu, d1, off);
        }
        if (t == 0) {
            int lr = wm * 64 + mt * 16 + g;
            atomicAdd(&attS[lr][hl], s0);
            atomicAdd(&attD[lr][hl], d0);
            atomicAdd(&attS[lr + 8][hl], s1);
            atomicAdd(&attD[lr + 8][hl], d1);
        }
#pragma unroll
        for (int nt = 0; nt < 4; nt++) {
            int col = colBase + wn * 32 + nt * 8 + 2 * t;
            int row0 = rowBase + wm * 64 + mt * 16 + g;
            int row1 = row0 + 8;
            if (row0 < M) *reinterpret_cast<float2*>(C + (size_t)row0 * Nc + col)
                = make_float2(acc[mt][nt][0], acc[mt][nt][1]);
            if (row1 < M) *reinterpret_cast<float2*>(C + (size_t)row1 * Nc + col)
                = make_float2(acc[mt][nt][2], acc[mt][nt][3]);
        }
    }
    __syncthreads();
    if (tid < 256) {
        int lr = tid >> 1, h = tid & 1;
        int grow = rowBase + lr;
        if (grow < M) {
            float sv = attS[lr][h], dv = attD[lr][h];
            osrc[(size_t)grow * 4 + blockIdx.x * 2 + h] = sv;
            odst[(size_t)grow * 4 + blockIdx.x * 2 + h] = dv;
            om[(size_t)grow * 4 + blockIdx.x * 2 + h] = fmap(leaky(sv + dv));
        }
    }
}

// ---------------- final GEMM: concat(A1,A2)@Wf + bf, fused LN(128) + L2 normalize --------
__global__ void __launch_bounds__(256) tgemm_final_k(
    const float* __restrict__ A1, const float* __restrict__ A2, int K1,
    const float* __restrict__ B, const float* __restrict__ bias,
    const float* __restrict__ gw, const float* __restrict__ bw,
    float* __restrict__ C, int M, int K)
{
    const int BM = 128, BK = 16, Nc = 128;
    __shared__ float As[2][BM][20];
    __shared__ float Bs[2][BK][136];
    __shared__ float redS[128], redQ[128], redN[128];

    int tid = threadIdx.x;
    int lane = tid & 31, wid = tid >> 5;
    int g = lane >> 2, t = lane & 3;
    int wm = wid >> 2, wn = wid & 3;
    int rowBase = blockIdx.x * BM;

    if (tid < 128) { redS[tid] = 0.f; redQ[tid] = 0.f; redN[tid] = 0.f; }

    float acc[4][4][4];
#pragma unroll
    for (int i = 0; i < 4; i++)
#pragma unroll
        for (int j = 0; j < 4; j++)
#pragma unroll
            for (int r = 0; r < 4; r++) acc[i][j][r] = 0.f;

    int ar0 = tid >> 2, ac0 = (tid & 3) * 4;
    int ar1 = ar0 + 64;
    int br0 = tid >> 5, bc0 = (tid & 31) * 4;
    int br1 = br0 + 8;

    auto loadtile = [&](int kt, int sb) {
        const float* Ap; int kk, stride;
        if (kt < K1) { Ap = A1; kk = kt;      stride = K1;     }
        else         { Ap = A2; kk = kt - K1; stride = K - K1; }
        int r0 = rowBase + ar0, r1 = rowBase + ar1;
        cp16(&As[sb][ar0][ac0], Ap + (size_t)r0 * stride + kk + ac0, r0 < M);
        cp16(&As[sb][ar1][ac0], Ap + (size_t)r1 * stride + kk + ac0, r1 < M);
        cp16(&Bs[sb][br0][bc0], B + (size_t)(kt + br0) * Nc + bc0, true);
        cp16(&Bs[sb][br1][bc0], B + (size_t)(kt + br1) * Nc + bc0, true);
        cp_commit();
    };

    int ntiles = K / BK;
    loadtile(0, 0);
    for (int kt = 0; kt < ntiles; kt++) {
        int s = kt & 1;
        if (kt + 1 < ntiles) loadtile((kt + 1) * BK, s ^ 1);
        else cp_commit();
        cp_wait<1>();
        __syncthreads();
#pragma unroll
        for (int ks = 0; ks < 2; ks++) {
            int k0 = ks * 8;
            unsigned a[4][4], b[4][2];
#pragma unroll
            for (int mt = 0; mt < 4; mt++) {
                int m0 = wm * 64 + mt * 16;
                a[mt][0] = __float_as_uint(As[s][m0 + g][k0 + t]);
                a[mt][1] = __float_as_uint(As[s][m0 + g + 8][k0 + t]);
                a[mt][2] = __float_as_uint(As[s][m0 + g][k0 + t + 4]);
                a[mt][3] = __float_as_uint(As[s][m0 + g + 8][k0 + t + 4]);
            }
#pragma unroll
            for (int nt = 0; nt < 4; nt++) {
                int n0 = wn * 32 + nt * 8;
                b[nt][0] = __float_as_uint(Bs[s][k0 + t][n0 + g]);
                b[nt][1] = __float_as_uint(Bs[s][k0 + t + 4][n0 + g]);
            }
#pragma unroll
            for (int mt = 0; mt < 4; mt++)
#pragma unroll
                for (int nt = 0; nt < 4; nt++)
                    mma_tf32(acc[mt][nt], a[mt], b[nt]);
        }
        __syncthreads();
    }

#pragma unroll
    for (int nt = 0; nt < 4; nt++) {
        int col = wn * 32 + nt * 8 + 2 * t;
        float2 bb = *reinterpret_cast<const float2*>(bias + col);
#pragma unroll
        for (int mt = 0; mt < 4; mt++) {
            acc[mt][nt][0] += bb.x; acc[mt][nt][1] += bb.y;
            acc[mt][nt][2] += bb.x; acc[mt][nt][3] += bb.y;
        }
    }
#pragma unroll
    for (int mt = 0; mt < 4; mt++) {
        float s0 = 0.f, q0 = 0.f, s1 = 0.f, q1 = 0.f;
#pragma unroll
        for (int nt = 0; nt < 4; nt++) {
            s0 += acc[mt][nt][0] + acc[mt][nt][1];
            q0 += acc[mt][nt][0] * acc[mt][nt][0] + acc[mt][nt][1] * acc[mt][nt][1];
            s1 += acc[mt][nt][2] + acc[mt][nt][3];
            q1 += acc[mt][nt][2] * acc[mt][nt][2] + acc[mt][nt][3] * acc[mt][nt][3];
        }
#pragma unroll
        for (int off = 1; off <= 2; off <<= 1) {
            s0 += __shfl_xor_sync(0xffffffffu, s0, off);
            q0 += __shfl_xor_sync(0xffffffffu, q0, off);
            s1 += __shfl_xor_sync(0xffffffffu, s1, off);
            q1 += __shfl_xor_sync(0xffffffffu, q1, off);
        }
        if (t == 0) {
            int lr = wm * 64 + mt * 16 + g;
            atomicAdd(&redS[lr], s0); atomicAdd(&redQ[lr], q0);
            atomicAdd(&redS[lr + 8], s1); atomicAdd(&redQ[lr + 8], q1);
        }
    }
    __syncthreads();
#pragma unroll
    for (int mt = 0; mt < 4; mt++) {
        int lr0 = wm * 64 + mt * 16 + g, lr1 = lr0 + 8;
        float m0 = redS[lr0] * (1.f / 128.f), m1 = redS[lr1] * (1.f / 128.f);
        float var0 = redQ[lr0] * (1.f / 128.f) - m0 * m0;
        float var1 = redQ[lr1] * (1.f / 128.f) - m1 * m1;
        float r0 = rsqrtf(var0 + 1e-5f), r1 = rsqrtf(var1 + 1e-5f);
        float n0 = 0.f, n1 = 0.f;
#pragma unroll
        for (int nt = 0; nt < 4; nt++) {
            int col = wn * 32 + nt * 8 + 2 * t;
            float2 gg = *reinterpret_cast<const float2*>(gw + col);
            float2 b2 = *reinterpret_cast<const float2*>(bw + col);
            float y00 = (acc[mt][nt][0] - m0) * r0 * gg.x + b2.x;
            float y01 = (acc[mt][nt][1] - m0) * r0 * gg.y + b2.y;
            float y10 = (acc[mt][nt][2] - m1) * r1 * gg.x + b2.x;
            float y11 = (acc[mt][nt][3] - m1) * r1 * gg.y + b2.y;
            acc[mt][nt][0] = y00; acc[mt][nt][1] = y01;
            acc[mt][nt][2] = y10; acc[mt][nt][3] = y11;
            n0 += y00 * y00 + y01 * y01;
            n1 += y10 * y10 + y11 * y11;
        }
#pragma unroll
        for (int off = 1; off <= 2; off <<= 1) {
            n0 += __shfl_xor_sync(0xffffffffu, n0, off);
            n1 += __shfl_xor_sync(0xffffffffu, n1, off);
        }
        if (t == 0) { atomicAdd(&redN[lr0], n0); atomicAdd(&redN[lr1], n1); }
    }
    __syncthreads();
#pragma unroll
    for (int mt = 0; mt < 4; mt++) {
        int lr0 = wm * 64 + mt * 16 + g, lr1 = lr0 + 8;
        float inv0 = 1.f / fmaxf(sqrtf(redN[lr0]), 1e-12f);
        float inv1 = 1.f / fmaxf(sqrtf(redN[lr1]), 1e-12f);
        int row0 = rowBase + lr0, row1 = rowBase + lr1;
#pragma unroll
        for (int nt = 0; nt < 4; nt++) {
            int col = wn * 32 + nt * 8 + 2 * t;
            if (row0 < M) *reinterpret_cast<float2*>(C + (size_t)row0 * 128 + col)
                = make_float2(acc[mt][nt][0] * inv0, acc[mt][nt][1] * inv0);
            if (row1 < M) *reinterpret_cast<float2*>(C + (size_t)row1 * 128 + col)
                = make_float2(acc[mt][nt][2] * inv1, acc[mt][nt][3] * inv1);
        }
    }
}

// ---------------- round weights once into g_wt ----------------
__global__ void round_w_k(const float* __restrict__ w0, const float* __restrict__ w1,
                          const float* __restrict__ w2, float* __restrict__ out)
{
    int i = blockIdx.x * 256 + threadIdx.x;
    out[i]          = rnd_tf32(w0[i]);
    out[65536 + i]  = rnd_tf32(w1[i]);
    out[131072 + i] = rnd_tf32(w2[i]);
}

// ---------------- edge pass 1 (real edges only): logits + segment max --------------------
__global__ void edge_logits_k(const int* __restrict__ ei,
                              const float* __restrict__ asrc, const float* __restrict__ adst,
                              float* __restrict__ ebuf, unsigned* __restrict__ m)
{
    int i = blockIdx.x * blockDim.x + threadIdx.x;
    if (i >= EE) return;
    int s = ei[i], d = ei[EE + i];
    float4 as = *reinterpret_cast<const float4*>(asrc + (size_t)s * 4);
    float4 ad = *reinterpret_cast<const float4*>(adst + (size_t)d * 4);
    float e[4] = {as.x + ad.x, as.y + ad.y, as.z + ad.z, as.w + ad.w};
    float4 o;
    float* op = &o.x;
#pragma unroll
    for (int h = 0; h < 4; h++) {
        float v = leaky(e[h]);
        op[h] = v;
        atomicMax(m + d * 4 + h, fmap(v));
    }
    *reinterpret_cast<float4*>(ebuf + (size_t)i * 4) = o;
}

// ---------------- den init (after max pass): den[n] = exp(e_self - m[n]) ----------------
__global__ void den_init_k(const float* __restrict__ asrc, const float* __restrict__ adst,
                           const unsigned* __restrict__ m, float* __restrict__ den)
{
    int n = blockIdx.x * blockDim.x + threadIdx.x;
    if (n >= NN) return;
    float4 as = *reinterpret_cast<const float4*>(asrc + (size_t)n * 4);
    float4 ad = *reinterpret_cast<const float4*>(adst + (size_t)n * 4);
    uint4 mu = *reinterpret_cast<const uint4*>(m + (size_t)n * 4);
    float4 o;
    o.x = expf(leaky(as.x + ad.x) - funmap(mu.x));
    o.y = expf(leaky(as.y + ad.y) - funmap(mu.y));
    o.z = expf(leaky(as.z + ad.z) - funmap(mu.z));
    o.w = expf(leaky(as.w + ad.w) - funmap(mu.w));
    *reinterpret_cast<float4*>(den + (size_t)n * 4) = o;
}

// ---------------- edge pass 2 (real edges only): exp + segment sum ----------------------
__global__ void edge_exp_k(const int* __restrict__ ei,
                           const unsigned* __restrict__ m, float* __restrict__ ebuf,
                           float* __restrict__ den)
{
    int i = blockIdx.x * blockDim.x + threadIdx.x;
    if (i >= EE) return;
    int d = ei[EE + i];
    float4 e = *reinterpret_cast<const float4*>(ebuf + (size_t)i * 4);
    float4 o;
    o.x = expf(e.x - funmap(m[d * 4 + 0]));
    o.y = expf(e.y - funmap(m[d * 4 + 1]));
    o.z = expf(e.z - funmap(m[d * 4 + 2]));
    o.w = expf(e.w - funmap(m[d * 4 + 3]));
    *reinterpret_cast<float4*>(ebuf + (size_t)i * 4) = o;
    red4(den + (size_t)d * 4, o);
}

// ---------------- edge pass 3 (real edges only): weighted scatter -----------------------
__global__ void __launch_bounds__(256) edge_scatter_k(const int* __restrict__ ei,
        const float* __restrict__ ebuf, const float* __restrict__ den,
        const float* __restrict__ hw, float* __restrict__ acc)
{
    int idx = blockIdx.x * 4 + (threadIdx.x >> 6);
    int lane = threadIdx.x & 63;
    if (idx >= EE) return;
    int s = ei[idx], d = ei[EE + idx];
    float4 ex = *reinterpret_cast<const float4*>(ebuf + (size_t)idx * 4);
    float4 dn = *reinterpret_cast<const float4*>(den + (size_t)d * 4);
    int head = lane >> 4;
    float exs = (head == 0) ? ex.x : (head == 1) ? ex.y : (head == 2) ? ex.z : ex.w;
    float dns = (head == 0) ? dn.x : (head == 1) ? dn.y : (head == 2) ? dn.z : dn.w;
    float al = exs / dns;
    float4 hv = reinterpret_cast<const float4*>(hw + (size_t)s * 256)[lane];
    float4 v = make_float4(hv.x * al, hv.y * al, hv.z * al, hv.w * al);
    red4(acc + (size_t)d * 256 + lane * 4, v);
}

// ---------------- LN(256) of (acc + alpha_self*hw + bias), ReLU, tf32-rounded out -------
__global__ void ln_relu_k(const float* __restrict__ in, const float* __restrict__ hw,
                          const float* __restrict__ asrc, const float* __restrict__ adst,
                          const unsigned* __restrict__ m, const float* __restrict__ den,
                          const float* __restrict__ bias,
                          const float* __restrict__ g, const float* __restrict__ b,
                          float* __restrict__ out)
{
    int row = (blockIdx.x * blockDim.x + threadIdx.x) >> 5;
    int lane = threadIdx.x & 31;
    if (row >= NN) return;
    int h = lane >> 3;
    float es = leaky(asrc[row * 4 + h] + adst[row * 4 + h]);
    float al = expf(es - funmap(m[row * 4 + h])) / den[row * 4 + h];

    const float4* ip = reinterpret_cast<const float4*>(in + (size_t)row * 256);
    const float4* hp = reinterpret_cast<const float4*>(hw + (size_t)row * 256);
    const float4* bsp = reinterpret_cast<const float4*>(bias);
    float4 v0 = ip[lane * 2], v1 = ip[lane * 2 + 1];
    float4 h0 = hp[lane * 2], h1 = hp[lane * 2 + 1];
    float4 a0 = bsp[lane * 2], a1 = bsp[lane * 2 + 1];
    v0.x += al * h0.x + a0.x; v0.y += al * h0.y + a0.y;
    v0.z += al * h0.z + a0.z; v0.w += al * h0.w + a0.w;
    v1.x += al * h1.x + a1.x; v1.y += al * h1.y + a1.y;
    v1.z += al * h1.z + a1.z; v1.w += al * h1.w + a1.w;
    float sum = v0.x + v0.y + v0.z + v0.w + v1.x + v1.y + v1.z + v1.w;
#pragma unroll
    for (int off = 16; off; off >>= 1) sum += __shfl_xor_sync(0xffffffffu, sum, off);
    float mean = sum * (1.f / 256.f);
    float c0x = v0.x - mean, c0y = v0.y - mean, c0z = v0.z - mean, c0w = v0.w - mean;
    float c1x = v1.x - mean, c1y = v1.y - mean, c1z = v1.z - mean, c1w = v1.w - mean;
    float sq = c0x * c0x + c0y * c0y + c0z * c0z + c0w * c0w
             + c1x * c1x + c1y * c1y + c1z * c1z + c1w * c1w;
#pragma unroll
    for (int off = 16; off; off >>= 1) sq += __shfl_xor_sync(0xffffffffu, sq, off);
    float r = rsqrtf(sq * (1.f / 256.f) + 1e-5f);
    const float4* gp = reinterpret_cast<const float4*>(g);
    const float4* bp = reinterpret_cast<const float4*>(b);
    float4 g0 = gp[lane * 2], g1 = gp[lane * 2 + 1];
    float4 b0 = bp[lane * 2], b1 = bp[lane * 2 + 1];
    float4 o0, o1;
    o0.x = rnd_tf32(fmaxf(c0x * r * g0.x + b0.x, 0.f));
    o0.y = rnd_tf32(fmaxf(c0y * r * g0.y + b0.y, 0.f));
    o0.z = rnd_tf32(fmaxf(c0z * r * g0.z + b0.z, 0.f));
    o0.w = rnd_tf32(fmaxf(c0w * r * g0.w + b0.w, 0.f));
    o1.x = rnd_tf32(fmaxf(c1x * r * g1.x + b1.x, 0.f));
    o1.y = rnd_tf32(fmaxf(c1y * r * g1.y + b1.y, 0.f));
    o1.z = rnd_tf32(fmaxf(c1z * r * g1.z + b1.z, 0.f));
    o1.w = rnd_tf32(fmaxf(c1w * r * g1.w + b1.w, 0.f));
    float4* op = reinterpret_cast<float4*>(out + (size_t)row * 256);
    op[lane * 2] = o0;
    op[lane * 2 + 1] = o1;
}

// ---------------- launcher ----------------
extern "C" void kernel_launch(void* const* d_in, const int* in_sizes, int n_in,
                              void* d_out, int out_size)
{
    const float* x       = (const float*)d_in[0];
    const int*   ei_bu   = (const int*)d_in[1];
    const int*   ei_td   = (const int*)d_in[2];
    const float* Wp      = (const float*)d_in[3];
    const float* bp      = (const float*)d_in[4];
    const float* W_bu    = (const float*)d_in[5];
    const float* asrc_bu = (const float*)d_in[6];
    const float* adst_bu = (const float*)d_in[7];
    const float* bias_bu = (const float*)d_in[8];
    const float* W_td    = (const float*)d_in[9];
    const float* asrc_td = (const float*)d_in[10];
    const float* adst_td = (const float*)d_in[11];
    const float* bias_td = (const float*)d_in[12];
    const float* Wf      = (const float*)d_in[13];
    const float* bf      = (const float*)d_in[14];
    const float* g_bu    = (const float*)d_in[15];
    const float* b_bu    = (const float*)d_in[16];
    const float* g_td    = (const float*)d_in[17];
    const float* b_td    = (const float*)d_in[18];
    const float* g_out   = (const float*)d_in[19];
    const float* b_out   = (const float*)d_in[20];
    float* out = (float*)d_out;

    float *ph, *pxbu, *pxtd, *pwt;
    float *phw[2], *pacc[2], *pas[2], *pad[2], *pden[2], *pe[2];
    unsigned *pm[2];
    cudaGetSymbolAddress((void**)&ph,      g_h);
    cudaGetSymbolAddress((void**)&phw[0],  g_hw0);
    cudaGetSymbolAddress((void**)&phw[1],  g_hw1);
    cudaGetSymbolAddress((void**)&pacc[0], g_acc0);
    cudaGetSymbolAddress((void**)&pacc[1], g_acc1);
    cudaGetSymbolAddress((void**)&pxbu,    g_xbu);
    cudaGetSymbolAddress((void**)&pxtd,    g_xtd);
    cudaGetSymbolAddress((void**)&pas[0],  g_as0);
    cudaGetSymbolAddress((void**)&pas[1],  g_as1);
    cudaGetSymbolAddress((void**)&pad[0],  g_ad0);
    cudaGetSymbolAddress((void**)&pad[1],  g_ad1);
    cudaGetSymbolAddress((void**)&pm[0],   g_m0);
    cudaGetSymbolAddress((void**)&pm[1],   g_m1);
    cudaGetSymbolAddress((void**)&pden[0], g_den0);
    cudaGetSymbolAddress((void**)&pden[1], g_den1);
    cudaGetSymbolAddress((void**)&pe[0],   g_e0);
    cudaGetSymbolAddress((void**)&pe[1],   g_e1);
    cudaGetSymbolAddress((void**)&pwt,     g_wt);

    // one-time stream/event creation (host resources, not device memory)
    static cudaStream_t s1 = nullptr;
    static cudaEvent_t evFork = nullptr, evJoin = nullptr;
    if (s1 == nullptr) {
        cudaStreamCreateWithFlags(&s1, cudaStreamNonBlocking);
        cudaEventCreateWithFlags(&evFork, cudaEventDisableTiming);
        cudaEventCreateWithFlags(&evJoin, cudaEventDisableTiming);
    }

    const int mblocks = (NN + 127) / 128;               // 1563
    const dim3 gemmGrid256(2, mblocks);
    const int warpRowBlocks = (NN * 32) / 256;          // 25000
    const int nodeBlocks    = (NN + 255) / 256;         // 782
    const int edgeBlocks    = (EE + 255) / 256;         // 782
    const int scatBlocks    = (EE + 3) / 4;             // 50000

    round_w_k<<<256, 256>>>(W_bu, W_td, Wf, pwt);

    // h = round_tf32(relu(x @ Wp + bp))
    tgemm_k<true, true, true><<<gemmGrid256, 256>>>(x, Wp, bp, ph, NN, 256, 256);

    // fork: dir1 chain runs on s1 concurrently with dir0 chain on the capture stream
    cudaEventRecord(evFork, 0);
    cudaStreamWaitEvent(s1, evFork, 0);

    const int*   eis[2]   = {ei_bu, ei_td};
    const float* asr[2]   = {asrc_bu, asrc_td};
    const float* ads[2]   = {adst_bu, adst_td};
    const float* bis[2]   = {bias_bu, bias_td};
    const float* gln[2]   = {g_bu, g_td};
    const float* bln[2]   = {b_bu, b_td};
    float*       xdir[2]  = {pxbu, pxtd};

    for (int dir = 0; dir < 2; dir++) {
        cudaStream_t st = (dir == 0) ? (cudaStream_t)0 : s1;
        cudaMemsetAsync(pacc[dir], 0, (size_t)NN * 256 * sizeof(float), st);
        tgemm_att_k<<<gemmGrid256, 256, 0, st>>>(
            ph, pwt + dir * 65536, phw[dir], NN, 256, 256,
            asr[dir], ads[dir], pas[dir], pad[dir], pm[dir]);
        edge_logits_k<<<edgeBlocks, 256, 0, st>>>(eis[dir], pas[dir], pad[dir], pe[dir], pm[dir]);
        den_init_k<<<nodeBlocks, 256, 0, st>>>(pas[dir], pad[dir], pm[dir], pden[dir]);
        edge_exp_k<<<edgeBlocks, 256, 0, st>>>(eis[dir], pm[dir], pe[dir], pden[dir]);
        edge_scatter_k<<<scatBlocks, 256, 0, st>>>(eis[dir], pe[dir], pden[dir], phw[dir], pacc[dir]);
        ln_relu_k<<<warpRowBlocks, 256, 0, st>>>(pacc[dir], phw[dir], pas[dir], pad[dir],
                                                 pm[dir], pden[dir],
                                                 bis[dir], gln[dir], bln[dir], xdir[dir]);
    }

    // join
    cudaEventRecord(evJoin, s1);
    cudaStreamWaitEvent(0, evJoin, 0);

    // out = L2norm(LN(concat(x_bu, x_td) @ Wf + bf)) fused
    tgemm_final_k<<<mblocks, 256>>>(pxbu, pxtd, 256, pwt + 131072, bf,
                                    g_out, b_out, out, NN, 512);
}

// round 10
// speedup vs baseline: 2.9813x; 1.0080x over previous
#include <cuda_runtime.h>
#include <cstdint>

#define NN 200000
#define EE 200000

// ---------------- scratch (static device globals; no runtime allocation) ----------------
__device__ float    g_h   [(size_t)NN * 256];
__device__ float    g_hw0 [(size_t)NN * 256];
__device__ float    g_hw1 [(size_t)NN * 256];
__device__ float    g_acc0[(size_t)NN * 256];
__device__ float    g_acc1[(size_t)NN * 256];
__device__ float    g_xbu [(size_t)NN * 256];
__device__ float    g_xtd [(size_t)NN * 256];
__device__ float    g_as0 [NN * 4];
__device__ float    g_as1 [NN * 4];
__device__ float    g_ad0 [NN * 4];
__device__ float    g_ad1 [NN * 4];
__device__ float    g_den0[NN * 4];
__device__ float    g_den1[NN * 4];
__device__ float    g_e0  [(size_t)EE * 4];
__device__ float    g_e1  [(size_t)EE * 4];
__device__ float    g_wt  [3 * 65536];     // pre-rounded W_bu | W_td | Wf

// ---------------- helpers ----------------
__device__ __forceinline__ unsigned f2tf32(float f) {
    unsigned r;
    asm("cvt.rna.tf32.f32 %0, %1;" : "=r"(r) : "f"(f));
    return r;
}
__device__ __forceinline__ float rnd_tf32(float f) { return __uint_as_float(f2tf32(f)); }

__device__ __forceinline__ void mma_tf32(float c[4], const unsigned a[4], const unsigned b[2]) {
    asm volatile(
        "mma.sync.aligned.m16n8k8.row.col.f32.tf32.tf32.f32 "
        "{%0,%1,%2,%3}, {%4,%5,%6,%7}, {%8,%9}, {%0,%1,%2,%3};\n"
        : "+f"(c[0]), "+f"(c[1]), "+f"(c[2]), "+f"(c[3])
        : "r"(a[0]), "r"(a[1]), "r"(a[2]), "r"(a[3]), "r"(b[0]), "r"(b[1]));
}

__device__ __forceinline__ void cp16(void* smem_dst, const void* gsrc, bool pred) {
    uint32_t s = (uint32_t)__cvta_generic_to_shared(smem_dst);
    int sz = pred ? 16 : 0;
    asm volatile("cp.async.cg.shared.global [%0], [%1], 16, %2;\n"
                 :: "r"(s), "l"(gsrc), "r"(sz));
}
__device__ __forceinline__ void cp_commit() { asm volatile("cp.async.commit_group;\n"); }
template<int N>
__device__ __forceinline__ void cp_wait() { asm volatile("cp.async.wait_group %0;\n" :: "n"(N)); }

__device__ __forceinline__ void red4(float* p, float4 v) {
    asm volatile("red.global.add.v4.f32 [%0], {%1,%2,%3,%4};\n"
                 :: "l"(p), "f"(v.x), "f"(v.y), "f"(v.z), "f"(v.w) : "memory");
}

__device__ __forceinline__ float leaky(float v) { return v > 0.f ? v : 0.2f * v; }

// ---------------- GEMM path 1: register-staged with tf32 cvt (raw fp32 input x) ----------
template<bool RELU, bool BIAS, bool ROUND>
__global__ void __launch_bounds__(256) tgemm_k(
    const float* __restrict__ A1,
    const float* __restrict__ B, const float* __restrict__ bias,
    float* __restrict__ C, int M, int K, int Nc)
{
    const int BM = 128, BK = 16;
    __shared__ float As[2][BM][20];
    __shared__ float Bs[2][BK][136];

    int tid = threadIdx.x;
    int lane = tid & 31, wid = tid >> 5;
    int g = lane >> 2, t = lane & 3;
    int wm = wid >> 2, wn = wid & 3;
    int rowBase = blockIdx.y * BM;
    int colBase = blockIdx.x * 128;

    float acc[4][4][4];
#pragma unroll
    for (int i = 0; i < 4; i++)
#pragma unroll
        for (int j = 0; j < 4; j++)
#pragma unroll
            for (int r = 0; r < 4; r++) acc[i][j][r] = 0.f;

    int ar0 = tid >> 2,          ac0 = (tid & 3) * 4;
    int ar1 = (tid + 256) >> 2;
    int br0 = tid >> 5,          bc0 = (tid & 31) * 4;
    int br1 = (tid + 256) >> 5;

    float4 pa0, pa1, pb0, pb1;
    const float4 z4 = make_float4(0.f, 0.f, 0.f, 0.f);

    int ntiles = K / BK;
    int s = 0;
    {
        int r0 = rowBase + ar0, r1 = rowBase + ar1;
        pa0 = (r0 < M) ? *reinterpret_cast<const float4*>(A1 + (size_t)r0 * K + ac0) : z4;
        pa1 = (r1 < M) ? *reinterpret_cast<const float4*>(A1 + (size_t)r1 * K + ac0) : z4;
        pb0 = *reinterpret_cast<const float4*>(B + (size_t)br0 * Nc + colBase + bc0);
        pb1 = *reinterpret_cast<const float4*>(B + (size_t)br1 * Nc + colBase + bc0);
        As[0][ar0][ac0 + 0] = rnd_tf32(pa0.x); As[0][ar0][ac0 + 1] = rnd_tf32(pa0.y);
        As[0][ar0][ac0 + 2] = rnd_tf32(pa0.z); As[0][ar0][ac0 + 3] = rnd_tf32(pa0.w);
        As[0][ar1][ac0 + 0] = rnd_tf32(pa1.x); As[0][ar1][ac0 + 1] = rnd_tf32(pa1.y);
        As[0][ar1][ac0 + 2] = rnd_tf32(pa1.z); As[0][ar1][ac0 + 3] = rnd_tf32(pa1.w);
        Bs[0][br0][bc0 + 0] = rnd_tf32(pb0.x); Bs[0][br0][bc0 + 1] = rnd_tf32(pb0.y);
        Bs[0][br0][bc0 + 2] = rnd_tf32(pb0.z); Bs[0][br0][bc0 + 3] = rnd_tf32(pb0.w);
        Bs[0][br1][bc0 + 0] = rnd_tf32(pb1.x); Bs[0][br1][bc0 + 1] = rnd_tf32(pb1.y);
        Bs[0][br1][bc0 + 2] = rnd_tf32(pb1.z); Bs[0][br1][bc0 + 3] = rnd_tf32(pb1.w);
    }
    __syncthreads();
    for (int kt = 0; kt < ntiles; kt++) {
        bool more = (kt + 1 < ntiles);
        if (more) {
            int kk = (kt + 1) * BK;
            int r0 = rowBase + ar0, r1 = rowBase + ar1;
            pa0 = (r0 < M) ? *reinterpret_cast<const float4*>(A1 + (size_t)r0 * K + kk + ac0) : z4;
            pa1 = (r1 < M) ? *reinterpret_cast<const float4*>(A1 + (size_t)r1 * K + kk + ac0) : z4;
            pb0 = *reinterpret_cast<const float4*>(B + (size_t)(kk + br0) * Nc + colBase + bc0);
            pb1 = *reinterpret_cast<const float4*>(B + (size_t)(kk + br1) * Nc + colBase + bc0);
        }
#pragma unroll
        for (int ks = 0; ks < 2; ks++) {
            int k0 = ks * 8;
            unsigned a[4][4], b[4][2];
#pragma unroll
            for (int mt = 0; mt < 4; mt++) {
                int m0 = wm * 64 + mt * 16;
                a[mt][0] = __float_as_uint(As[s][m0 + g][k0 + t]);
                a[mt][1] = __float_as_uint(As[s][m0 + g + 8][k0 + t]);
                a[mt][2] = __float_as_uint(As[s][m0 + g][k0 + t + 4]);
                a[mt][3] = __float_as_uint(As[s][m0 + g + 8][k0 + t + 4]);
            }
#pragma unroll
            for (int nt = 0; nt < 4; nt++) {
                int n0 = wn * 32 + nt * 8;
                b[nt][0] = __float_as_uint(Bs[s][k0 + t][n0 + g]);
                b[nt][1] = __float_as_uint(Bs[s][k0 + t + 4][n0 + g]);
            }
#pragma unroll
            for (int mt = 0; mt < 4; mt++)
#pragma unroll
                for (int nt = 0; nt < 4; nt++)
                    mma_tf32(acc[mt][nt], a[mt], b[nt]);
        }
        if (more) {
            int so = s ^ 1;
            As[so][ar0][ac0 + 0] = rnd_tf32(pa0.x); As[so][ar0][ac0 + 1] = rnd_tf32(pa0.y);
            As[so][ar0][ac0 + 2] = rnd_tf32(pa0.z); As[so][ar0][ac0 + 3] = rnd_tf32(pa0.w);
            As[so][ar1][ac0 + 0] = rnd_tf32(pa1.x); As[so][ar1][ac0 + 1] = rnd_tf32(pa1.y);
            As[so][ar1][ac0 + 2] = rnd_tf32(pa1.z); As[so][ar1][ac0 + 3] = rnd_tf32(pa1.w);
            Bs[so][br0][bc0 + 0] = rnd_tf32(pb0.x); Bs[so][br0][bc0 + 1] = rnd_tf32(pb0.y);
            Bs[so][br0][bc0 + 2] = rnd_tf32(pb0.z); Bs[so][br0][bc0 + 3] = rnd_tf32(pb0.w);
            Bs[so][br1][bc0 + 0] = rnd_tf32(pb1.x); Bs[so][br1][bc0 + 1] = rnd_tf32(pb1.y);
            Bs[so][br1][bc0 + 2] = rnd_tf32(pb1.z); Bs[so][br1][bc0 + 3] = rnd_tf32(pb1.w);
            __syncthreads();
        }
        s ^= 1;
    }

#pragma unroll
    for (int nt = 0; nt < 4; nt++) {
        int col = colBase + wn * 32 + nt * 8 + 2 * t;
        float2 bb = make_float2(0.f, 0.f);
        if (BIAS) bb = *reinterpret_cast<const float2*>(bias + col);
#pragma unroll
        for (int mt = 0; mt < 4; mt++) {
            int row0 = rowBase + wm * 64 + mt * 16 + g;
            int row1 = row0 + 8;
            float2 v0 = make_float2(acc[mt][nt][0] + bb.x, acc[mt][nt][1] + bb.y);
            float2 v1 = make_float2(acc[mt][nt][2] + bb.x, acc[mt][nt][3] + bb.y);
            if (RELU) {
                v0.x = fmaxf(v0.x, 0.f); v0.y = fmaxf(v0.y, 0.f);
                v1.x = fmaxf(v1.x, 0.f); v1.y = fmaxf(v1.y, 0.f);
            }
            if (ROUND) {
                v0.x = rnd_tf32(v0.x); v0.y = rnd_tf32(v0.y);
                v1.x = rnd_tf32(v1.x); v1.y = rnd_tf32(v1.y);
            }
            if (row0 < M) *reinterpret_cast<float2*>(C + (size_t)row0 * Nc + col) = v0;
            if (row1 < M) *reinterpret_cast<float2*>(C + (size_t)row1 * Nc + col) = v1;
        }
    }
}

// ---------------- GEMM path 2: cp.async + fused attention-coefficient epilogue ----------
__global__ void __launch_bounds__(256) tgemm_att_k(
    const float* __restrict__ A1,
    const float* __restrict__ B,
    float* __restrict__ C, int M, int K, int Nc,
    const float* __restrict__ asrc, const float* __restrict__ adst,
    float* __restrict__ osrc, float* __restrict__ odst)
{
    const int BM = 128, BK = 16;
    __shared__ float As[2][BM][20];
    __shared__ float Bs[2][BK][136];
    __shared__ float attS[128][2];
    __shared__ float attD[128][2];

    int tid = threadIdx.x;
    int lane = tid & 31, wid = tid >> 5;
    int g = lane >> 2, t = lane & 3;
    int wm = wid >> 2, wn = wid & 3;
    int rowBase = blockIdx.y * BM;
    int colBase = blockIdx.x * 128;

    if (tid < 128) {
        attS[tid][0] = 0.f; attS[tid][1] = 0.f;
        attD[tid][0] = 0.f; attD[tid][1] = 0.f;
    }

    float acc[4][4][4];
#pragma unroll
    for (int i = 0; i < 4; i++)
#pragma unroll
        for (int j = 0; j < 4; j++)
#pragma unroll
            for (int r = 0; r < 4; r++) acc[i][j][r] = 0.f;

    int ar0 = tid >> 2, ac0 = (tid & 3) * 4;
    int ar1 = ar0 + 64;
    int br0 = tid >> 5, bc0 = (tid & 31) * 4;
    int br1 = br0 + 8;

    auto loadtile = [&](int kt, int sb) {
        int r0 = rowBase + ar0, r1 = rowBase + ar1;
        cp16(&As[sb][ar0][ac0], A1 + (size_t)r0 * K + kt + ac0, r0 < M);
        cp16(&As[sb][ar1][ac0], A1 + (size_t)r1 * K + kt + ac0, r1 < M);
        cp16(&Bs[sb][br0][bc0], B + (size_t)(kt + br0) * Nc + colBase + bc0, true);
        cp16(&Bs[sb][br1][bc0], B + (size_t)(kt + br1) * Nc + colBase + bc0, true);
        cp_commit();
    };

    int ntiles = K / BK;
    loadtile(0, 0);
    for (int kt = 0; kt < ntiles; kt++) {
        int s = kt & 1;
        if (kt + 1 < ntiles) loadtile((kt + 1) * BK, s ^ 1);
        else cp_commit();
        cp_wait<1>();
        __syncthreads();
#pragma unroll
        for (int ks = 0; ks < 2; ks++) {
            int k0 = ks * 8;
            unsigned a[4][4], b[4][2];
#pragma unroll
            for (int mt = 0; mt < 4; mt++) {
                int m0 = wm * 64 + mt * 16;
                a[mt][0] = __float_as_uint(As[s][m0 + g][k0 + t]);
                a[mt][1] = __float_as_uint(As[s][m0 + g + 8][k0 + t]);
                a[mt][2] = __float_as_uint(As[s][m0 + g][k0 + t + 4]);
                a[mt][3] = __float_as_uint(As[s][m0 + g + 8][k0 + t + 4]);
            }
#pragma unroll
            for (int nt = 0; nt < 4; nt++) {
                int n0 = wn * 32 + nt * 8;
                b[nt][0] = __float_as_uint(Bs[s][k0 + t][n0 + g]);
                b[nt][1] = __float_as_uint(Bs[s][k0 + t + 4][n0 + g]);
            }
#pragma unroll
            for (int mt = 0; mt < 4; mt++)
#pragma unroll
                for (int nt = 0; nt < 4; nt++)
                    mma_tf32(acc[mt][nt], a[mt], b[nt]);
        }
        __syncthreads();
    }

    float as_c[4][2], ad_c[4][2];
#pragma unroll
    for (int nt = 0; nt < 4; nt++) {
        int colG = colBase + wn * 32 + nt * 8 + 2 * t;
        float2 a2 = *reinterpret_cast<const float2*>(asrc + colG);
        float2 d2 = *reinterpret_cast<const float2*>(adst + colG);
        as_c[nt][0] = a2.x; as_c[nt][1] = a2.y;
        ad_c[nt][0] = d2.x; ad_c[nt][1] = d2.y;
    }
    int hl = wn >> 1;

#pragma unroll
    for (int mt = 0; mt < 4; mt++) {
        float s0 = 0.f, d0 = 0.f, s1 = 0.f, d1 = 0.f;
#pragma unroll
        for (int nt = 0; nt < 4; nt++) {
            s0 += acc[mt][nt][0] * as_c[nt][0] + acc[mt][nt][1] * as_c[nt][1];
            d0 += acc[mt][nt][0] * ad_c[nt][0] + acc[mt][nt][1] * ad_c[nt][1];
            s1 += acc[mt][nt][2] * as_c[nt][0] + acc[mt][nt][3] * as_c[nt][1];
            d1 += acc[mt][nt][2] * ad_c[nt][0] + acc[mt][nt][3] * ad_c[nt][1];
        }
#pragma unroll
        for (int off = 1; off <= 2; off <<= 1) {
            s0 += __shfl_xor_sync(0xffffffffu, s0, off);
            d0 += __shfl_xor_sync(0xffffffffu, d0, off);
            s1 += __shfl_xor_sync(0xffffffffu, s1, off);
            d1 += __shfl_xor_sync(0xffffffffu, d1, off);
        }
        if (t == 0) {
            int lr = wm * 64 + mt * 16 + g;
            atomicAdd(&attS[lr][hl], s0);
            atomicAdd(&attD[lr][hl], d0);
            atomicAdd(&attS[lr + 8][hl], s1);
            atomicAdd(&attD[lr + 8][hl], d1);
        }
#pragma unroll
        for (int nt = 0; nt < 4; nt++) {
            int col = colBase + wn * 32 + nt * 8 + 2 * t;
            int row0 = rowBase + wm * 64 + mt * 16 + g;
            int row1 = row0 + 8;
            if (row0 < M) *reinterpret_cast<float2*>(C + (size_t)row0 * Nc + col)
                = make_float2(acc[mt][nt][0], acc[mt][nt][1]);
            if (row1 < M) *reinterpret_cast<float2*>(C + (size_t)row1 * Nc + col)
                = make_float2(acc[mt][nt][2], acc[mt][nt][3]);
        }
    }
    __syncthreads();
    if (tid < 256) {
        int lr = tid >> 1, h = tid & 1;
        int grow = rowBase + lr;
        if (grow < M) {
            osrc[(size_t)grow * 4 + blockIdx.x * 2 + h] = attS[lr][h];
            odst[(size_t)grow * 4 + blockIdx.x * 2 + h] = attD[lr][h];
        }
    }
}

// ---------------- final GEMM: concat(A1,A2)@Wf + bf, fused LN(128) + L2 normalize --------
__global__ void __launch_bounds__(256) tgemm_final_k(
    const float* __restrict__ A1, const float* __restrict__ A2, int K1,
    const float* __restrict__ B, const float* __restrict__ bias,
    const float* __restrict__ gw, const float* __restrict__ bw,
    float* __restrict__ C, int M, int K)
{
    const int BM = 128, BK = 16, Nc = 128;
    __shared__ float As[2][BM][20];
    __shared__ float Bs[2][BK][136];
    __shared__ float redS[128], redQ[128], redN[128];

    int tid = threadIdx.x;
    int lane = tid & 31, wid = tid >> 5;
    int g = lane >> 2, t = lane & 3;
    int wm = wid >> 2, wn = wid & 3;
    int rowBase = blockIdx.x * BM;

    if (tid < 128) { redS[tid] = 0.f; redQ[tid] = 0.f; redN[tid] = 0.f; }

    float acc[4][4][4];
#pragma unroll
    for (int i = 0; i < 4; i++)
#pragma unroll
        for (int j = 0; j < 4; j++)
#pragma unroll
            for (int r = 0; r < 4; r++) acc[i][j][r] = 0.f;

    int ar0 = tid >> 2, ac0 = (tid & 3) * 4;
    int ar1 = ar0 + 64;
    int br0 = tid >> 5, bc0 = (tid & 31) * 4;
    int br1 = br0 + 8;

    auto loadtile = [&](int kt, int sb) {
        const float* Ap; int kk, stride;
        if (kt < K1) { Ap = A1; kk = kt;      stride = K1;     }
        else         { Ap = A2; kk = kt - K1; stride = K - K1; }
        int r0 = rowBase + ar0, r1 = rowBase + ar1;
        cp16(&As[sb][ar0][ac0], Ap + (size_t)r0 * stride + kk + ac0, r0 < M);
        cp16(&As[sb][ar1][ac0], Ap + (size_t)r1 * stride + kk + ac0, r1 < M);
        cp16(&Bs[sb][br0][bc0], B + (size_t)(kt + br0) * Nc + bc0, true);
        cp16(&Bs[sb][br1][bc0], B + (size_t)(kt + br1) * Nc + bc0, true);
        cp_commit();
    };

    int ntiles = K / BK;
    loadtile(0, 0);
    for (int kt = 0; kt < ntiles; kt++) {
        int s = kt & 1;
        if (kt + 1 < ntiles) loadtile((kt + 1) * BK, s ^ 1);
        else cp_commit();
        cp_wait<1>();
        __syncthreads();
#pragma unroll
        for (int ks = 0; ks < 2; ks++) {
            int k0 = ks * 8;
            unsigned a[4][4], b[4][2];
#pragma unroll
            for (int mt = 0; mt < 4; mt++) {
                int m0 = wm * 64 + mt * 16;
                a[mt][0] = __float_as_uint(As[s][m0 + g][k0 + t]);
                a[mt][1] = __float_as_uint(As[s][m0 + g + 8][k0 + t]);
                a[mt][2] = __float_as_uint(As[s][m0 + g][k0 + t + 4]);
                a[mt][3] = __float_as_uint(As[s][m0 + g + 8][k0 + t + 4]);
            }
#pragma unroll
            for (int nt = 0; nt < 4; nt++) {
                int n0 = wn * 32 + nt * 8;
                b[nt][0] = __float_as_uint(Bs[s][k0 + t][n0 + g]);
                b[nt][1] = __float_as_uint(Bs[s][k0 + t + 4][n0 + g]);
            }
#pragma unroll
            for (int mt = 0; mt < 4; mt++)
#pragma unroll
                for (int nt = 0; nt < 4; nt++)
                    mma_tf32(acc[mt][nt], a[mt], b[nt]);
        }
        __syncthreads();
    }

#pragma unroll
    for (int nt = 0; nt < 4; nt++) {
        int col = wn * 32 + nt * 8 + 2 * t;
        float2 bb = *reinterpret_cast<const float2*>(bias + col);
#pragma unroll
        for (int mt = 0; mt < 4; mt++) {
            acc[mt][nt][0] += bb.x; acc[mt][nt][1] += bb.y;
            acc[mt][nt][2] += bb.x; acc[mt][nt][3] += bb.y;
        }
    }
#pragma unroll
    for (int mt = 0; mt < 4; mt++) {
        float s0 = 0.f, q0 = 0.f, s1 = 0.f, q1 = 0.f;
#pragma unroll
        for (int nt = 0; nt < 4; nt++) {
            s0 += acc[mt][nt][0] + acc[mt][nt][1];
            q0 += acc[mt][nt][0] * acc[mt][nt][0] + acc[mt][nt][1] * acc[mt][nt][1];
            s1 += acc[mt][nt][2] + acc[mt][nt][3];
            q1 += acc[mt][nt][2] * acc[mt][nt][2] + acc[mt][nt][3] * acc[mt][nt][3];
        }
#pragma unroll
        for (int off = 1; off <= 2; off <<= 1) {
            s0 += __shfl_xor_sync(0xffffffffu, s0, off);
            q0 += __shfl_xor_sync(0xffffffffu, q0, off);
            s1 += __shfl_xor_sync(0xffffffffu, s1, off);
            q1 += __shfl_xor_sync(0xffffffffu, q1, off);
        }
        if (t == 0) {
            int lr = wm * 64 + mt * 16 + g;
            atomicAdd(&redS[lr], s0); atomicAdd(&redQ[lr], q0);
            atomicAdd(&redS[lr + 8], s1); atomicAdd(&redQ[lr + 8], q1);
        }
    }
    __syncthreads();
#pragma unroll
    for (int mt = 0; mt < 4; mt++) {
        int lr0 = wm * 64 + mt * 16 + g, lr1 = lr0 + 8;
        float m0 = redS[lr0] * (1.f / 128.f), m1 = redS[lr1] * (1.f / 128.f);
        float var0 = redQ[lr0] * (1.f / 128.f) - m0 * m0;
        float var1 = redQ[lr1] * (1.f / 128.f) - m1 * m1;
        float r0 = rsqrtf(var0 + 1e-5f), r1 = rsqrtf(var1 + 1e-5f);
        float n0 = 0.f, n1 = 0.f;
#pragma unroll
        for (int nt = 0; nt < 4; nt++) {
            int col = wn * 32 + nt * 8 + 2 * t;
            float2 gg = *reinterpret_cast<const float2*>(gw + col);
            float2 b2 = *reinterpret_cast<const float2*>(bw + col);
            float y00 = (acc[mt][nt][0] - m0) * r0 * gg.x + b2.x;
            float y01 = (acc[mt][nt][1] - m0) * r0 * gg.y + b2.y;
            float y10 = (acc[mt][nt][2] - m1) * r1 * gg.x + b2.x;
            float y11 = (acc[mt][nt][3] - m1) * r1 * gg.y + b2.y;
            acc[mt][nt][0] = y00; acc[mt][nt][1] = y01;
            acc[mt][nt][2] = y10; acc[mt][nt][3] = y11;
            n0 += y00 * y00 + y01 * y01;
            n1 += y10 * y10 + y11 * y11;
        }
#pragma unroll
        for (int off = 1; off <= 2; off <<= 1) {
            n0 += __shfl_xor_sync(0xffffffffu, n0, off);
            n1 += __shfl_xor_sync(0xffffffffu, n1, off);
        }
        if (t == 0) { atomicAdd(&redN[lr0], n0); atomicAdd(&redN[lr1], n1); }
    }
    __syncthreads();
#pragma unroll
    for (int mt = 0; mt < 4; mt++) {
        int lr0 = wm * 64 + mt * 16 + g, lr1 = lr0 + 8;
        float inv0 = 1.f / fmaxf(sqrtf(redN[lr0]), 1e-12f);
        float inv1 = 1.f / fmaxf(sqrtf(redN[lr1]), 1e-12f);
        int row0 = rowBase + lr0, row1 = rowBase + lr1;
#pragma unroll
        for (int nt = 0; nt < 4; nt++) {
            int col = wn * 32 + nt * 8 + 2 * t;
            if (row0 < M) *reinterpret_cast<float2*>(C + (size_t)row0 * 128 + col)
                = make_float2(acc[mt][nt][0] * inv0, acc[mt][nt][1] * inv0);
            if (row1 < M) *reinterpret_cast<float2*>(C + (size_t)row1 * 128 + col)
                = make_float2(acc[mt][nt][2] * inv1, acc[mt][nt][3] * inv1);
        }
    }
}

// ---------------- round weights once into g_wt ----------------
__global__ void round_w_k(const float* __restrict__ w0, const float* __restrict__ w1,
                          const float* __restrict__ w2, float* __restrict__ out)
{
    int i = blockIdx.x * 256 + threadIdx.x;
    out[i]          = rnd_tf32(w0[i]);
    out[65536 + i]  = rnd_tf32(w1[i]);
    out[131072 + i] = rnd_tf32(w2[i]);
}

// ---------------- den init: den[n] = exp(e_self) (no max shift needed, logits O(1)) ------
__global__ void den_init_k(const float* __restrict__ asrc, const float* __restrict__ adst,
                           float* __restrict__ den)
{
    int n = blockIdx.x * blockDim.x + threadIdx.x;
    if (n >= NN) return;
    float4 as = *reinterpret_cast<const float4*>(asrc + (size_t)n * 4);
    float4 ad = *reinterpret_cast<const float4*>(adst + (size_t)n * 4);
    float4 o;
    o.x = expf(leaky(as.x + ad.x));
    o.y = expf(leaky(as.y + ad.y));
    o.z = expf(leaky(as.z + ad.z));
    o.w = expf(leaky(as.w + ad.w));
    *reinterpret_cast<float4*>(den + (size_t)n * 4) = o;
}

// ---------------- fused edge pass: exp(logit) + segment-sum into den --------------------
__global__ void edge_expsum_k(const int* __restrict__ ei,
                              const float* __restrict__ asrc, const float* __restrict__ adst,
                              float* __restrict__ ebuf, float* __restrict__ den)
{
    int i = blockIdx.x * blockDim.x + threadIdx.x;
    if (i >= EE) return;
    int s = ei[i], d = ei[EE + i];
    float4 as = *reinterpret_cast<const float4*>(asrc + (size_t)s * 4);
    float4 ad = *reinterpret_cast<const float4*>(adst + (size_t)d * 4);
    float4 o;
    o.x = expf(leaky(as.x + ad.x));
    o.y = expf(leaky(as.y + ad.y));
    o.z = expf(leaky(as.z + ad.z));
    o.w = expf(leaky(as.w + ad.w));
    *reinterpret_cast<float4*>(ebuf + (size_t)i * 4) = o;
    red4(den + (size_t)d * 4, o);
}

// ---------------- edge scatter (real edges only) ----------------------------------------
__global__ void __launch_bounds__(256) edge_scatter_k(const int* __restrict__ ei,
        const float* __restrict__ ebuf, const float* __restrict__ den,
        const float* __restrict__ hw, float* __restrict__ acc)
{
    int idx = blockIdx.x * 4 + (threadIdx.x >> 6);
    int lane = threadIdx.x & 63;
    if (idx >= EE) return;
    int s = ei[idx], d = ei[EE + idx];
    float4 ex = *reinterpret_cast<const float4*>(ebuf + (size_t)idx * 4);
    float4 dn = *reinterpret_cast<const float4*>(den + (size_t)d * 4);
    int head = lane >> 4;
    float exs = (head == 0) ? ex.x : (head == 1) ? ex.y : (head == 2) ? ex.z : ex.w;
    float dns = (head == 0) ? dn.x : (head == 1) ? dn.y : (head == 2) ? dn.z : dn.w;
    float al = exs / dns;
    float4 hv = reinterpret_cast<const float4*>(hw + (size_t)s * 256)[lane];
    float4 v = make_float4(hv.x * al, hv.y * al, hv.z * al, hv.w * al);
    red4(acc + (size_t)d * 256 + lane * 4, v);
}

// ---------------- LN(256) of (acc + alpha_self*hw + bias), ReLU, tf32-rounded out -------
__global__ void ln_relu_k(const float* __restrict__ in, const float* __restrict__ hw,
                          const float* __restrict__ asrc, const float* __restrict__ adst,
                          const float* __restrict__ den,
                          const float* __restrict__ bias,
                          const float* __restrict__ g, const float* __restrict__ b,
                          float* __restrict__ out)
{
    int row = (blockIdx.x * blockDim.x + threadIdx.x) >> 5;
    int lane = threadIdx.x & 31;
    if (row >= NN) return;
    int h = lane >> 3;
    float es = leaky(asrc[row * 4 + h] + adst[row * 4 + h]);
    float al = expf(es) / den[row * 4 + h];

    const float4* ip = reinterpret_cast<const float4*>(in + (size_t)row * 256);
    const float4* hp = reinterpret_cast<const float4*>(hw + (size_t)row * 256);
    const float4* bsp = reinterpret_cast<const float4*>(bias);
    float4 v0 = ip[lane * 2], v1 = ip[lane * 2 + 1];
    float4 h0 = hp[lane * 2], h1 = hp[lane * 2 + 1];
    float4 a0 = bsp[lane * 2], a1 = bsp[lane * 2 + 1];
    v0.x += al * h0.x + a0.x; v0.y += al * h0.y + a0.y;
    v0.z += al * h0.z + a0.z; v0.w += al * h0.w + a0.w;
    v1.x += al * h1.x + a1.x; v1.y += al * h1.y + a1.y;
    v1.z += al * h1.z + a1.z; v1.w += al * h1.w + a1.w;
    float sum = v0.x + v0.y + v0.z + v0.w + v1.x + v1.y + v1.z + v1.w;
#pragma unroll
    for (int off = 16; off; off >>= 1) sum += __shfl_xor_sync(0xffffffffu, sum, off);
    float mean = sum * (1.f / 256.f);
    float c0x = v0.x - mean, c0y = v0.y - mean, c0z = v0.z - mean, c0w = v0.w - mean;
    float c1x = v1.x - mean, c1y = v1.y - mean, c1z = v1.z - mean, c1w = v1.w - mean;
    float sq = c0x * c0x + c0y * c0y + c0z * c0z + c0w * c0w
             + c1x * c1x + c1y * c1y + c1z * c1z + c1w * c1w;
#pragma unroll
    for (int off = 16; off; off >>= 1) sq += __shfl_xor_sync(0xffffffffu, sq, off);
    float r = rsqrtf(sq * (1.f / 256.f) + 1e-5f);
    const float4* gp = reinterpret_cast<const float4*>(g);
    const float4* bp = reinterpret_cast<const float4*>(b);
    float4 g0 = gp[lane * 2], g1 = gp[lane * 2 + 1];
    float4 b0 = bp[lane * 2], b1 = bp[lane * 2 + 1];
    float4 o0, o1;
    o0.x = rnd_tf32(fmaxf(c0x * r * g0.x + b0.x, 0.f));
    o0.y = rnd_tf32(fmaxf(c0y * r * g0.y + b0.y, 0.f));
    o0.z = rnd_tf32(fmaxf(c0z * r * g0.z + b0.z, 0.f));
    o0.w = rnd_tf32(fmaxf(c0w * r * g0.w + b0.w, 0.f));
    o1.x = rnd_tf32(fmaxf(c1x * r * g1.x + b1.x, 0.f));
    o1.y = rnd_tf32(fmaxf(c1y * r * g1.y + b1.y, 0.f));
    o1.z = rnd_tf32(fmaxf(c1z * r * g1.z + b1.z, 0.f));
    o1.w = rnd_tf32(fmaxf(c1w * r * g1.w + b1.w, 0.f));
    float4* op = reinterpret_cast<float4*>(out + (size_t)row * 256);
    op[lane * 2] = o0;
    op[lane * 2 + 1] = o1;
}

// ---------------- launcher ----------------
extern "C" void kernel_launch(void* const* d_in, const int* in_sizes, int n_in,
                              void* d_out, int out_size)
{
    const float* x       = (const float*)d_in[0];
    const int*   ei_bu   = (const int*)d_in[1];
    const int*   ei_td   = (const int*)d_in[2];
    const float* Wp      = (const float*)d_in[3];
    const float* bp      = (const float*)d_in[4];
    const float* W_bu    = (const float*)d_in[5];
    const float* asrc_bu = (const float*)d_in[6];
    const float* adst_bu = (const float*)d_in[7];
    const float* bias_bu = (const float*)d_in[8];
    const float* W_td    = (const float*)d_in[9];
    const float* asrc_td = (const float*)d_in[10];
    const float* adst_td = (const float*)d_in[11];
    const float* bias_td = (const float*)d_in[12];
    const float* Wf      = (const float*)d_in[13];
    const float* bf      = (const float*)d_in[14];
    const float* g_bu    = (const float*)d_in[15];
    const float* b_bu    = (const float*)d_in[16];
    const float* g_td    = (const float*)d_in[17];
    const float* b_td    = (const float*)d_in[18];
    const float* g_out   = (const float*)d_in[19];
    const float* b_out   = (const float*)d_in[20];
    float* out = (float*)d_out;

    float *ph, *pxbu, *pxtd, *pwt;
    float *phw[2], *pacc[2], *pas[2], *pad[2], *pden[2], *pe[2];
    cudaGetSymbolAddress((void**)&ph,      g_h);
    cudaGetSymbolAddress((void**)&phw[0],  g_hw0);
    cudaGetSymbolAddress((void**)&phw[1],  g_hw1);
    cudaGetSymbolAddress((void**)&pacc[0], g_acc0);
    cudaGetSymbolAddress((void**)&pacc[1], g_acc1);
    cudaGetSymbolAddress((void**)&pxbu,    g_xbu);
    cudaGetSymbolAddress((void**)&pxtd,    g_xtd);
    cudaGetSymbolAddress((void**)&pas[0],  g_as0);
    cudaGetSymbolAddress((void**)&pas[1],  g_as1);
    cudaGetSymbolAddress((void**)&pad[0],  g_ad0);
    cudaGetSymbolAddress((void**)&pad[1],  g_ad1);
    cudaGetSymbolAddress((void**)&pden[0], g_den0);
    cudaGetSymbolAddress((void**)&pden[1], g_den1);
    cudaGetSymbolAddress((void**)&pe[0],   g_e0);
    cudaGetSymbolAddress((void**)&pe[1],   g_e1);
    cudaGetSymbolAddress((void**)&pwt,     g_wt);

    // one-time stream/event creation (host resources, not device memory)
    static cudaStream_t sc[2] = {nullptr, nullptr};
    static cudaEvent_t evFork = nullptr, evG[2] = {nullptr, nullptr}, evJ[2] = {nullptr, nullptr};
    if (sc[0] == nullptr) {
        cudaStreamCreateWithFlags(&sc[0], cudaStreamNonBlocking);
        cudaStreamCreateWithFlags(&sc[1], cudaStreamNonBlocking);
        cudaEventCreateWithFlags(&evFork, cudaEventDisableTiming);
        cudaEventCreateWithFlags(&evG[0], cudaEventDisableTiming);
        cudaEventCreateWithFlags(&evG[1], cudaEventDisableTiming);
        cudaEventCreateWithFlags(&evJ[0], cudaEventDisableTiming);
        cudaEventCreateWithFlags(&evJ[1], cudaEventDisableTiming);
    }

    const int mblocks = (NN + 127) / 128;               // 1563
    const dim3 gemmGrid256(2, mblocks);
    const int warpRowBlocks = (NN * 32) / 256;          // 25000
    const int nodeBlocks    = (NN + 255) / 256;         // 782
    const int edgeBlocks    = (EE + 255) / 256;         // 782
    const int scatBlocks    = (EE + 3) / 4;             // 50000

    round_w_k<<<256, 256>>>(W_bu, W_td, Wf, pwt);

    // h = round_tf32(relu(x @ Wp + bp))
    tgemm_k<true, true, true><<<gemmGrid256, 256>>>(x, Wp, bp, ph, NN, 256, 256);

    // fork memsets onto side streams (overlap with the direction GEMMs)
    cudaEventRecord(evFork, 0);
    cudaStreamWaitEvent(sc[0], evFork, 0);
    cudaStreamWaitEvent(sc[1], evFork, 0);
    cudaMemsetAsync(pacc[0], 0, (size_t)NN * 256 * sizeof(float), sc[0]);
    cudaMemsetAsync(pacc[1], 0, (size_t)NN * 256 * sizeof(float), sc[1]);

    const int*   eis[2]   = {ei_bu, ei_td};
    const float* asr[2]   = {asrc_bu, asrc_td};
    const float* ads[2]   = {adst_bu, adst_td};
    const float* bis[2]   = {bias_bu, bias_td};
    const float* gln[2]   = {g_bu, g_td};
    const float* bln[2]   = {b_bu, b_td};
    float*       xdir[2]  = {pxbu, pxtd};

    // staggered: GEMMs serialized on stream 0; each memory chain forked to its side
    // stream so chain(dir) overlaps GEMM(dir+1)'s compute.
    for (int dir = 0; dir < 2; dir++) {
        tgemm_att_k<<<gemmGrid256, 256>>>(
            ph, pwt + dir * 65536, phw[dir], NN, 256, 256,
            asr[dir], ads[dir], pas[dir], pad[dir]);
        cudaEventRecord(evG[dir], 0);
        cudaStreamWaitEvent(sc[dir], evG[dir], 0);
        cudaStream_t st = sc[dir];
        den_init_k<<<nodeBlocks, 256, 0, st>>>(pas[dir], pad[dir], pden[dir]);
        edge_expsum_k<<<edgeBlocks, 256, 0, st>>>(eis[dir], pas[dir], pad[dir], pe[dir], pden[dir]);
        edge_scatter_k<<<scatBlocks, 256, 0, st>>>(eis[dir], pe[dir], pden[dir], phw[dir], pacc[dir]);
        ln_relu_k<<<warpRowBlocks, 256, 0, st>>>(pacc[dir], phw[dir], pas[dir], pad[dir],
                                                 pden[dir],
                                                 bis[dir], gln[dir], bln[dir], xdir[dir]);
        cudaEventRecord(evJ[dir], st);
    }

    // join both chains
    cudaStreamWaitEvent(0, evJ[0], 0);
    cudaStreamWaitEvent(0, evJ[1], 0);

    // out = L2norm(LN(concat(x_bu, x_td) @ Wf + bf)) fused
    tgemm_final_k<<<mblocks, 256>>>(pxbu, pxtd, 256, pwt + 131072, bf,
                                    g_out, b_out, out, NN, 512);
}